// round 10
// baseline (speedup 1.0000x reference)
#include <cuda_runtime.h>
#include <math.h>
#include <stdint.h>

// ---------------- constants ----------------
#define BB 2
#define SS 1024
#define DD 768
#define HH 12
#define HD 64
#define EE 8
#define FF 2048
#define CIN 512
#define TOK (BB*SS)          // 2048
#define FB 513
#define PADL 384
#define OUTL 262144
#define TWO_PI_N 0.006135923151542565f   // 2*pi/1024

// ---------------- scratch (device globals; allocation-free) ----------------
__device__ float g_zt[TOK*CIN];
__device__ float g_x [TOK*DD];
__device__ float g_h [TOK*DD];
__device__ float g_qkv[3*TOK*DD];
__device__ float g_bqkv[3*DD];
__device__ float g_ao[TOK*DD];
__device__ float g_scores[24u*1024u*1024u];
__device__ float g_hidden[4096*FF];
__device__ float g_yslot [4096*DD];
__device__ float g_Cb[1026*1024];
__device__ float g_Mt[DD*1024];
__device__ float g_bf[1024];
__device__ float g_frames[TOK*1024];
__device__ int   g_cnt[EE];
__device__ int   g_etok[EE*TOK];
__device__ int   g_easn[EE*TOK];
__device__ float g_wts[2*TOK];

// packed weights: hi in [0,SZ), lo in [SZ,2SZ)
#define SZ_INW  (256*768)
#define SZ_QKV1 (384*768)
#define SZ_QKV  (3*SZ_QKV1)
#define SZ_WO   (384*768)
#define SZ_E1   (8*384*2048)
#define SZ_E2   (8*1024*768)
#define SZ_MT   (384*1024)
#define SZ_CB   (513*1024)
__device__ uint32_t g_pk_inw[2*SZ_INW];
__device__ uint32_t g_pk_qkv[2*SZ_QKV];
__device__ uint32_t g_pk_wo [2*SZ_WO];
__device__ uint32_t g_pk_e1 [2u*SZ_E1];
__device__ uint32_t g_pk_e2 [2u*SZ_E2];
__device__ uint32_t g_pk_mt [2*SZ_MT];
__device__ uint32_t g_pk_cb [2*SZ_CB];

// ---------------- bf16x3 helpers ----------------
__device__ __forceinline__ void pack_bf16pair(float f0, float f1, uint32_t& hi, uint32_t& lo) {
    uint32_t u0 = __float_as_uint(f0);
    uint32_t u1 = __float_as_uint(f1);
    uint32_t h;
    asm("prmt.b32 %0, %1, %2, 0x7632;" : "=r"(h) : "r"(u0), "r"(u1));
    hi = h;
    float l0 = f0 - __uint_as_float(u0 & 0xFFFF0000u);
    float l1 = f1 - __uint_as_float(u1 & 0xFFFF0000u);
    asm("cvt.rn.bf16x2.f32 %0, %1, %2;" : "=r"(lo) : "f"(l1), "f"(l0));
}
__device__ __forceinline__ void mma_bf16(float* c, const uint32_t* a, const uint32_t* b) {
    asm volatile(
        "mma.sync.aligned.m16n8k16.row.col.f32.bf16.bf16.f32 "
        "{%0,%1,%2,%3}, {%4,%5,%6,%7}, {%8,%9}, {%0,%1,%2,%3};"
        : "+f"(c[0]), "+f"(c[1]), "+f"(c[2]), "+f"(c[3])
        : "r"(a[0]), "r"(a[1]), "r"(a[2]), "r"(a[3]), "r"(b[0]), "r"(b[1]));
}
__device__ __forceinline__ void cpa16(uint32_t dst, const void* src, bool pred) {
    asm volatile("cp.async.ca.shared.global [%0], [%1], 16, %2;"
                 :: "r"(dst), "l"(src), "r"(pred ? 16 : 0));
}
__device__ __forceinline__ void cpa_commit() { asm volatile("cp.async.commit_group;"); }
__device__ __forceinline__ void cpa_wait1() { asm volatile("cp.async.wait_group 1;"); }
__device__ __forceinline__ void cpa_wait0() { asm volatile("cp.async.wait_group 0;"); }

// ---------------- weight pre-pack kernel ----------------
__global__ void pack_w(const float* __restrict__ W, long long sWz, int K, int N,
                       uint32_t* __restrict__ Ph, uint32_t* __restrict__ Pl, long long sPz)
{
    int z = blockIdx.z;
    int K2 = (K + 1) >> 1;
    int idx = blockIdx.x * 256 + threadIdx.x;
    if (idx >= K2 * N) return;
    int p = idx / N, n = idx - p * N;
    const float* Wz = W + (long long)z * sWz;
    float f0 = Wz[(long long)(2 * p) * N + n];
    float f1 = (2 * p + 1 < K) ? Wz[(long long)(2 * p + 1) * N + n] : 0.f;
    uint32_t hi, lo; pack_bf16pair(f0, f1, hi, lo);
    Ph[(long long)z * sPz + idx] = hi;
    Pl[(long long)z * sPz + idx] = lo;
}

// ---------------- register/async staged tensor-core GEMM (3xBF16) ----------------
// Tile: 64(M) x BN(N), K-step 16. 8 warps as 2(M) x 4(N); warp = 32 x BN/4.
#define APK_LD 12   // packed A row stride (uint32; 8 pairs + pad)
#define APK_SZ (64 * APK_LD)

template<int ACT, bool TRB, int BN, bool PKB>
__global__ __launch_bounds__(256, 2)
void gemm_kernel(const float* __restrict__ A, int lda, long long sAz, long long sAz2,
                 const float* __restrict__ B, int ldb, long long sBz, long long sBz2,
                 float* __restrict__ C, int ldc, long long sCz, long long sCz2,
                 int zdiv,
                 const float* __restrict__ bias, long long sbz,
                 const float* __restrict__ res,
                 int M, int N, int Kd, float alpha,
                 const int* __restrict__ idxA, const int* __restrict__ idxC,
                 const int* __restrict__ cnt, int causal,
                 const uint32_t* __restrict__ PBh, const uint32_t* __restrict__ PBl,
                 long long sPBz, int ldPB)
{
    constexpr int BPK_LD = TRB ? APK_LD : (BN + 8);
    constexpr int BPK_SZ = TRB ? (BN * APK_LD) : (8 * (BN + 8));
    constexpr int STAGE  = 2 * APK_SZ + 2 * BPK_SZ;   // non-PKB stage (u32)
    constexpr int BJ = BN / 32;
    // PKB layout: A 2 stages of 2*APK_SZ; B 3 stages of 2*1088 (8*136)
    constexpr int PK_AST = 2 * APK_SZ;        // 1536
    constexpr int PK_BST = 2 * 8 * 136;       // 2176

    int z = blockIdx.z;
    int z1 = z / zdiv, z0 = z - z1 * zdiv;
    if (cnt) M = cnt[z];
    int m0 = blockIdx.y * 64, n0 = blockIdx.x * BN;
    if (m0 >= M) return;
    if (causal == 1 && n0 > m0 + 63) return;
    if (causal == 2) Kd = min(Kd, m0 + 64);
    A += (long long)z0 * sAz + (long long)z1 * sAz2;
    if (!PKB) B += (long long)z0 * sBz + (long long)z1 * sBz2;
    else { PBh += (long long)z0 * sPBz; PBl += (long long)z0 * sPBz; }
    C += (long long)z0 * sCz + (long long)z1 * sCz2;
    if (bias) bias += (long long)z * sbz;
    if (res)  res  += (long long)z0 * sCz + (long long)z1 * sCz2;
    const int* iA = idxA ? idxA + z * TOK : nullptr;
    const int* iC = idxC ? idxC + z * TOK : nullptr;

    extern __shared__ uint32_t smem[];
    uint32_t smemBase = (uint32_t)__cvta_generic_to_shared(smem);

    int tid = threadIdx.x;
    int lane = tid & 31, wid = tid >> 5;
    int wm = wid >> 2, wn = wid & 3;
    int lm = lane >> 2, lk = lane & 3;

    float acc[2][BJ][4];
#pragma unroll
    for (int i = 0; i < 2; i++)
#pragma unroll
        for (int j = 0; j < BJ; j++)
#pragma unroll
            for (int r = 0; r < 4; r++) acc[i][j][r] = 0.f;

    const bool fastA = ((lda & 3) == 0) && ((Kd & 15) == 0);
    const bool fastB = ((ldb & 3) == 0) && (TRB ? ((Kd & 15) == 0) : true);

    // per-thread register staging
    float rA[4];
    float rB[8];
    int mmA = tid >> 2, qA = tid & 3;
    int raA = -1;
    {
        int gm = m0 + mmA;
        if (gm < M) raA = iA ? iA[gm] : gm;
    }
    int pB = 0, nqB = 0;
    bool bAct = true;
    if (!TRB && !PKB) {
        if (BN == 128) { pB = tid >> 5; nqB = tid & 31; }
        else { pB = tid >> 4; nqB = tid & 15; bAct = (tid < 128); }
    }

    auto load_regsA = [&](int k0) {
        if (raA >= 0) {
            if (fastA) {
                const float4 v = *(const float4*)(A + (long long)raA * lda + k0 + 4 * qA);
                rA[0] = v.x; rA[1] = v.y; rA[2] = v.z; rA[3] = v.w;
            } else {
#pragma unroll
                for (int j = 0; j < 4; j++) {
                    int gk = k0 + 4 * qA + j;
                    rA[j] = (gk < Kd) ? A[(long long)raA * lda + gk] : 0.f;
                }
            }
        } else {
            rA[0] = rA[1] = rA[2] = rA[3] = 0.f;
        }
    };

    auto load_regsB = [&](int k0) {
        if (!TRB) {
            if (bAct) {
                int gk0 = k0 + 2 * pB;
                int nb = n0 + 4 * nqB;
#pragma unroll
                for (int r = 0; r < 2; r++) {
                    int gk = gk0 + r;
                    if (gk < Kd) {
                        if (fastB) {
                            const float4 v = *(const float4*)(B + (long long)gk * ldb + nb);
                            rB[4 * r + 0] = v.x; rB[4 * r + 1] = v.y;
                            rB[4 * r + 2] = v.z; rB[4 * r + 3] = v.w;
                        } else {
#pragma unroll
                            for (int j = 0; j < 4; j++)
                                rB[4 * r + j] = B[(long long)gk * ldb + nb + j];
                        }
                    } else {
                        rB[4 * r + 0] = rB[4 * r + 1] = rB[4 * r + 2] = rB[4 * r + 3] = 0.f;
                    }
                }
            }
        } else {
#pragma unroll
            for (int it = 0; it < BN / 64; it++) {
                int lin = tid + it * 256;
                int nn = lin >> 2, q = lin & 3;
                int gn = n0 + nn;
                if (gn < N) {
                    if (fastB) {
                        const float4 v = *(const float4*)(B + (long long)gn * ldb + k0 + 4 * q);
                        rB[4 * it + 0] = v.x; rB[4 * it + 1] = v.y;
                        rB[4 * it + 2] = v.z; rB[4 * it + 3] = v.w;
                    } else {
#pragma unroll
                        for (int j = 0; j < 4; j++) {
                            int gk = k0 + 4 * q + j;
                            rB[4 * it + j] = (gk < Kd) ? B[(long long)gn * ldb + gk] : 0.f;
                        }
                    }
                } else {
                    rB[4 * it + 0] = rB[4 * it + 1] = rB[4 * it + 2] = rB[4 * it + 3] = 0.f;
                }
            }
        }
    };

    // ============== PKB path ==============
    if constexpr (PKB) {
        uint32_t* Asm = smem;                 // 2 * PK_AST
        uint32_t* Bsm = smem + 2 * PK_AST;    // 3 * PK_BST

        auto convA = [&](int s) {
            uint32_t* Aph = Asm + s * PK_AST;
            uint32_t* Apl = Aph + APK_SZ;
            uint32_t hi, lo;
            pack_bf16pair(rA[0], rA[1], hi, lo);
            Aph[mmA * APK_LD + 2 * qA] = hi;
            Apl[mmA * APK_LD + 2 * qA] = lo;
            pack_bf16pair(rA[2], rA[3], hi, lo);
            Aph[mmA * APK_LD + 2 * qA + 1] = hi;
            Apl[mmA * APK_LD + 2 * qA + 1] = lo;
        };
        auto cpaB = [&](int k0, int st) {
            int p = tid >> 5, n4 = (tid & 31) * 4;
            bool pred = (k0 + 2 * p) < Kd;
            long long row = (long long)((k0 >> 1) + p) * ldPB + n0 + n4;
            uint32_t dbase = smemBase + ((2 * PK_AST + st * PK_BST + p * 136 + n4) << 2);
            cpa16(dbase, PBh + row, pred);
            cpa16(dbase + (1088 << 2), PBl + row, pred);
        };
        auto computeP = [&](int i) {
            const uint32_t* Aph = Asm + (i & 1) * PK_AST;
            const uint32_t* Apl = Aph + APK_SZ;
            const uint32_t* Bph = Bsm + (i % 3) * PK_BST;
            const uint32_t* Bpl = Bph + 1088;
            uint32_t ah[2][4], al[2][4];
#pragma unroll
            for (int i2 = 0; i2 < 2; i2++) {
                int r0 = wm * 32 + i2 * 16 + lm;
                ah[i2][0] = Aph[r0 * APK_LD + lk];
                ah[i2][1] = Aph[(r0 + 8) * APK_LD + lk];
                ah[i2][2] = Aph[r0 * APK_LD + lk + 4];
                ah[i2][3] = Aph[(r0 + 8) * APK_LD + lk + 4];
                al[i2][0] = Apl[r0 * APK_LD + lk];
                al[i2][1] = Apl[(r0 + 8) * APK_LD + lk];
                al[i2][2] = Apl[r0 * APK_LD + lk + 4];
                al[i2][3] = Apl[(r0 + 8) * APK_LD + lk + 4];
            }
#pragma unroll
            for (int j = 0; j < BJ; j++) {
                int bn = wn * (BN / 4) + j * 8 + lm;
                uint32_t bh[2], bl[2];
                bh[0] = Bph[lk * 136 + bn];
                bh[1] = Bph[(lk + 4) * 136 + bn];
                bl[0] = Bpl[lk * 136 + bn];
                bl[1] = Bpl[(lk + 4) * 136 + bn];
                mma_bf16(acc[0][j], ah[0], bh);
                mma_bf16(acc[1][j], ah[1], bh);
                mma_bf16(acc[0][j], al[0], bh);
                mma_bf16(acc[1][j], al[1], bh);
                mma_bf16(acc[0][j], ah[0], bl);
                mma_bf16(acc[1][j], ah[1], bl);
            }
        };

        int nk = (Kd + 15) >> 4;
        load_regsA(0);
        convA(0);
        cpaB(0, 0); cpa_commit();
        if (nk > 1) { cpaB(16, 1); load_regsA(16); }
        cpa_commit();
        cpa_wait0();
        __syncthreads();
        for (int i = 0; i < nk; i++) {
            computeP(i);
            if (i + 1 < nk) convA((i + 1) & 1);
            if (i + 2 < nk) { load_regsA((i + 2) * 16); cpaB((i + 2) * 16, (i + 2) % 3); }
            cpa_commit();
            cpa_wait1();
            __syncthreads();
        }
    } else {
    // ============== reg-staged path (TRB / dynamic B) ==============
        auto convert_stage = [&](int s) {
            uint32_t* Aph = smem + s * STAGE;
            uint32_t* Apl = Aph + APK_SZ;
            uint32_t* Bph = Apl + APK_SZ;
            uint32_t* Bpl = Bph + BPK_SZ;
            {
                uint32_t hi, lo;
                pack_bf16pair(rA[0], rA[1], hi, lo);
                Aph[mmA * APK_LD + 2 * qA] = hi;
                Apl[mmA * APK_LD + 2 * qA] = lo;
                pack_bf16pair(rA[2], rA[3], hi, lo);
                Aph[mmA * APK_LD + 2 * qA + 1] = hi;
                Apl[mmA * APK_LD + 2 * qA + 1] = lo;
            }
            if (!TRB) {
                if (bAct) {
#pragma unroll
                    for (int j = 0; j < 4; j++) {
                        uint32_t hi, lo;
                        pack_bf16pair(rB[j], rB[4 + j], hi, lo);
                        Bph[pB * BPK_LD + 4 * nqB + j] = hi;
                        Bpl[pB * BPK_LD + 4 * nqB + j] = lo;
                    }
                }
            } else {
#pragma unroll
                for (int it = 0; it < BN / 64; it++) {
                    int lin = tid + it * 256;
                    int nn = lin >> 2, q = lin & 3;
                    uint32_t hi, lo;
                    pack_bf16pair(rB[4 * it + 0], rB[4 * it + 1], hi, lo);
                    Bph[nn * BPK_LD + 2 * q] = hi;
                    Bpl[nn * BPK_LD + 2 * q] = lo;
                    pack_bf16pair(rB[4 * it + 2], rB[4 * it + 3], hi, lo);
                    Bph[nn * BPK_LD + 2 * q + 1] = hi;
                    Bpl[nn * BPK_LD + 2 * q + 1] = lo;
                }
            }
        };
        auto compute = [&](int s) {
            const uint32_t* Aph = smem + s * STAGE;
            const uint32_t* Apl = Aph + APK_SZ;
            const uint32_t* Bph = Apl + APK_SZ;
            const uint32_t* Bpl = Bph + BPK_SZ;
            uint32_t ah[2][4], al[2][4];
#pragma unroll
            for (int i = 0; i < 2; i++) {
                int r0 = wm * 32 + i * 16 + lm;
                ah[i][0] = Aph[r0 * APK_LD + lk];
                ah[i][1] = Aph[(r0 + 8) * APK_LD + lk];
                ah[i][2] = Aph[r0 * APK_LD + lk + 4];
                ah[i][3] = Aph[(r0 + 8) * APK_LD + lk + 4];
                al[i][0] = Apl[r0 * APK_LD + lk];
                al[i][1] = Apl[(r0 + 8) * APK_LD + lk];
                al[i][2] = Apl[r0 * APK_LD + lk + 4];
                al[i][3] = Apl[(r0 + 8) * APK_LD + lk + 4];
            }
#pragma unroll
            for (int j = 0; j < BJ; j++) {
                int bn = wn * (BN / 4) + j * 8 + lm;
                uint32_t bh[2], bl[2];
                if (!TRB) {
                    bh[0] = Bph[lk * BPK_LD + bn];
                    bh[1] = Bph[(lk + 4) * BPK_LD + bn];
                    bl[0] = Bpl[lk * BPK_LD + bn];
                    bl[1] = Bpl[(lk + 4) * BPK_LD + bn];
                } else {
                    bh[0] = Bph[bn * BPK_LD + lk];
                    bh[1] = Bph[bn * BPK_LD + lk + 4];
                    bl[0] = Bpl[bn * BPK_LD + lk];
                    bl[1] = Bpl[bn * BPK_LD + lk + 4];
                }
                mma_bf16(acc[0][j], ah[0], bh);
                mma_bf16(acc[1][j], ah[1], bh);
                mma_bf16(acc[0][j], al[0], bh);
                mma_bf16(acc[1][j], al[1], bh);
                mma_bf16(acc[0][j], ah[0], bl);
                mma_bf16(acc[1][j], ah[1], bl);
            }
        };

        int nk = (Kd + 15) >> 4;
        load_regsA(0); load_regsB(0);
        convert_stage(0);
        if (nk > 1) { load_regsA(16); load_regsB(16); }
        __syncthreads();
        for (int i = 0; i < nk; i++) {
            compute(i & 1);
            if (i + 1 < nk) {
                convert_stage((i + 1) & 1);
                if (i + 2 < nk) { load_regsA((i + 2) * 16); load_regsB((i + 2) * 16); }
            }
            __syncthreads();
        }
    }

    // ---- epilogue ----
#pragma unroll
    for (int i = 0; i < 2; i++) {
#pragma unroll
        for (int r2 = 0; r2 < 2; r2++) {
            int gm = m0 + wm * 32 + i * 16 + lm + r2 * 8;
            if (gm >= M) continue;
            int rc = iC ? iC[gm] : gm;
            float* crow = C + (long long)rc * ldc;
            const float* rrow = res ? res + (long long)rc * ldc : nullptr;
#pragma unroll
            for (int j = 0; j < BJ; j++) {
#pragma unroll
                for (int c2 = 0; c2 < 2; c2++) {
                    int gn = n0 + wn * (BN / 4) + j * 8 + lk * 2 + c2;
                    if (gn >= N) continue;
                    float v = acc[i][j][r2 * 2 + c2] * alpha;
                    if (bias) v += bias[gn];
                    if (ACT == 1) {
                        float x = v;
                        float t = tanhf(0.7978845608028654f * (x + 0.044715f * x * x * x));
                        v = 0.5f * x * (1.f + t);
                    }
                    if (rrow) v += rrow[gn];
                    crow[gn] = v;
                }
            }
        }
    }
}

// ---------------- small kernels ----------------
__global__ void transpose_z(const float* __restrict__ z, float* __restrict__ zt) {
    __shared__ float tile[32][33];
    int b = blockIdx.z;
    int l0 = blockIdx.x * 32, c0 = blockIdx.y * 32;
    int x = threadIdx.x, y = threadIdx.y;
    for (int i = y; i < 32; i += 8)
        tile[i][x] = z[b * CIN * SS + (c0 + i) * SS + l0 + x];
    __syncthreads();
    for (int i = y; i < 32; i += 8)
        zt[b * SS * CIN + (long long)(l0 + i) * CIN + c0 + x] = tile[x][i];
}

__global__ void ln_kernel(const float* __restrict__ x, float* __restrict__ y,
                          const float* __restrict__ g, const float* __restrict__ b) {
    int row = blockIdx.x;
    const float* xr = x + (long long)row * DD;
    __shared__ float sh[32];
    __shared__ float sh2[32];
    float s = 0.f, s2 = 0.f;
    for (int d = threadIdx.x; d < DD; d += 256) { float v = xr[d]; s += v; s2 += v * v; }
    int lane = threadIdx.x & 31, wid = threadIdx.x >> 5;
    for (int o = 16; o; o >>= 1) { s += __shfl_xor_sync(~0u, s, o); s2 += __shfl_xor_sync(~0u, s2, o); }
    if (lane == 0) { sh[wid] = s; sh2[wid] = s2; }
    __syncthreads();
    if (wid == 0) {
        s  = (lane < 8) ? sh[lane]  : 0.f;
        s2 = (lane < 8) ? sh2[lane] : 0.f;
        for (int o = 16; o; o >>= 1) { s += __shfl_xor_sync(~0u, s, o); s2 += __shfl_xor_sync(~0u, s2, o); }
        if (lane == 0) { sh[0] = s; sh2[0] = s2; }
    }
    __syncthreads();
    float mean = sh[0] / DD;
    float var  = sh2[0] / DD - mean * mean;
    float inv = rsqrtf(var + 1e-5f);
    float* yr = y + (long long)row * DD;
    for (int d = threadIdx.x; d < DD; d += 256)
        yr[d] = (xr[d] - mean) * inv * g[d] + b[d];
}

__global__ void rope_kernel(float* __restrict__ q, float* __restrict__ k) {
    int idx = blockIdx.x * blockDim.x + threadIdx.x;
    if (idx >= TOK * (DD / 2)) return;
    int t = idx / (DD / 2), j = idx - t * (DD / 2);
    int s = t & (SS - 1);
    float freq = __expf(-9.210340371976184f * ((float)j / 384.f));
    float ang = (float)s * freq;
    float c, sn; sincosf(ang, &sn, &c);
    {
        float* p = q + (long long)t * DD + 2 * j;
        float a = p[0], b = p[1];
        p[0] = a * c - b * sn; p[1] = a * sn + b * c;
    }
    {
        float* p = k + (long long)t * DD + 2 * j;
        float a = p[0], b = p[1];
        p[0] = a * c - b * sn; p[1] = a * sn + b * c;
    }
}

__global__ void softmax_causal(float* __restrict__ sc) {
    int z = blockIdx.y, r = blockIdx.x;
    float* row = sc + ((long long)z << 20) + (long long)r * 1024;
    int n = r + 1;
    int nz = (r & ~63) + 64;   // AV reads only up to the row's 64-block end
    __shared__ float sh[32];
    int lane = threadIdx.x & 31, wid = threadIdx.x >> 5;
    float mx = -1e30f;
    for (int j = threadIdx.x; j < n; j += 256) mx = fmaxf(mx, row[j]);
    for (int o = 16; o; o >>= 1) mx = fmaxf(mx, __shfl_xor_sync(~0u, mx, o));
    if (lane == 0) sh[wid] = mx;
    __syncthreads();
    if (wid == 0) {
        mx = (lane < 8) ? sh[lane] : -1e30f;
        for (int o = 16; o; o >>= 1) mx = fmaxf(mx, __shfl_xor_sync(~0u, mx, o));
        if (lane == 0) sh[0] = mx;
    }
    __syncthreads();
    mx = sh[0];
    __syncthreads();
    float s = 0.f;
    for (int j = threadIdx.x; j < n; j += 256) s += __expf(row[j] - mx);
    for (int o = 16; o; o >>= 1) s += __shfl_xor_sync(~0u, s, o);
    if (lane == 0) sh[wid] = s;
    __syncthreads();
    if (wid == 0) {
        s = (lane < 8) ? sh[lane] : 0.f;
        for (int o = 16; o; o >>= 1) s += __shfl_xor_sync(~0u, s, o);
        if (lane == 0) sh[0] = s;
    }
    __syncthreads();
    float inv = 1.f / sh[0];
    for (int j = threadIdx.x; j < nz; j += 256)
        row[j] = (j < n) ? __expf(row[j] - mx) * inv : 0.f;
}

__global__ void zero_cnt(int* c) { if (threadIdx.x < EE) c[threadIdx.x] = 0; }

__global__ void route_kernel(const float* __restrict__ h, const float* __restrict__ gw,
                             int* cnt, int* etok, int* easn, float* wts) {
    int w = (blockIdx.x * blockDim.x + threadIdx.x) >> 5;
    int lane = threadIdx.x & 31;
    if (w >= TOK) return;
    const float* hr = h + (long long)w * DD;
    float lg[EE];
#pragma unroll
    for (int e = 0; e < EE; e++) {
        float s = 0.f;
        for (int d = lane; d < DD; d += 32) s += hr[d] * gw[d * EE + e];
        for (int o = 16; o; o >>= 1) s += __shfl_xor_sync(~0u, s, o);
        lg[e] = s;
    }
    if (lane == 0) {
        int e0 = 0;
        for (int e = 1; e < EE; e++) if (lg[e] > lg[e0]) e0 = e;
        int e1 = -1;
        for (int e = 0; e < EE; e++) { if (e == e0) continue; if (e1 < 0 || lg[e] > lg[e1]) e1 = e; }
        float x1 = __expf(lg[e1] - lg[e0]);
        float den = 1.f + x1;
        float w0 = 1.f / den, w1 = x1 / den;
        int s0 = atomicAdd(&cnt[e0], 1);
        etok[e0 * TOK + s0] = w; easn[e0 * TOK + s0] = 2 * w;
        int s1 = atomicAdd(&cnt[e1], 1);
        etok[e1 * TOK + s1] = w; easn[e1 * TOK + s1] = 2 * w + 1;
        wts[2 * w] = w0; wts[2 * w + 1] = w1;
    }
}

__global__ void combine_kernel(float* __restrict__ x, const float* __restrict__ ys,
                               const float* __restrict__ wts) {
    int idx = blockIdx.x * blockDim.x + threadIdx.x;
    if (idx >= TOK * DD) return;
    int t = idx / DD, d = idx - t * DD;
    x[idx] += wts[2 * t] * ys[(long long)(2 * t) * DD + d]
            + wts[2 * t + 1] * ys[(long long)(2 * t + 1) * DD + d];
}

__global__ void basis_kernel(float* __restrict__ Cb) {
    int idx = blockIdx.x * blockDim.x + threadIdx.x;
    if (idx >= 1026 * 1024) return;
    int j = idx >> 10, n = idx & 1023;
    const float invN = 1.f / 1024.f;
    float v;
    if (j == 0) v = invN;
    else if (j <= 511) { int m = (j * n) & 1023; v = 2.f * invN * cosf(m * TWO_PI_N); }
    else if (j == 512) v = invN * ((n & 1) ? -1.f : 1.f);
    else if (j == 513 || j == 1025) v = 0.f;
    else { int kk = j - 513; int m = (kk * n) & 1023; v = -2.f * invN * sinf(m * TWO_PI_N); }
    Cb[idx] = v;
}

__global__ void bf_kernel(const float* __restrict__ ob, const float* __restrict__ Cb,
                          float* __restrict__ bf) {
    int n = threadIdx.x;
    float s = 0.f;
    for (int j = 0; j < 1026; j++) s += ob[j] * Cb[j * 1024 + n];
    bf[n] = s;
}

__global__ void istft_kernel(const float* __restrict__ frames, float* __restrict__ out) {
    int idx = blockIdx.x * blockDim.x + threadIdx.x;
    if (idx >= BB * OUTL) return;
    int b = idx / OUTL, i = idx - b * OUTL;
    int ip = i + PADL;
    int tmin = (ip >= 1024) ? ((ip - 768) >> 8) : 0;
    int tmax = min(1023, ip >> 8);
    float acc = 0.f, env = 0.f;
    for (int t = tmin; t <= tmax; t++) {
        int n = ip - (t << 8);
        float w = 0.5f * (1.f - cosf(n * TWO_PI_N));
        acc += frames[((long long)(b * 1024 + t) << 10) + n] * w;
        env += w * w;
    }
    out[idx] = acc / env;
}

// ---------------- host side ----------------
static void* symaddr(const void* sym) {
    void* p = nullptr;
    cudaGetSymbolAddress(&p, sym);
    return p;
}

struct GemmArgs {
    const float* A; int lda; long long sAz, sAz2;
    const float* B; int ldb; long long sBz, sBz2;
    float* C; int ldc; long long sCz, sCz2;
    int zdiv;
    const float* bias; long long sbz; const float* res;
    int M, N, Kd; float alpha; int Z;
    const int* idxA; const int* idxC; const int* cnt;
    int causal; int gridM;
    const uint32_t* PBh; const uint32_t* PBl; long long sPBz; int ldPB;
};

#define BPK_SZH(TRB, BN) ((TRB) ? ((BN) * APK_LD) : (8 * ((BN) + 8)))
#define SMEM_RSTG(TRB, BN) (4 * 2 * (2 * APK_SZ + 2 * BPK_SZH(TRB, BN)))
#define SMEM_PKB (4 * (2 * 2 * APK_SZ + 3 * 2 * 8 * 136))

static void gemm(int act, bool trb, int BN, const GemmArgs& a)
{
    dim3 grid((a.N + BN - 1) / BN, a.gridM ? a.gridM : (a.M + 63) / 64, a.Z);
    if (a.PBh) {
        size_t shm = SMEM_PKB;
        if (act == 1) {
            cudaFuncSetAttribute(gemm_kernel<1, false, 128, true>, cudaFuncAttributeMaxDynamicSharedMemorySize, (int)shm);
            gemm_kernel<1, false, 128, true><<<grid, 256, shm>>>(a.A, a.lda, a.sAz, a.sAz2, a.B, a.ldb, a.sBz, a.sBz2,
                a.C, a.ldc, a.sCz, a.sCz2, a.zdiv, a.bias, a.sbz, a.res,
                a.M, a.N, a.Kd, a.alpha, a.idxA, a.idxC, a.cnt, a.causal, a.PBh, a.PBl, a.sPBz, a.ldPB);
        } else {
            cudaFuncSetAttribute(gemm_kernel<0, false, 128, true>, cudaFuncAttributeMaxDynamicSharedMemorySize, (int)shm);
            gemm_kernel<0, false, 128, true><<<grid, 256, shm>>>(a.A, a.lda, a.sAz, a.sAz2, a.B, a.ldb, a.sBz, a.sBz2,
                a.C, a.ldc, a.sCz, a.sCz2, a.zdiv, a.bias, a.sbz, a.res,
                a.M, a.N, a.Kd, a.alpha, a.idxA, a.idxC, a.cnt, a.causal, a.PBh, a.PBl, a.sPBz, a.ldPB);
        }
    } else if (trb) {
        size_t shm = SMEM_RSTG(true, 128);
        cudaFuncSetAttribute(gemm_kernel<0, true, 128, false>, cudaFuncAttributeMaxDynamicSharedMemorySize, (int)shm);
        gemm_kernel<0, true, 128, false><<<grid, 256, shm>>>(a.A, a.lda, a.sAz, a.sAz2, a.B, a.ldb, a.sBz, a.sBz2,
            a.C, a.ldc, a.sCz, a.sCz2, a.zdiv, a.bias, a.sbz, a.res,
            a.M, a.N, a.Kd, a.alpha, a.idxA, a.idxC, a.cnt, a.causal, nullptr, nullptr, 0, 0);
    } else {
        size_t shm = SMEM_RSTG(false, 64);
        cudaFuncSetAttribute(gemm_kernel<0, false, 64, false>, cudaFuncAttributeMaxDynamicSharedMemorySize, (int)shm);
        gemm_kernel<0, false, 64, false><<<grid, 256, shm>>>(a.A, a.lda, a.sAz, a.sAz2, a.B, a.ldb, a.sBz, a.sBz2,
            a.C, a.ldc, a.sCz, a.sCz2, a.zdiv, a.bias, a.sbz, a.res,
            a.M, a.N, a.Kd, a.alpha, a.idxA, a.idxC, a.cnt, a.causal, nullptr, nullptr, 0, 0);
    }
}

static void launch_pack(const float* W, long long sWz, int K, int N, int zc,
                        uint32_t* base, long long SZtot, long long sPz, long long dstOff)
{
    int K2 = (K + 1) >> 1;
    int total = K2 * N;
    pack_w<<<dim3((total + 255) / 256, 1, zc), 256>>>(W, sWz, K, N,
        base + dstOff, base + SZtot + dstOff, sPz);
}

extern "C" void kernel_launch(void* const* d_in, const int* in_sizes, int n_in,
                              void* d_out, int out_size)
{
    const float* z_in  = (const float*)d_in[0];
    const float* in_w  = (const float*)d_in[1];
    const float* in_b  = (const float*)d_in[2];
    const float* ln1g  = (const float*)d_in[3];
    const float* ln1b  = (const float*)d_in[4];
    const float* wq    = (const float*)d_in[5];
    const float* bq    = (const float*)d_in[6];
    const float* wk    = (const float*)d_in[7];
    const float* bk    = (const float*)d_in[8];
    const float* wv    = (const float*)d_in[9];
    const float* bv    = (const float*)d_in[10];
    const float* wo    = (const float*)d_in[11];
    const float* bo    = (const float*)d_in[12];
    const float* ln2g  = (const float*)d_in[13];
    const float* ln2b  = (const float*)d_in[14];
    const float* gatew = (const float*)d_in[15];
    const float* ew1   = (const float*)d_in[16];
    const float* eb1   = (const float*)d_in[17];
    const float* ew2   = (const float*)d_in[18];
    const float* eb2   = (const float*)d_in[19];
    const float* outw  = (const float*)d_in[20];
    const float* outb  = (const float*)d_in[21];
    float* out = (float*)d_out;

    float* ZT = (float*)symaddr(g_zt);
    float* X  = (float*)symaddr(g_x);
    float* H  = (float*)symaddr(g_h);
    float* QKV = (float*)symaddr(g_qkv);
    float* BQKV = (float*)symaddr(g_bqkv);
    float* Q  = QKV;
    float* Kb = QKV + (long long)TOK * DD;
    float* V  = QKV + 2LL * TOK * DD;
    float* AO = (float*)symaddr(g_ao);
    float* SC = (float*)symaddr(g_scores);
    float* HID = (float*)symaddr(g_hidden);
    float* YS = (float*)symaddr(g_yslot);
    float* CB = (float*)symaddr(g_Cb);
    float* MT = (float*)symaddr(g_Mt);
    float* BF = (float*)symaddr(g_bf);
    float* FR = (float*)symaddr(g_frames);
    int* CNT = (int*)symaddr(g_cnt);
    int* ETK = (int*)symaddr(g_etok);
    int* EAS = (int*)symaddr(g_easn);
    float* WTS = (float*)symaddr(g_wts);
    uint32_t* PK_INW = (uint32_t*)symaddr(g_pk_inw);
    uint32_t* PK_QKV = (uint32_t*)symaddr(g_pk_qkv);
    uint32_t* PK_WO  = (uint32_t*)symaddr(g_pk_wo);
    uint32_t* PK_E1  = (uint32_t*)symaddr(g_pk_e1);
    uint32_t* PK_E2  = (uint32_t*)symaddr(g_pk_e2);
    uint32_t* PK_MT  = (uint32_t*)symaddr(g_pk_mt);
    uint32_t* PK_CB  = (uint32_t*)symaddr(g_pk_cb);

    // ---- pre-pack static weights ----
    launch_pack(in_w, 0, CIN, DD, 1, PK_INW, SZ_INW, 0, 0);

    // in_projection: zt = z^T, x = zt @ in_w + in_b
    transpose_z<<<dim3(SS / 32, CIN / 32, BB), dim3(32, 8)>>>(z_in, ZT);
    {
        GemmArgs a = {ZT, CIN, 0, 0, nullptr, DD, 0, 0, X, DD, 0, 0, 1,
                      in_b, 0, nullptr, TOK, DD, CIN, 1.f, 1, nullptr, nullptr, nullptr, 0, 0,
                      PK_INW, PK_INW + SZ_INW, 0, DD};
        gemm(0, false, 128, a);
    }

    for (int L = 0; L < 2; L++) {
        // pack per-layer weights
        launch_pack(wq + (long long)L * DD * DD, 0, DD, DD, 1, PK_QKV, SZ_QKV, SZ_QKV1, 0);
        launch_pack(wk + (long long)L * DD * DD, 0, DD, DD, 1, PK_QKV, SZ_QKV, SZ_QKV1, SZ_QKV1);
        launch_pack(wv + (long long)L * DD * DD, 0, DD, DD, 1, PK_QKV, SZ_QKV, SZ_QKV1, 2 * SZ_QKV1);
        launch_pack(wo + (long long)L * DD * DD, 0, DD, DD, 1, PK_WO, SZ_WO, 0, 0);
        cudaMemcpyAsync(BQKV,          bq + L * DD, DD * sizeof(float), cudaMemcpyDeviceToDevice);
        cudaMemcpyAsync(BQKV + DD,     bk + L * DD, DD * sizeof(float), cudaMemcpyDeviceToDevice);
        cudaMemcpyAsync(BQKV + 2 * DD, bv + L * DD, DD * sizeof(float), cudaMemcpyDeviceToDevice);

        ln_kernel<<<TOK, 256>>>(X, H, ln1g + L * DD, ln1b + L * DD);
        {
            GemmArgs a = {H, DD, 0, 0, nullptr, DD, 0, 0,
                          QKV, DD, (long long)TOK * DD, 0, 3,
                          BQKV, DD, nullptr, TOK, DD, DD, 1.f, 3, 0, 0, 0, 0, 0,
                          PK_QKV, PK_QKV + SZ_QKV, SZ_QKV1, DD};
            gemm(0, false, 128, a);
        }
        if (L == 0)
            rope_kernel<<<(TOK * (DD / 2) + 255) / 256, 256>>>(Q, Kb);

        {
            GemmArgs a = {Q, DD, HD, (long long)SS * DD,
                          Kb, DD, HD, (long long)SS * DD,
                          SC, SS, (long long)SS * SS, (long long)HH * SS * SS, HH,
                          nullptr, 0, nullptr, SS, SS, HD, 0.125f, BB * HH, 0, 0, 0, 1, 0,
                          nullptr, nullptr, 0, 0};
            gemm(0, true, 128, a);
        }
        softmax_causal<<<dim3(SS, BB * HH), 256>>>(SC);
        {
            GemmArgs a = {SC, SS, (long long)SS * SS, (long long)HH * SS * SS,
                          V, DD, HD, (long long)SS * DD,
                          AO, DD, HD, (long long)SS * DD, HH,
                          nullptr, 0, nullptr, SS, HD, SS, 1.f, BB * HH, 0, 0, 0, 2, 0,
                          nullptr, nullptr, 0, 0};
            gemm(0, false, 64, a);
        }
        {
            GemmArgs a = {AO, DD, 0, 0, nullptr, DD, 0, 0, X, DD, 0, 0, 1,
                          bo + L * DD, 0, X, TOK, DD, DD, 1.f, 1, 0, 0, 0, 0, 0,
                          PK_WO, PK_WO + SZ_WO, 0, DD};
            gemm(0, false, 128, a);
        }

        // MoE
        launch_pack(ew1 + (long long)L * EE * DD * FF, (long long)DD * FF, DD, FF, EE,
                    PK_E1, SZ_E1, (long long)384 * FF, 0);
        ln_kernel<<<TOK, 256>>>(X, H, ln2g + L * DD, ln2b + L * DD);
        zero_cnt<<<1, 32>>>(CNT);
        route_kernel<<<TOK / 8, 256>>>(H, gatew + (long long)L * DD * EE, CNT, ETK, EAS, WTS);
        {
            GemmArgs a = {H, DD, 0, 0, nullptr, FF, 0, 0,
                          HID, FF, 0, 0, EE,
                          eb1 + (long long)L * EE * FF, FF, nullptr,
                          TOK, FF, DD, 1.f, EE, ETK, EAS, CNT, 0, TOK / 64,
                          PK_E1, PK_E1 + SZ_E1, (long long)384 * FF, FF};
            gemm(1, false, 128, a);
        }
        launch_pack(ew2 + (long long)L * EE * FF * DD, (long long)FF * DD, FF, DD, EE,
                    PK_E2, SZ_E2, (long long)1024 * DD, 0);
        {
            GemmArgs a = {HID, FF, 0, 0, nullptr, DD, 0, 0,
                          YS, DD, 0, 0, EE,
                          eb2 + (long long)L * EE * DD, DD, nullptr,
                          TOK, DD, FF, 1.f, EE, EAS, EAS, CNT, 0, TOK / 64,
                          PK_E2, PK_E2 + SZ_E2, (long long)1024 * DD, DD};
            gemm(0, false, 128, a);
        }
        combine_kernel<<<(TOK * DD + 255) / 256, 256>>>(X, YS, WTS);
    }

    // out projection fused with irfft basis: frames = x @ (out_w @ Cb) + out_b @ Cb
    basis_kernel<<<(1026 * 1024 + 255) / 256, 256>>>(CB);
    launch_pack(CB, 0, 1026, 1024, 1, PK_CB, SZ_CB, 0, 0);
    {
        GemmArgs a = {outw, 2 * FB, 0, 0, nullptr, 1024, 0, 0, MT, 1024, 0, 0, 1,
                      nullptr, 0, nullptr, DD, 1024, 2 * FB, 1.f, 1, 0, 0, 0, 0, 0,
                      PK_CB, PK_CB + SZ_CB, 0, 1024};
        gemm(0, false, 128, a);
    }
    launch_pack(MT, 0, DD, 1024, 1, PK_MT, SZ_MT, 0, 0);
    bf_kernel<<<1, 1024>>>(outb, CB, BF);
    {
        GemmArgs a = {X, DD, 0, 0, nullptr, 1024, 0, 0, FR, 1024, 0, 0, 1,
                      BF, 0, nullptr, TOK, 1024, DD, 1.f, 1, 0, 0, 0, 0, 0,
                      PK_MT, PK_MT + SZ_MT, 0, 1024};
        gemm(0, false, 128, a);
    }

    // windowed overlap-add + env normalize + trim
    istft_kernel<<<(BB * OUTL + 255) / 256, 256>>>(FR, out);
}

// round 11
// speedup vs baseline: 1.4593x; 1.4593x over previous
#include <cuda_runtime.h>
#include <math.h>
#include <stdint.h>

// ---------------- constants ----------------
#define BB 2
#define SS 1024
#define DD 768
#define HH 12
#define HD 64
#define EE 8
#define FF 2048
#define CIN 512
#define TOK (BB*SS)          // 2048
#define FB 513
#define PADL 384
#define OUTL 262144
#define TWO_PI_N 0.006135923151542565f   // 2*pi/1024

// ---------------- scratch (device globals; allocation-free) ----------------
__device__ float g_zt[TOK*CIN];
__device__ float g_x [TOK*DD];
__device__ float g_h [TOK*DD];
__device__ float g_qkv[3*TOK*DD];
__device__ float g_wqkv[3*DD*DD];
__device__ float g_bqkv[3*DD];
__device__ float g_ao[TOK*DD];
__device__ float g_scores[24u*1024u*1024u];
__device__ float g_hidden[4096*FF];
__device__ float g_yslot [4096*DD];
__device__ float g_Cb[1026*1024];
__device__ float g_Mt[DD*1024];
__device__ float g_bf[1024];
__device__ float g_frames[TOK*1024];
__device__ int   g_cnt[EE];
__device__ int   g_etok[EE*TOK];
__device__ int   g_easn[EE*TOK];
__device__ float g_wts[2*TOK];

// ---------------- bf16x3 helpers ----------------
// hi = bf16-truncate(f); lo = bf16-round(f - hi). Pack 2 consecutive-k into bf16x2.
__device__ __forceinline__ void pack_bf16pair(float f0, float f1, uint32_t& hi, uint32_t& lo) {
    uint32_t u0 = __float_as_uint(f0);
    uint32_t u1 = __float_as_uint(f1);
    uint32_t h;
    asm("prmt.b32 %0, %1, %2, 0x7632;" : "=r"(h) : "r"(u0), "r"(u1));
    hi = h;
    float l0 = f0 - __uint_as_float(u0 & 0xFFFF0000u);
    float l1 = f1 - __uint_as_float(u1 & 0xFFFF0000u);
    asm("cvt.rn.bf16x2.f32 %0, %1, %2;" : "=r"(lo) : "f"(l1), "f"(l0));
}
__device__ __forceinline__ void mma_bf16(float* c, const uint32_t* a, const uint32_t* b) {
    asm volatile(
        "mma.sync.aligned.m16n8k16.row.col.f32.bf16.bf16.f32 "
        "{%0,%1,%2,%3}, {%4,%5,%6,%7}, {%8,%9}, {%0,%1,%2,%3};"
        : "+f"(c[0]), "+f"(c[1]), "+f"(c[2]), "+f"(c[3])
        : "r"(a[0]), "r"(a[1]), "r"(a[2]), "r"(a[3]), "r"(b[0]), "r"(b[1]));
}

// ---------------- register-staged tensor-core GEMM (3xBF16, 2-stage) ----------------
// Tile: 64(M) x BN(N), K-step 16. 8 warps as 2(M) x 4(N); warp = 32 x BN/4.
#define APK_LD 12   // packed A row stride (uint32; 8 pairs + pad)
#define APK_SZ (64 * APK_LD)

template<int ACT, bool TRB, int BN>
__global__ __launch_bounds__(256, 2)
void gemm_kernel(const float* __restrict__ A, int lda, long long sAz, long long sAz2,
                 const float* __restrict__ B, int ldb, long long sBz, long long sBz2,
                 float* __restrict__ C, int ldc, long long sCz, long long sCz2,
                 int zdiv,
                 const float* __restrict__ bias, long long sbz,
                 const float* __restrict__ res,
                 int M, int N, int Kd, float alpha,
                 const int* __restrict__ idxA, const int* __restrict__ idxC,
                 const int* __restrict__ cnt, int causal)
{
    constexpr int BPK_LD = TRB ? APK_LD : (BN + 8);
    constexpr int BPK_SZ = TRB ? (BN * APK_LD) : (8 * (BN + 8));
    constexpr int STAGE  = 2 * APK_SZ + 2 * BPK_SZ;   // uint32 per stage
    constexpr int BJ = BN / 32;

    int z = blockIdx.z;
    int z1 = z / zdiv, z0 = z - z1 * zdiv;
    if (cnt) M = cnt[z];
    int m0 = blockIdx.y * 64, n0 = blockIdx.x * BN;
    if (m0 >= M) return;
    if (causal == 1 && n0 > m0 + 63) return;
    if (causal == 2) Kd = min(Kd, m0 + 64);   // AV: keys beyond row block are zero
    A += (long long)z0 * sAz + (long long)z1 * sAz2;
    B += (long long)z0 * sBz + (long long)z1 * sBz2;
    C += (long long)z0 * sCz + (long long)z1 * sCz2;
    if (bias) bias += (long long)z * sbz;
    if (res)  res  += (long long)z0 * sCz + (long long)z1 * sCz2;
    const int* iA = idxA ? idxA + z * TOK : nullptr;
    const int* iC = idxC ? idxC + z * TOK : nullptr;

    extern __shared__ uint32_t smem[];

    int tid = threadIdx.x;
    int lane = tid & 31, wid = tid >> 5;
    int wm = wid >> 2, wn = wid & 3;
    int lm = lane >> 2, lk = lane & 3;

    float acc[2][BJ][4];
#pragma unroll
    for (int i = 0; i < 2; i++)
#pragma unroll
        for (int j = 0; j < BJ; j++)
#pragma unroll
            for (int r = 0; r < 4; r++) acc[i][j][r] = 0.f;

    const bool fastA = ((lda & 3) == 0) && ((Kd & 15) == 0);
    const bool fastB = ((ldb & 3) == 0) && (TRB ? ((Kd & 15) == 0) : true);

    // per-thread register staging
    float rA[4];
    float rB[8];
    int mmA = tid >> 2, qA = tid & 3;
    int raA = -1;
    {
        int gm = m0 + mmA;
        if (gm < M) raA = iA ? iA[gm] : gm;
    }
    int pB = 0, nqB = 0;
    bool bAct = true;
    if (!TRB) {
        if (BN == 128) { pB = tid >> 5; nqB = tid & 31; }
        else { pB = tid >> 4; nqB = tid & 15; bAct = (tid < 128); }
    }

    auto load_regs = [&](int k0) {
        // ---- A ----
        if (raA >= 0) {
            if (fastA) {
                const float4 v = *(const float4*)(A + (long long)raA * lda + k0 + 4 * qA);
                rA[0] = v.x; rA[1] = v.y; rA[2] = v.z; rA[3] = v.w;
            } else {
#pragma unroll
                for (int j = 0; j < 4; j++) {
                    int gk = k0 + 4 * qA + j;
                    rA[j] = (gk < Kd) ? A[(long long)raA * lda + gk] : 0.f;
                }
            }
        } else {
            rA[0] = rA[1] = rA[2] = rA[3] = 0.f;
        }
        // ---- B ----
        if (!TRB) {
            if (bAct) {
                int gk0 = k0 + 2 * pB;
                int nb = n0 + 4 * nqB;
#pragma unroll
                for (int r = 0; r < 2; r++) {
                    int gk = gk0 + r;
                    if (gk < Kd) {
                        if (fastB) {
                            const float4 v = *(const float4*)(B + (long long)gk * ldb + nb);
                            rB[4 * r + 0] = v.x; rB[4 * r + 1] = v.y;
                            rB[4 * r + 2] = v.z; rB[4 * r + 3] = v.w;
                        } else {
#pragma unroll
                            for (int j = 0; j < 4; j++)
                                rB[4 * r + j] = B[(long long)gk * ldb + nb + j];
                        }
                    } else {
                        rB[4 * r + 0] = rB[4 * r + 1] = rB[4 * r + 2] = rB[4 * r + 3] = 0.f;
                    }
                }
            }
        } else {
#pragma unroll
            for (int it = 0; it < BN / 64; it++) {
                int lin = tid + it * 256;
                int nn = lin >> 2, q = lin & 3;
                int gn = n0 + nn;
                if (gn < N) {
                    if (fastB) {
                        const float4 v = *(const float4*)(B + (long long)gn * ldb + k0 + 4 * q);
                        rB[4 * it + 0] = v.x; rB[4 * it + 1] = v.y;
                        rB[4 * it + 2] = v.z; rB[4 * it + 3] = v.w;
                    } else {
#pragma unroll
                        for (int j = 0; j < 4; j++) {
                            int gk = k0 + 4 * q + j;
                            rB[4 * it + j] = (gk < Kd) ? B[(long long)gn * ldb + gk] : 0.f;
                        }
                    }
                } else {
                    rB[4 * it + 0] = rB[4 * it + 1] = rB[4 * it + 2] = rB[4 * it + 3] = 0.f;
                }
            }
        }
    };

    auto convert_stage = [&](int s) {
        uint32_t* Aph = smem + s * STAGE;
        uint32_t* Apl = Aph + APK_SZ;
        uint32_t* Bph = Apl + APK_SZ;
        uint32_t* Bpl = Bph + BPK_SZ;
        {
            uint32_t hi, lo;
            pack_bf16pair(rA[0], rA[1], hi, lo);
            Aph[mmA * APK_LD + 2 * qA] = hi;
            Apl[mmA * APK_LD + 2 * qA] = lo;
            pack_bf16pair(rA[2], rA[3], hi, lo);
            Aph[mmA * APK_LD + 2 * qA + 1] = hi;
            Apl[mmA * APK_LD + 2 * qA + 1] = lo;
        }
        if (!TRB) {
            if (bAct) {
#pragma unroll
                for (int j = 0; j < 4; j++) {
                    uint32_t hi, lo;
                    pack_bf16pair(rB[j], rB[4 + j], hi, lo);
                    Bph[pB * BPK_LD + 4 * nqB + j] = hi;
                    Bpl[pB * BPK_LD + 4 * nqB + j] = lo;
                }
            }
        } else {
#pragma unroll
            for (int it = 0; it < BN / 64; it++) {
                int lin = tid + it * 256;
                int nn = lin >> 2, q = lin & 3;
                uint32_t hi, lo;
                pack_bf16pair(rB[4 * it + 0], rB[4 * it + 1], hi, lo);
                Bph[nn * BPK_LD + 2 * q] = hi;
                Bpl[nn * BPK_LD + 2 * q] = lo;
                pack_bf16pair(rB[4 * it + 2], rB[4 * it + 3], hi, lo);
                Bph[nn * BPK_LD + 2 * q + 1] = hi;
                Bpl[nn * BPK_LD + 2 * q + 1] = lo;
            }
        }
    };

    auto compute = [&](int s) {
        const uint32_t* Aph = smem + s * STAGE;
        const uint32_t* Apl = Aph + APK_SZ;
        const uint32_t* Bph = Apl + APK_SZ;
        const uint32_t* Bpl = Bph + BPK_SZ;
        uint32_t ah[2][4], al[2][4];
#pragma unroll
        for (int i = 0; i < 2; i++) {
            int r0 = wm * 32 + i * 16 + lm;
            ah[i][0] = Aph[r0 * APK_LD + lk];
            ah[i][1] = Aph[(r0 + 8) * APK_LD + lk];
            ah[i][2] = Aph[r0 * APK_LD + lk + 4];
            ah[i][3] = Aph[(r0 + 8) * APK_LD + lk + 4];
            al[i][0] = Apl[r0 * APK_LD + lk];
            al[i][1] = Apl[(r0 + 8) * APK_LD + lk];
            al[i][2] = Apl[r0 * APK_LD + lk + 4];
            al[i][3] = Apl[(r0 + 8) * APK_LD + lk + 4];
        }
#pragma unroll
        for (int j = 0; j < BJ; j++) {
            int bn = wn * (BN / 4) + j * 8 + lm;
            uint32_t bh[2], bl[2];
            if (!TRB) {
                bh[0] = Bph[lk * BPK_LD + bn];
                bh[1] = Bph[(lk + 4) * BPK_LD + bn];
                bl[0] = Bpl[lk * BPK_LD + bn];
                bl[1] = Bpl[(lk + 4) * BPK_LD + bn];
            } else {
                bh[0] = Bph[bn * BPK_LD + lk];
                bh[1] = Bph[bn * BPK_LD + lk + 4];
                bl[0] = Bpl[bn * BPK_LD + lk];
                bl[1] = Bpl[bn * BPK_LD + lk + 4];
            }
            // hh + lh + hl (ll dropped, ~2^-16)
            mma_bf16(acc[0][j], ah[0], bh);
            mma_bf16(acc[1][j], ah[1], bh);
            mma_bf16(acc[0][j], al[0], bh);
            mma_bf16(acc[1][j], al[1], bh);
            mma_bf16(acc[0][j], ah[0], bl);
            mma_bf16(acc[1][j], ah[1], bl);
        }
    };

    int nk = (Kd + 15) >> 4;
    // prologue
    load_regs(0);
    convert_stage(0);
    if (nk > 1) load_regs(16);
    __syncthreads();
    for (int i = 0; i < nk; i++) {
        compute(i & 1);
        if (i + 1 < nk) {
            convert_stage((i + 1) & 1);
            if (i + 2 < nk) load_regs((i + 2) * 16);
        }
        __syncthreads();
    }

    // ---- epilogue ----
#pragma unroll
    for (int i = 0; i < 2; i++) {
#pragma unroll
        for (int r2 = 0; r2 < 2; r2++) {
            int gm = m0 + wm * 32 + i * 16 + lm + r2 * 8;
            if (gm >= M) continue;
            int rc = iC ? iC[gm] : gm;
            float* crow = C + (long long)rc * ldc;
            const float* rrow = res ? res + (long long)rc * ldc : nullptr;
#pragma unroll
            for (int j = 0; j < BJ; j++) {
#pragma unroll
                for (int c2 = 0; c2 < 2; c2++) {
                    int gn = n0 + wn * (BN / 4) + j * 8 + lk * 2 + c2;
                    if (gn >= N) continue;
                    float v = acc[i][j][r2 * 2 + c2] * alpha;
                    if (bias) v += bias[gn];
                    if (ACT == 1) {
                        float x = v;
                        float t = tanhf(0.7978845608028654f * (x + 0.044715f * x * x * x));
                        v = 0.5f * x * (1.f + t);
                    }
                    if (rrow) v += rrow[gn];
                    crow[gn] = v;
                }
            }
        }
    }
}

// ---------------- small kernels ----------------
__global__ void transpose_z(const float* __restrict__ z, float* __restrict__ zt) {
    __shared__ float tile[32][33];
    int b = blockIdx.z;
    int l0 = blockIdx.x * 32, c0 = blockIdx.y * 32;
    int x = threadIdx.x, y = threadIdx.y;
    for (int i = y; i < 32; i += 8)
        tile[i][x] = z[b * CIN * SS + (c0 + i) * SS + l0 + x];
    __syncthreads();
    for (int i = y; i < 32; i += 8)
        zt[b * SS * CIN + (long long)(l0 + i) * CIN + c0 + x] = tile[x][i];
}

__global__ void ln_kernel(const float* __restrict__ x, float* __restrict__ y,
                          const float* __restrict__ g, const float* __restrict__ b) {
    int row = blockIdx.x;
    const float* xr = x + (long long)row * DD;
    __shared__ float sh[32];
    __shared__ float sh2[32];
    float s = 0.f, s2 = 0.f;
    for (int d = threadIdx.x; d < DD; d += 256) { float v = xr[d]; s += v; s2 += v * v; }
    int lane = threadIdx.x & 31, wid = threadIdx.x >> 5;
    for (int o = 16; o; o >>= 1) { s += __shfl_xor_sync(~0u, s, o); s2 += __shfl_xor_sync(~0u, s2, o); }
    if (lane == 0) { sh[wid] = s; sh2[wid] = s2; }
    __syncthreads();
    if (wid == 0) {
        s  = (lane < 8) ? sh[lane]  : 0.f;
        s2 = (lane < 8) ? sh2[lane] : 0.f;
        for (int o = 16; o; o >>= 1) { s += __shfl_xor_sync(~0u, s, o); s2 += __shfl_xor_sync(~0u, s2, o); }
        if (lane == 0) { sh[0] = s; sh2[0] = s2; }
    }
    __syncthreads();
    float mean = sh[0] / DD;
    float var  = sh2[0] / DD - mean * mean;
    float inv = rsqrtf(var + 1e-5f);
    float* yr = y + (long long)row * DD;
    for (int d = threadIdx.x; d < DD; d += 256)
        yr[d] = (xr[d] - mean) * inv * g[d] + b[d];
}

__global__ void rope_kernel(float* __restrict__ q, float* __restrict__ k) {
    int idx = blockIdx.x * blockDim.x + threadIdx.x;
    if (idx >= TOK * (DD / 2)) return;
    int t = idx / (DD / 2), j = idx - t * (DD / 2);
    int s = t & (SS - 1);
    float freq = __expf(-9.210340371976184f * ((float)j / 384.f));
    float ang = (float)s * freq;
    float c, sn; sincosf(ang, &sn, &c);
    {
        float* p = q + (long long)t * DD + 2 * j;
        float a = p[0], b = p[1];
        p[0] = a * c - b * sn; p[1] = a * sn + b * c;
    }
    {
        float* p = k + (long long)t * DD + 2 * j;
        float a = p[0], b = p[1];
        p[0] = a * c - b * sn; p[1] = a * sn + b * c;
    }
}

__global__ void softmax_causal(float* __restrict__ sc) {
    int z = blockIdx.y, r = blockIdx.x;
    float* row = sc + ((long long)z << 20) + (long long)r * 1024;
    int n = r + 1;
    int nz = (r & ~63) + 64;   // AV (causal=2) reads only up to the row's 64-block end
    __shared__ float sh[32];
    int lane = threadIdx.x & 31, wid = threadIdx.x >> 5;
    float mx = -1e30f;
    for (int j = threadIdx.x; j < n; j += 256) mx = fmaxf(mx, row[j]);
    for (int o = 16; o; o >>= 1) mx = fmaxf(mx, __shfl_xor_sync(~0u, mx, o));
    if (lane == 0) sh[wid] = mx;
    __syncthreads();
    if (wid == 0) {
        mx = (lane < 8) ? sh[lane] : -1e30f;
        for (int o = 16; o; o >>= 1) mx = fmaxf(mx, __shfl_xor_sync(~0u, mx, o));
        if (lane == 0) sh[0] = mx;
    }
    __syncthreads();
    mx = sh[0];
    __syncthreads();
    float s = 0.f;
    for (int j = threadIdx.x; j < n; j += 256) s += __expf(row[j] - mx);
    for (int o = 16; o; o >>= 1) s += __shfl_xor_sync(~0u, s, o);
    if (lane == 0) sh[wid] = s;
    __syncthreads();
    if (wid == 0) {
        s = (lane < 8) ? sh[lane] : 0.f;
        for (int o = 16; o; o >>= 1) s += __shfl_xor_sync(~0u, s, o);
        if (lane == 0) sh[0] = s;
    }
    __syncthreads();
    float inv = 1.f / sh[0];
    for (int j = threadIdx.x; j < nz; j += 256)
        row[j] = (j < n) ? __expf(row[j] - mx) * inv : 0.f;
}

__global__ void zero_cnt(int* c) { if (threadIdx.x < EE) c[threadIdx.x] = 0; }

__global__ void route_kernel(const float* __restrict__ h, const float* __restrict__ gw,
                             int* cnt, int* etok, int* easn, float* wts) {
    int w = (blockIdx.x * blockDim.x + threadIdx.x) >> 5;
    int lane = threadIdx.x & 31;
    if (w >= TOK) return;
    const float* hr = h + (long long)w * DD;
    float lg[EE];
#pragma unroll
    for (int e = 0; e < EE; e++) {
        float s = 0.f;
        for (int d = lane; d < DD; d += 32) s += hr[d] * gw[d * EE + e];
        for (int o = 16; o; o >>= 1) s += __shfl_xor_sync(~0u, s, o);
        lg[e] = s;
    }
    if (lane == 0) {
        int e0 = 0;
        for (int e = 1; e < EE; e++) if (lg[e] > lg[e0]) e0 = e;
        int e1 = -1;
        for (int e = 0; e < EE; e++) { if (e == e0) continue; if (e1 < 0 || lg[e] > lg[e1]) e1 = e; }
        float x1 = __expf(lg[e1] - lg[e0]);
        float den = 1.f + x1;
        float w0 = 1.f / den, w1 = x1 / den;
        int s0 = atomicAdd(&cnt[e0], 1);
        etok[e0 * TOK + s0] = w; easn[e0 * TOK + s0] = 2 * w;
        int s1 = atomicAdd(&cnt[e1], 1);
        etok[e1 * TOK + s1] = w; easn[e1 * TOK + s1] = 2 * w + 1;
        wts[2 * w] = w0; wts[2 * w + 1] = w1;
    }
}

__global__ void combine_kernel(float* __restrict__ x, const float* __restrict__ ys,
                               const float* __restrict__ wts) {
    int idx = blockIdx.x * blockDim.x + threadIdx.x;
    if (idx >= TOK * DD) return;
    int t = idx / DD, d = idx - t * DD;
    x[idx] += wts[2 * t] * ys[(long long)(2 * t) * DD + d]
            + wts[2 * t + 1] * ys[(long long)(2 * t + 1) * DD + d];
}

__global__ void basis_kernel(float* __restrict__ Cb) {
    int idx = blockIdx.x * blockDim.x + threadIdx.x;
    if (idx >= 1026 * 1024) return;
    int j = idx >> 10, n = idx & 1023;
    const float invN = 1.f / 1024.f;
    float v;
    if (j == 0) v = invN;
    else if (j <= 511) { int m = (j * n) & 1023; v = 2.f * invN * cosf(m * TWO_PI_N); }
    else if (j == 512) v = invN * ((n & 1) ? -1.f : 1.f);
    else if (j == 513 || j == 1025) v = 0.f;
    else { int kk = j - 513; int m = (kk * n) & 1023; v = -2.f * invN * sinf(m * TWO_PI_N); }
    Cb[idx] = v;
}

__global__ void bf_kernel(const float* __restrict__ ob, const float* __restrict__ Cb,
                          float* __restrict__ bf) {
    int n = blockIdx.x * 128 + threadIdx.x;
    float s = 0.f;
    for (int j = 0; j < 1026; j++) s += ob[j] * Cb[j * 1024 + n];
    bf[n] = s;
}

__global__ void istft_kernel(const float* __restrict__ frames, float* __restrict__ out) {
    int idx = blockIdx.x * blockDim.x + threadIdx.x;
    if (idx >= BB * OUTL) return;
    int b = idx / OUTL, i = idx - b * OUTL;
    int ip = i + PADL;
    int tmin = (ip >= 1024) ? ((ip - 768) >> 8) : 0;
    int tmax = min(1023, ip >> 8);
    float acc = 0.f, env = 0.f;
    for (int t = tmin; t <= tmax; t++) {
        int n = ip - (t << 8);
        float w = 0.5f * (1.f - cosf(n * TWO_PI_N));
        acc += frames[((long long)(b * 1024 + t) << 10) + n] * w;
        env += w * w;
    }
    out[idx] = acc / env;
}

// ---------------- host side ----------------
static void* symaddr(const void* sym) {
    void* p = nullptr;
    cudaGetSymbolAddress(&p, sym);
    return p;
}

struct GemmArgs {
    const float* A; int lda; long long sAz, sAz2;
    const float* B; int ldb; long long sBz, sBz2;
    float* C; int ldc; long long sCz, sCz2;
    int zdiv;
    const float* bias; long long sbz; const float* res;
    int M, N, Kd; float alpha; int Z;
    const int* idxA; const int* idxC; const int* cnt;
    int causal; int gridM;
};

#define BPK_SZH(TRB, BN) ((TRB) ? ((BN) * APK_LD) : (8 * ((BN) + 8)))
#define SMEM_BYTES(TRB, BN) (4 * 2 * (2 * APK_SZ + 2 * BPK_SZH(TRB, BN)))

static void gemm(int act, bool trb, int BN, const GemmArgs& a)
{
    dim3 grid((a.N + BN - 1) / BN, a.gridM ? a.gridM : (a.M + 63) / 64, a.Z);
    if (act == 1) {
        size_t shm = SMEM_BYTES(false, 128);
        cudaFuncSetAttribute(gemm_kernel<1, false, 128>, cudaFuncAttributeMaxDynamicSharedMemorySize, (int)shm);
        gemm_kernel<1, false, 128><<<grid, 256, shm>>>(a.A, a.lda, a.sAz, a.sAz2, a.B, a.ldb, a.sBz, a.sBz2,
            a.C, a.ldc, a.sCz, a.sCz2, a.zdiv, a.bias, a.sbz, a.res,
            a.M, a.N, a.Kd, a.alpha, a.idxA, a.idxC, a.cnt, a.causal);
    } else if (trb) {
        size_t shm = SMEM_BYTES(true, 128);
        cudaFuncSetAttribute(gemm_kernel<0, true, 128>, cudaFuncAttributeMaxDynamicSharedMemorySize, (int)shm);
        gemm_kernel<0, true, 128><<<grid, 256, shm>>>(a.A, a.lda, a.sAz, a.sAz2, a.B, a.ldb, a.sBz, a.sBz2,
            a.C, a.ldc, a.sCz, a.sCz2, a.zdiv, a.bias, a.sbz, a.res,
            a.M, a.N, a.Kd, a.alpha, a.idxA, a.idxC, a.cnt, a.causal);
    } else if (BN == 128) {
        size_t shm = SMEM_BYTES(false, 128);
        cudaFuncSetAttribute(gemm_kernel<0, false, 128>, cudaFuncAttributeMaxDynamicSharedMemorySize, (int)shm);
        gemm_kernel<0, false, 128><<<grid, 256, shm>>>(a.A, a.lda, a.sAz, a.sAz2, a.B, a.ldb, a.sBz, a.sBz2,
            a.C, a.ldc, a.sCz, a.sCz2, a.zdiv, a.bias, a.sbz, a.res,
            a.M, a.N, a.Kd, a.alpha, a.idxA, a.idxC, a.cnt, a.causal);
    } else {
        size_t shm = SMEM_BYTES(false, 64);
        cudaFuncSetAttribute(gemm_kernel<0, false, 64>, cudaFuncAttributeMaxDynamicSharedMemorySize, (int)shm);
        gemm_kernel<0, false, 64><<<grid, 256, shm>>>(a.A, a.lda, a.sAz, a.sAz2, a.B, a.ldb, a.sBz, a.sBz2,
            a.C, a.ldc, a.sCz, a.sCz2, a.zdiv, a.bias, a.sbz, a.res,
            a.M, a.N, a.Kd, a.alpha, a.idxA, a.idxC, a.cnt, a.causal);
    }
}

extern "C" void kernel_launch(void* const* d_in, const int* in_sizes, int n_in,
                              void* d_out, int out_size)
{
    const float* z_in  = (const float*)d_in[0];
    const float* in_w  = (const float*)d_in[1];
    const float* in_b  = (const float*)d_in[2];
    const float* ln1g  = (const float*)d_in[3];
    const float* ln1b  = (const float*)d_in[4];
    const float* wq    = (const float*)d_in[5];
    const float* bq    = (const float*)d_in[6];
    const float* wk    = (const float*)d_in[7];
    const float* bk    = (const float*)d_in[8];
    const float* wv    = (const float*)d_in[9];
    const float* bv    = (const float*)d_in[10];
    const float* wo    = (const float*)d_in[11];
    const float* bo    = (const float*)d_in[12];
    const float* ln2g  = (const float*)d_in[13];
    const float* ln2b  = (const float*)d_in[14];
    const float* gatew = (const float*)d_in[15];
    const float* ew1   = (const float*)d_in[16];
    const float* eb1   = (const float*)d_in[17];
    const float* ew2   = (const float*)d_in[18];
    const float* eb2   = (const float*)d_in[19];
    const float* outw  = (const float*)d_in[20];
    const float* outb  = (const float*)d_in[21];
    float* out = (float*)d_out;

    float* ZT = (float*)symaddr(g_zt);
    float* X  = (float*)symaddr(g_x);
    float* H  = (float*)symaddr(g_h);
    float* QKV = (float*)symaddr(g_qkv);
    float* WQKV = (float*)symaddr(g_wqkv);
    float* BQKV = (float*)symaddr(g_bqkv);
    float* Q  = QKV;
    float* Kb = QKV + (long long)TOK * DD;
    float* V  = QKV + 2LL * TOK * DD;
    float* AO = (float*)symaddr(g_ao);
    float* SC = (float*)symaddr(g_scores);
    float* HID = (float*)symaddr(g_hidden);
    float* YS = (float*)symaddr(g_yslot);
    float* CB = (float*)symaddr(g_Cb);
    float* MT = (float*)symaddr(g_Mt);
    float* BF = (float*)symaddr(g_bf);
    float* FR = (float*)symaddr(g_frames);
    int* CNT = (int*)symaddr(g_cnt);
    int* ETK = (int*)symaddr(g_etok);
    int* EAS = (int*)symaddr(g_easn);
    float* WTS = (float*)symaddr(g_wts);

    // in_projection: zt = z^T, x = zt @ in_w + in_b
    transpose_z<<<dim3(SS / 32, CIN / 32, BB), dim3(32, 8)>>>(z_in, ZT);
    {
        GemmArgs a = {ZT, CIN, 0, 0, in_w, DD, 0, 0, X, DD, 0, 0, 1,
                      in_b, 0, nullptr, TOK, DD, CIN, 1.f, 1, nullptr, nullptr, nullptr, 0, 0};
        gemm(0, false, 128, a);
    }

    for (int L = 0; L < 2; L++) {
        const size_t WSZ = (size_t)DD * DD * sizeof(float);
        cudaMemcpyAsync(WQKV,               wq + (long long)L * DD * DD, WSZ, cudaMemcpyDeviceToDevice);
        cudaMemcpyAsync(WQKV + DD * DD,     wk + (long long)L * DD * DD, WSZ, cudaMemcpyDeviceToDevice);
        cudaMemcpyAsync(WQKV + 2 * DD * DD, wv + (long long)L * DD * DD, WSZ, cudaMemcpyDeviceToDevice);
        cudaMemcpyAsync(BQKV,          bq + L * DD, DD * sizeof(float), cudaMemcpyDeviceToDevice);
        cudaMemcpyAsync(BQKV + DD,     bk + L * DD, DD * sizeof(float), cudaMemcpyDeviceToDevice);
        cudaMemcpyAsync(BQKV + 2 * DD, bv + L * DD, DD * sizeof(float), cudaMemcpyDeviceToDevice);

        ln_kernel<<<TOK, 256>>>(X, H, ln1g + L * DD, ln1b + L * DD);
        {
            GemmArgs a = {H, DD, 0, 0, WQKV, DD, (long long)DD * DD, 0,
                          QKV, DD, (long long)TOK * DD, 0, 3,
                          BQKV, DD, nullptr, TOK, DD, DD, 1.f, 3, 0, 0, 0, 0, 0};
            gemm(0, false, 128, a);
        }
        if (L == 0)
            rope_kernel<<<(TOK * (DD / 2) + 255) / 256, 256>>>(Q, Kb);

        {
            GemmArgs a = {Q, DD, HD, (long long)SS * DD,
                          Kb, DD, HD, (long long)SS * DD,
                          SC, SS, (long long)SS * SS, (long long)HH * SS * SS, HH,
                          nullptr, 0, nullptr, SS, SS, HD, 0.125f, BB * HH, 0, 0, 0, 1, 0};
            gemm(0, true, 128, a);
        }
        softmax_causal<<<dim3(SS, BB * HH), 256>>>(SC);
        {
            GemmArgs a = {SC, SS, (long long)SS * SS, (long long)HH * SS * SS,
                          V, DD, HD, (long long)SS * DD,
                          AO, DD, HD, (long long)SS * DD, HH,
                          nullptr, 0, nullptr, SS, HD, SS, 1.f, BB * HH, 0, 0, 0, 2, 0};
            gemm(0, false, 64, a);
        }
        {
            GemmArgs a = {AO, DD, 0, 0, wo + (long long)L * DD * DD, DD, 0, 0, X, DD, 0, 0, 1,
                          bo + L * DD, 0, X, TOK, DD, DD, 1.f, 1, 0, 0, 0, 0, 0};
            gemm(0, false, 128, a);
        }

        // MoE
        ln_kernel<<<TOK, 256>>>(X, H, ln2g + L * DD, ln2b + L * DD);
        zero_cnt<<<1, 32>>>(CNT);
        route_kernel<<<TOK / 8, 256>>>(H, gatew + (long long)L * DD * EE, CNT, ETK, EAS, WTS);
        {
            GemmArgs a = {H, DD, 0, 0,
                          ew1 + (long long)L * EE * DD * FF, FF, (long long)DD * FF, 0,
                          HID, FF, 0, 0, EE,
                          eb1 + (long long)L * EE * FF, FF, nullptr,
                          TOK, FF, DD, 1.f, EE, ETK, EAS, CNT, 0, TOK / 64};
            gemm(1, false, 128, a);
        }
        {
            GemmArgs a = {HID, FF, 0, 0,
                          ew2 + (long long)L * EE * FF * DD, DD, (long long)FF * DD, 0,
                          YS, DD, 0, 0, EE,
                          eb2 + (long long)L * EE * DD, DD, nullptr,
                          TOK, DD, FF, 1.f, EE, EAS, EAS, CNT, 0, TOK / 64};
            gemm(0, false, 128, a);
        }
        combine_kernel<<<(TOK * DD + 255) / 256, 256>>>(X, YS, WTS);
    }

    // out projection fused with irfft basis: frames = x @ (out_w @ Cb) + out_b @ Cb
    basis_kernel<<<(1026 * 1024 + 255) / 256, 256>>>(CB);
    {
        GemmArgs a = {outw, 2 * FB, 0, 0, CB, 1024, 0, 0, MT, 1024, 0, 0, 1,
                      nullptr, 0, nullptr, DD, 1024, 2 * FB, 1.f, 1, 0, 0, 0, 0, 0};
        gemm(0, false, 128, a);
    }
    bf_kernel<<<8, 128>>>(outb, CB, BF);
    {
        GemmArgs a = {X, DD, 0, 0, MT, 1024, 0, 0, FR, 1024, 0, 0, 1,
                      BF, 0, nullptr, TOK, 1024, DD, 1.f, 1, 0, 0, 0, 0, 0};
        gemm(0, false, 128, a);
    }

    // windowed overlap-add + env normalize + trim
    istft_kernel<<<(BB * OUTL + 255) / 256, 256>>>(FR, out);
}

// round 14
// speedup vs baseline: 1.5344x; 1.0515x over previous
#include <cuda_runtime.h>
#include <math.h>
#include <stdint.h>

// ---------------- constants ----------------
#define BB 2
#define SS 1024
#define DD 768
#define HH 12
#define HD 64
#define EE 8
#define FF 2048
#define CIN 512
#define TOK (BB*SS)          // 2048
#define FB 513
#define PADL 384
#define OUTL 262144
#define TWO_PI_N 0.006135923151542565f   // 2*pi/1024

// ---------------- scratch (device globals; allocation-free) ----------------
__device__ float g_zt[TOK*CIN];
__device__ float g_x [TOK*DD];
__device__ float g_h [TOK*DD];
__device__ float g_qkv[3*TOK*DD];
__device__ float g_wqkv[3*DD*DD];
__device__ float g_bqkv[3*DD];
__device__ float g_ao[TOK*DD];
__device__ float g_scores[24u*1024u*1024u];
__device__ float g_hidden[4096*FF];
__device__ float g_yslot [4096*DD];
__device__ float g_Cb[1026*1024];
__device__ float g_Mt[DD*1024];
__device__ float g_bf[1024];
__device__ float g_frames[TOK*1024];
__device__ int   g_cnt[EE];
__device__ int   g_etok[EE*TOK];
__device__ int   g_easn[EE*TOK];
__device__ float g_wts[2*TOK];

// ---------------- bf16x3 helpers ----------------
// hi = bf16-truncate(f); lo = bf16-round(f - hi). Pack 2 consecutive-k into bf16x2.
__device__ __forceinline__ void pack_bf16pair(float f0, float f1, uint32_t& hi, uint32_t& lo) {
    uint32_t u0 = __float_as_uint(f0);
    uint32_t u1 = __float_as_uint(f1);
    uint32_t h;
    asm("prmt.b32 %0, %1, %2, 0x7632;" : "=r"(h) : "r"(u0), "r"(u1));
    hi = h;
    float l0 = f0 - __uint_as_float(u0 & 0xFFFF0000u);
    float l1 = f1 - __uint_as_float(u1 & 0xFFFF0000u);
    asm("cvt.rn.bf16x2.f32 %0, %1, %2;" : "=r"(lo) : "f"(l1), "f"(l0));
}
__device__ __forceinline__ void mma_bf16(float* c, const uint32_t* a, const uint32_t* b) {
    asm volatile(
        "mma.sync.aligned.m16n8k16.row.col.f32.bf16.bf16.f32 "
        "{%0,%1,%2,%3}, {%4,%5,%6,%7}, {%8,%9}, {%0,%1,%2,%3};"
        : "+f"(c[0]), "+f"(c[1]), "+f"(c[2]), "+f"(c[3])
        : "r"(a[0]), "r"(a[1]), "r"(a[2]), "r"(a[3]), "r"(b[0]), "r"(b[1]));
}
__device__ __forceinline__ void ldsm4(uint32_t& r0, uint32_t& r1, uint32_t& r2, uint32_t& r3, uint32_t addr) {
    asm volatile("ldmatrix.sync.aligned.m8n8.x4.shared.b16 {%0,%1,%2,%3}, [%4];"
        : "=r"(r0), "=r"(r1), "=r"(r2), "=r"(r3) : "r"(addr));
}
__device__ __forceinline__ void ldsm2(uint32_t& r0, uint32_t& r1, uint32_t addr) {
    asm volatile("ldmatrix.sync.aligned.m8n8.x2.shared.b16 {%0,%1}, [%2];"
        : "=r"(r0), "=r"(r1) : "r"(addr));
}

// ---------------- register-staged tensor-core GEMM (3xBF16, 2-stage) ----------------
// Tile: 64(M) x BN(N), K-step 16. 8 warps as 2(M) x 4(N); warp = 32 x BN/4.
#define APK_LD 12   // packed A row stride (uint32; 8 pairs + pad)
#define APK_SZ (64 * APK_LD)

template<int ACT, bool TRB, int BN>
__global__ __launch_bounds__(256, 2)
void gemm_kernel(const float* __restrict__ A, int lda, long long sAz, long long sAz2,
                 const float* __restrict__ B, int ldb, long long sBz, long long sBz2,
                 float* __restrict__ C, int ldc, long long sCz, long long sCz2,
                 int zdiv,
                 const float* __restrict__ bias, long long sbz,
                 const float* __restrict__ res,
                 int M, int N, int Kd, float alpha,
                 const int* __restrict__ idxA, const int* __restrict__ idxC,
                 const int* __restrict__ cnt, int causal)
{
    constexpr int BPK_LD = TRB ? APK_LD : (BN + 8);
    constexpr int BPK_SZ = TRB ? (BN * APK_LD) : (8 * (BN + 8));
    constexpr int STAGE  = 2 * APK_SZ + 2 * BPK_SZ;   // uint32 per stage
    constexpr int BJ = BN / 32;

    int z = blockIdx.z;
    int z1 = z / zdiv, z0 = z - z1 * zdiv;
    if (cnt) M = cnt[z];
    int m0 = blockIdx.y * 64, n0 = blockIdx.x * BN;
    if (m0 >= M) return;
    if (causal == 1 && n0 > m0 + 63) return;
    if (causal == 2) Kd = min(Kd, m0 + 64);   // AV: keys beyond row block are zero
    A += (long long)z0 * sAz + (long long)z1 * sAz2;
    B += (long long)z0 * sBz + (long long)z1 * sBz2;
    C += (long long)z0 * sCz + (long long)z1 * sCz2;
    if (bias) bias += (long long)z * sbz;
    if (res)  res  += (long long)z0 * sCz + (long long)z1 * sCz2;
    const int* iA = idxA ? idxA + z * TOK : nullptr;
    const int* iC = idxC ? idxC + z * TOK : nullptr;

    extern __shared__ uint32_t smem[];
    uint32_t smemAddr = (uint32_t)__cvta_generic_to_shared(smem);

    int tid = threadIdx.x;
    int lane = tid & 31, wid = tid >> 5;
    int wm = wid >> 2, wn = wid & 3;
    int lm = lane >> 2, lk = lane & 3;

    float acc[2][BJ][4];
#pragma unroll
    for (int i = 0; i < 2; i++)
#pragma unroll
        for (int j = 0; j < BJ; j++)
#pragma unroll
            for (int r = 0; r < 4; r++) acc[i][j][r] = 0.f;

    const bool fastA = ((lda & 3) == 0) && ((Kd & 15) == 0);
    const bool fastB = ((ldb & 3) == 0) && (TRB ? ((Kd & 15) == 0) : true);

    // per-thread register staging
    float rA[4];
    float rB[8];
    int mmA = tid >> 2, qA = tid & 3;
    int raA = -1;
    {
        int gm = m0 + mmA;
        if (gm < M) raA = iA ? iA[gm] : gm;
    }
    int pB = 0, nqB = 0;
    bool bAct = true;
    if (!TRB) {
        if (BN == 128) { pB = tid >> 5; nqB = tid & 31; }
        else { pB = tid >> 4; nqB = tid & 15; bAct = (tid < 128); }
    }

    auto load_regs = [&](int k0) {
        // ---- A ----
        if (raA >= 0) {
            if (fastA) {
                const float4 v = *(const float4*)(A + (long long)raA * lda + k0 + 4 * qA);
                rA[0] = v.x; rA[1] = v.y; rA[2] = v.z; rA[3] = v.w;
            } else {
#pragma unroll
                for (int j = 0; j < 4; j++) {
                    int gk = k0 + 4 * qA + j;
                    rA[j] = (gk < Kd) ? A[(long long)raA * lda + gk] : 0.f;
                }
            }
        } else {
            rA[0] = rA[1] = rA[2] = rA[3] = 0.f;
        }
        // ---- B ----
        if (!TRB) {
            if (bAct) {
                int gk0 = k0 + 2 * pB;
                int nb = n0 + 4 * nqB;
#pragma unroll
                for (int r = 0; r < 2; r++) {
                    int gk = gk0 + r;
                    if (gk < Kd) {
                        if (fastB) {
                            const float4 v = *(const float4*)(B + (long long)gk * ldb + nb);
                            rB[4 * r + 0] = v.x; rB[4 * r + 1] = v.y;
                            rB[4 * r + 2] = v.z; rB[4 * r + 3] = v.w;
                        } else {
#pragma unroll
                            for (int j = 0; j < 4; j++)
                                rB[4 * r + j] = B[(long long)gk * ldb + nb + j];
                        }
                    } else {
                        rB[4 * r + 0] = rB[4 * r + 1] = rB[4 * r + 2] = rB[4 * r + 3] = 0.f;
                    }
                }
            }
        } else {
#pragma unroll
            for (int it = 0; it < BN / 64; it++) {
                int lin = tid + it * 256;
                int nn = lin >> 2, q = lin & 3;
                int gn = n0 + nn;
                if (gn < N) {
                    if (fastB) {
                        const float4 v = *(const float4*)(B + (long long)gn * ldb + k0 + 4 * q);
                        rB[4 * it + 0] = v.x; rB[4 * it + 1] = v.y;
                        rB[4 * it + 2] = v.z; rB[4 * it + 3] = v.w;
                    } else {
#pragma unroll
                        for (int j = 0; j < 4; j++) {
                            int gk = k0 + 4 * q + j;
                            rB[4 * it + j] = (gk < Kd) ? B[(long long)gn * ldb + gk] : 0.f;
                        }
                    }
                } else {
                    rB[4 * it + 0] = rB[4 * it + 1] = rB[4 * it + 2] = rB[4 * it + 3] = 0.f;
                }
            }
        }
    };

    auto convert_stage = [&](int s) {
        uint32_t* Aph = smem + s * STAGE;
        uint32_t* Apl = Aph + APK_SZ;
        uint32_t* Bph = Apl + APK_SZ;
        uint32_t* Bpl = Bph + BPK_SZ;
        {
            uint32_t hi, lo;
            pack_bf16pair(rA[0], rA[1], hi, lo);
            Aph[mmA * APK_LD + 2 * qA] = hi;
            Apl[mmA * APK_LD + 2 * qA] = lo;
            pack_bf16pair(rA[2], rA[3], hi, lo);
            Aph[mmA * APK_LD + 2 * qA + 1] = hi;
            Apl[mmA * APK_LD + 2 * qA + 1] = lo;
        }
        if (!TRB) {
            if (bAct) {
#pragma unroll
                for (int j = 0; j < 4; j++) {
                    uint32_t hi, lo;
                    pack_bf16pair(rB[j], rB[4 + j], hi, lo);
                    Bph[pB * BPK_LD + 4 * nqB + j] = hi;
                    Bpl[pB * BPK_LD + 4 * nqB + j] = lo;
                }
            }
        } else {
#pragma unroll
            for (int it = 0; it < BN / 64; it++) {
                int lin = tid + it * 256;
                int nn = lin >> 2, q = lin & 3;
                uint32_t hi, lo;
                pack_bf16pair(rB[4 * it + 0], rB[4 * it + 1], hi, lo);
                Bph[nn * BPK_LD + 2 * q] = hi;
                Bpl[nn * BPK_LD + 2 * q] = lo;
                pack_bf16pair(rB[4 * it + 2], rB[4 * it + 3], hi, lo);
                Bph[nn * BPK_LD + 2 * q + 1] = hi;
                Bpl[nn * BPK_LD + 2 * q + 1] = lo;
            }
        }
    };

    auto compute = [&](int s) {
        uint32_t base = smemAddr + ((s * STAGE) << 2);
        uint32_t aph = base, apl = base + (APK_SZ << 2);
        uint32_t bphA = base + ((2 * APK_SZ) << 2);
        uint32_t bplA = base + ((2 * APK_SZ + BPK_SZ) << 2);
        const uint32_t* Bph = smem + s * STAGE + 2 * APK_SZ;
        const uint32_t* Bpl = Bph + BPK_SZ;
        uint32_t ah[2][4], al[2][4];
        // A fragments via ldmatrix.x4 (hi & lo)
        {
            int arow = wm * 32 + (lane & 15);
            uint32_t colp = (lane >> 4) << 2;   // 0 or 4 (u32 units)
#pragma unroll
            for (int i = 0; i < 2; i++) {
                uint32_t off = (uint32_t)(((arow + i * 16) * APK_LD + colp) << 2);
                ldsm4(ah[i][0], ah[i][1], ah[i][2], ah[i][3], aph + off);
                ldsm4(al[i][0], al[i][1], al[i][2], al[i][3], apl + off);
            }
        }
#pragma unroll
        for (int j = 0; j < BJ; j++) {
            uint32_t bh[2], bl[2];
            if (!TRB) {
                int bn = wn * (BN / 4) + j * 8 + lm;
                bh[0] = Bph[lk * BPK_LD + bn];
                bh[1] = Bph[(lk + 4) * BPK_LD + bn];
                bl[0] = Bpl[lk * BPK_LD + bn];
                bl[1] = Bpl[(lk + 4) * BPK_LD + bn];
            } else {
                int brow = wn * (BN / 4) + j * 8 + (lane & 7);
                uint32_t bcolp = (lane & 8) ? 4u : 0u;
                uint32_t boff = (uint32_t)((brow * APK_LD + bcolp) << 2);
                ldsm2(bh[0], bh[1], bphA + boff);
                ldsm2(bl[0], bl[1], bplA + boff);
            }
            // hh + lh + hl (ll dropped, ~2^-16)
            mma_bf16(acc[0][j], ah[0], bh);
            mma_bf16(acc[1][j], ah[1], bh);
            mma_bf16(acc[0][j], al[0], bh);
            mma_bf16(acc[1][j], al[1], bh);
            mma_bf16(acc[0][j], ah[0], bl);
            mma_bf16(acc[1][j], ah[1], bl);
        }
    };

    int nk = (Kd + 15) >> 4;
    // prologue
    load_regs(0);
    convert_stage(0);
    if (nk > 1) load_regs(16);
    __syncthreads();
    for (int i = 0; i < nk; i++) {
        compute(i & 1);
        if (i + 1 < nk) {
            convert_stage((i + 1) & 1);
            if (i + 2 < nk) load_regs((i + 2) * 16);
        }
        __syncthreads();
    }

    // ---- epilogue (float2 stores; all N/ldc even) ----
#pragma unroll
    for (int i = 0; i < 2; i++) {
#pragma unroll
        for (int r2 = 0; r2 < 2; r2++) {
            int gm = m0 + wm * 32 + i * 16 + lm + r2 * 8;
            if (gm >= M) continue;
            int rc = iC ? iC[gm] : gm;
            float* crow = C + (long long)rc * ldc;
            const float* rrow = res ? res + (long long)rc * ldc : nullptr;
#pragma unroll
            for (int j = 0; j < BJ; j++) {
                int gn = n0 + wn * (BN / 4) + j * 8 + lk * 2;
                if (gn >= N) continue;
                float v0 = acc[i][j][r2 * 2 + 0] * alpha;
                float v1 = acc[i][j][r2 * 2 + 1] * alpha;
                if (bias) { v0 += bias[gn]; v1 += bias[gn + 1]; }
                if (ACT == 1) {
                    float t0 = tanhf(0.7978845608028654f * (v0 + 0.044715f * v0 * v0 * v0));
                    float t1 = tanhf(0.7978845608028654f * (v1 + 0.044715f * v1 * v1 * v1));
                    v0 = 0.5f * v0 * (1.f + t0);
                    v1 = 0.5f * v1 * (1.f + t1);
                }
                if (rrow) {
                    const float2 rr = *(const float2*)(rrow + gn);
                    v0 += rr.x; v1 += rr.y;
                }
                float2 o; o.x = v0; o.y = v1;
                *(float2*)(crow + gn) = o;
            }
        }
    }
}

// ---------------- small kernels ----------------
__global__ void transpose_z(const float* __restrict__ z, float* __restrict__ zt) {
    __shared__ float tile[32][33];
    int b = blockIdx.z;
    int l0 = blockIdx.x * 32, c0 = blockIdx.y * 32;
    int x = threadIdx.x, y = threadIdx.y;
    for (int i = y; i < 32; i += 8)
        tile[i][x] = z[b * CIN * SS + (c0 + i) * SS + l0 + x];
    __syncthreads();
    for (int i = y; i < 32; i += 8)
        zt[b * SS * CIN + (long long)(l0 + i) * CIN + c0 + x] = tile[x][i];
}

__global__ void ln_kernel(const float* __restrict__ x, float* __restrict__ y,
                          const float* __restrict__ g, const float* __restrict__ b) {
    int row = blockIdx.x;
    const float* xr = x + (long long)row * DD;
    __shared__ float sh[32];
    __shared__ float sh2[32];
    float s = 0.f, s2 = 0.f;
    for (int d = threadIdx.x; d < DD; d += 256) { float v = xr[d]; s += v; s2 += v * v; }
    int lane = threadIdx.x & 31, wid = threadIdx.x >> 5;
    for (int o = 16; o; o >>= 1) { s += __shfl_xor_sync(~0u, s, o); s2 += __shfl_xor_sync(~0u, s2, o); }
    if (lane == 0) { sh[wid] = s; sh2[wid] = s2; }
    __syncthreads();
    if (wid == 0) {
        s  = (lane < 8) ? sh[lane]  : 0.f;
        s2 = (lane < 8) ? sh2[lane] : 0.f;
        for (int o = 16; o; o >>= 1) { s += __shfl_xor_sync(~0u, s, o); s2 += __shfl_xor_sync(~0u, s2, o); }
        if (lane == 0) { sh[0] = s; sh2[0] = s2; }
    }
    __syncthreads();
    float mean = sh[0] / DD;
    float var  = sh2[0] / DD - mean * mean;
    float inv = rsqrtf(var + 1e-5f);
    float* yr = y + (long long)row * DD;
    for (int d = threadIdx.x; d < DD; d += 256)
        yr[d] = (xr[d] - mean) * inv * g[d] + b[d];
}

__global__ void rope_kernel(float* __restrict__ q, float* __restrict__ k) {
    int idx = blockIdx.x * blockDim.x + threadIdx.x;
    if (idx >= TOK * (DD / 2)) return;
    int t = idx / (DD / 2), j = idx - t * (DD / 2);
    int s = t & (SS - 1);
    float freq = __expf(-9.210340371976184f * ((float)j / 384.f));
    float ang = (float)s * freq;
    float c, sn; sincosf(ang, &sn, &c);
    {
        float* p = q + (long long)t * DD + 2 * j;
        float a = p[0], b = p[1];
        p[0] = a * c - b * sn; p[1] = a * sn + b * c;
    }
    {
        float* p = k + (long long)t * DD + 2 * j;
        float a = p[0], b = p[1];
        p[0] = a * c - b * sn; p[1] = a * sn + b * c;
    }
}

__global__ void softmax_causal(float* __restrict__ sc) {
    int z = blockIdx.y, r = blockIdx.x;
    float* row = sc + ((long long)z << 20) + (long long)r * 1024;
    int n = r + 1;
    int nz = (r & ~63) + 64;   // AV (causal=2) reads only up to the row's 64-block end
    __shared__ float sh[32];
    int lane = threadIdx.x & 31, wid = threadIdx.x >> 5;
    float mx = -1e30f;
    for (int j = threadIdx.x; j < n; j += 256) mx = fmaxf(mx, row[j]);
    for (int o = 16; o; o >>= 1) mx = fmaxf(mx, __shfl_xor_sync(~0u, mx, o));
    if (lane == 0) sh[wid] = mx;
    __syncthreads();
    if (wid == 0) {
        mx = (lane < 8) ? sh[lane] : -1e30f;
        for (int o = 16; o; o >>= 1) mx = fmaxf(mx, __shfl_xor_sync(~0u, mx, o));
        if (lane == 0) sh[0] = mx;
    }
    __syncthreads();
    mx = sh[0];
    __syncthreads();
    float s = 0.f;
    for (int j = threadIdx.x; j < n; j += 256) s += __expf(row[j] - mx);
    for (int o = 16; o; o >>= 1) s += __shfl_xor_sync(~0u, s, o);
    if (lane == 0) sh[wid] = s;
    __syncthreads();
    if (wid == 0) {
        s = (lane < 8) ? sh[lane] : 0.f;
        for (int o = 16; o; o >>= 1) s += __shfl_xor_sync(~0u, s, o);
        if (lane == 0) sh[0] = s;
    }
    __syncthreads();
    float inv = 1.f / sh[0];
    for (int j = threadIdx.x; j < nz; j += 256)
        row[j] = (j < n) ? __expf(row[j] - mx) * inv : 0.f;
}

__global__ void zero_cnt(int* c) { if (threadIdx.x < EE) c[threadIdx.x] = 0; }

__global__ void route_kernel(const float* __restrict__ h, const float* __restrict__ gw,
                             int* cnt, int* etok, int* easn, float* wts) {
    int w = (blockIdx.x * blockDim.x + threadIdx.x) >> 5;
    int lane = threadIdx.x & 31;
    if (w >= TOK) return;
    const float* hr = h + (long long)w * DD;
    float lg[EE];
#pragma unroll
    for (int e = 0; e < EE; e++) {
        float s = 0.f;
        for (int d = lane; d < DD; d += 32) s += hr[d] * gw[d * EE + e];
        for (int o = 16; o; o >>= 1) s += __shfl_xor_sync(~0u, s, o);
        lg[e] = s;
    }
    if (lane == 0) {
        int e0 = 0;
        for (int e = 1; e < EE; e++) if (lg[e] > lg[e0]) e0 = e;
        int e1 = -1;
        for (int e = 0; e < EE; e++) { if (e == e0) continue; if (e1 < 0 || lg[e] > lg[e1]) e1 = e; }
        float x1 = __expf(lg[e1] - lg[e0]);
        float den = 1.f + x1;
        float w0 = 1.f / den, w1 = x1 / den;
        int s0 = atomicAdd(&cnt[e0], 1);
        etok[e0 * TOK + s0] = w; easn[e0 * TOK + s0] = 2 * w;
        int s1 = atomicAdd(&cnt[e1], 1);
        etok[e1 * TOK + s1] = w; easn[e1 * TOK + s1] = 2 * w + 1;
        wts[2 * w] = w0; wts[2 * w + 1] = w1;
    }
}

__global__ void combine_kernel(float* __restrict__ x, const float* __restrict__ ys,
                               const float* __restrict__ wts) {
    int idx = blockIdx.x * blockDim.x + threadIdx.x;
    if (idx >= TOK * DD) return;
    int t = idx / DD, d = idx - t * DD;
    x[idx] += wts[2 * t] * ys[(long long)(2 * t) * DD + d]
            + wts[2 * t + 1] * ys[(long long)(2 * t + 1) * DD + d];
}

__global__ void basis_kernel(float* __restrict__ Cb) {
    int idx = blockIdx.x * blockDim.x + threadIdx.x;
    if (idx >= 1026 * 1024) return;
    int j = idx >> 10, n = idx & 1023;
    const float invN = 1.f / 1024.f;
    float v;
    if (j == 0) v = invN;
    else if (j <= 511) { int m = (j * n) & 1023; v = 2.f * invN * cosf(m * TWO_PI_N); }
    else if (j == 512) v = invN * ((n & 1) ? -1.f : 1.f);
    else if (j == 513 || j == 1025) v = 0.f;
    else { int kk = j - 513; int m = (kk * n) & 1023; v = -2.f * invN * sinf(m * TWO_PI_N); }
    Cb[idx] = v;
}

__global__ void bf_kernel(const float* __restrict__ ob, const float* __restrict__ Cb,
                          float* __restrict__ bf) {
    int n = blockIdx.x * 128 + threadIdx.x;
    float s = 0.f;
    for (int j = 0; j < 1026; j++) s += ob[j] * Cb[j * 1024 + n];
    bf[n] = s;
}

__global__ void istft_kernel(const float* __restrict__ frames, float* __restrict__ out) {
    int idx = blockIdx.x * blockDim.x + threadIdx.x;
    if (idx >= BB * OUTL) return;
    int b = idx / OUTL, i = idx - b * OUTL;
    int ip = i + PADL;
    int tmin = (ip >= 1024) ? ((ip - 768) >> 8) : 0;
    int tmax = min(1023, ip >> 8);
    float acc = 0.f, env = 0.f;
    for (int t = tmin; t <= tmax; t++) {
        int n = ip - (t << 8);
        float w = 0.5f * (1.f - cosf(n * TWO_PI_N));
        acc += frames[((long long)(b * 1024 + t) << 10) + n] * w;
        env += w * w;
    }
    out[idx] = acc / env;
}

// ---------------- host side ----------------
static void* symaddr(const void* sym) {
    void* p = nullptr;
    cudaGetSymbolAddress(&p, sym);
    return p;
}

struct GemmArgs {
    const float* A; int lda; long long sAz, sAz2;
    const float* B; int ldb; long long sBz, sBz2;
    float* C; int ldc; long long sCz, sCz2;
    int zdiv;
    const float* bias; long long sbz; const float* res;
    int M, N, Kd; float alpha; int Z;
    const int* idxA; const int* idxC; const int* cnt;
    int causal; int gridM;
};

#define BPK_SZH(TRB, BN) ((TRB) ? ((BN) * APK_LD) : (8 * ((BN) + 8)))
#define SMEM_BYTES(TRB, BN) (4 * 2 * (2 * APK_SZ + 2 * BPK_SZH(TRB, BN)))

static void gemm(int act, bool trb, int BN, const GemmArgs& a)
{
    dim3 grid((a.N + BN - 1) / BN, a.gridM ? a.gridM : (a.M + 63) / 64, a.Z);
    if (act == 1) {
        size_t shm = SMEM_BYTES(false, 128);
        cudaFuncSetAttribute(gemm_kernel<1, false, 128>, cudaFuncAttributeMaxDynamicSharedMemorySize, (int)shm);
        gemm_kernel<1, false, 128><<<grid, 256, shm>>>(a.A, a.lda, a.sAz, a.sAz2, a.B, a.ldb, a.sBz, a.sBz2,
            a.C, a.ldc, a.sCz, a.sCz2, a.zdiv, a.bias, a.sbz, a.res,
            a.M, a.N, a.Kd, a.alpha, a.idxA, a.idxC, a.cnt, a.causal);
    } else if (trb) {
        size_t shm = SMEM_BYTES(true, 128);
        cudaFuncSetAttribute(gemm_kernel<0, true, 128>, cudaFuncAttributeMaxDynamicSharedMemorySize, (int)shm);
        gemm_kernel<0, true, 128><<<grid, 256, shm>>>(a.A, a.lda, a.sAz, a.sAz2, a.B, a.ldb, a.sBz, a.sBz2,
            a.C, a.ldc, a.sCz, a.sCz2, a.zdiv, a.bias, a.sbz, a.res,
            a.M, a.N, a.Kd, a.alpha, a.idxA, a.idxC, a.cnt, a.causal);
    } else if (BN == 128) {
        size_t shm = SMEM_BYTES(false, 128);
        cudaFuncSetAttribute(gemm_kernel<0, false, 128>, cudaFuncAttributeMaxDynamicSharedMemorySize, (int)shm);
        gemm_kernel<0, false, 128><<<grid, 256, shm>>>(a.A, a.lda, a.sAz, a.sAz2, a.B, a.ldb, a.sBz, a.sBz2,
            a.C, a.ldc, a.sCz, a.sCz2, a.zdiv, a.bias, a.sbz, a.res,
            a.M, a.N, a.Kd, a.alpha, a.idxA, a.idxC, a.cnt, a.causal);
    } else {
        size_t shm = SMEM_BYTES(false, 64);
        cudaFuncSetAttribute(gemm_kernel<0, false, 64>, cudaFuncAttributeMaxDynamicSharedMemorySize, (int)shm);
        gemm_kernel<0, false, 64><<<grid, 256, shm>>>(a.A, a.lda, a.sAz, a.sAz2, a.B, a.ldb, a.sBz, a.sBz2,
            a.C, a.ldc, a.sCz, a.sCz2, a.zdiv, a.bias, a.sbz, a.res,
            a.M, a.N, a.Kd, a.alpha, a.idxA, a.idxC, a.cnt, a.causal);
    }
}

extern "C" void kernel_launch(void* const* d_in, const int* in_sizes, int n_in,
                              void* d_out, int out_size)
{
    const float* z_in  = (const float*)d_in[0];
    const float* in_w  = (const float*)d_in[1];
    const float* in_b  = (const float*)d_in[2];
    const float* ln1g  = (const float*)d_in[3];
    const float* ln1b  = (const float*)d_in[4];
    const float* wq    = (const float*)d_in[5];
    const float* bq    = (const float*)d_in[6];
    const float* wk    = (const float*)d_in[7];
    const float* bk    = (const float*)d_in[8];
    const float* wv    = (const float*)d_in[9];
    const float* bv    = (const float*)d_in[10];
    const float* wo    = (const float*)d_in[11];
    const float* bo    = (const float*)d_in[12];
    const float* ln2g  = (const float*)d_in[13];
    const float* ln2b  = (const float*)d_in[14];
    const float* gatew = (const float*)d_in[15];
    const float* ew1   = (const float*)d_in[16];
    const float* eb1   = (const float*)d_in[17];
    const float* ew2   = (const float*)d_in[18];
    const float* eb2   = (const float*)d_in[19];
    const float* outw  = (const float*)d_in[20];
    const float* outb  = (const float*)d_in[21];
    float* out = (float*)d_out;

    float* ZT = (float*)symaddr(g_zt);
    float* X  = (float*)symaddr(g_x);
    float* H  = (float*)symaddr(g_h);
    float* QKV = (float*)symaddr(g_qkv);
    float* WQKV = (float*)symaddr(g_wqkv);
    float* BQKV = (float*)symaddr(g_bqkv);
    float* Q  = QKV;
    float* Kb = QKV + (long long)TOK * DD;
    float* V  = QKV + 2LL * TOK * DD;
    float* AO = (float*)symaddr(g_ao);
    float* SC = (float*)symaddr(g_scores);
    float* HID = (float*)symaddr(g_hidden);
    float* YS = (float*)symaddr(g_yslot);
    float* CB = (float*)symaddr(g_Cb);
    float* MT = (float*)symaddr(g_Mt);
    float* BF = (float*)symaddr(g_bf);
    float* FR = (float*)symaddr(g_frames);
    int* CNT = (int*)symaddr(g_cnt);
    int* ETK = (int*)symaddr(g_etok);
    int* EAS = (int*)symaddr(g_easn);
    float* WTS = (float*)symaddr(g_wts);

    // in_projection: zt = z^T, x = zt @ in_w + in_b
    transpose_z<<<dim3(SS / 32, CIN / 32, BB), dim3(32, 8)>>>(z_in, ZT);
    {
        GemmArgs a = {ZT, CIN, 0, 0, in_w, DD, 0, 0, X, DD, 0, 0, 1,
                      in_b, 0, nullptr, TOK, DD, CIN, 1.f, 1, nullptr, nullptr, nullptr, 0, 0};
        gemm(0, false, 128, a);
    }

    for (int L = 0; L < 2; L++) {
        const size_t WSZ = (size_t)DD * DD * sizeof(float);
        cudaMemcpyAsync(WQKV,               wq + (long long)L * DD * DD, WSZ, cudaMemcpyDeviceToDevice);
        cudaMemcpyAsync(WQKV + DD * DD,     wk + (long long)L * DD * DD, WSZ, cudaMemcpyDeviceToDevice);
        cudaMemcpyAsync(WQKV + 2 * DD * DD, wv + (long long)L * DD * DD, WSZ, cudaMemcpyDeviceToDevice);
        cudaMemcpyAsync(BQKV,          bq + L * DD, DD * sizeof(float), cudaMemcpyDeviceToDevice);
        cudaMemcpyAsync(BQKV + DD,     bk + L * DD, DD * sizeof(float), cudaMemcpyDeviceToDevice);
        cudaMemcpyAsync(BQKV + 2 * DD, bv + L * DD, DD * sizeof(float), cudaMemcpyDeviceToDevice);

        ln_kernel<<<TOK, 256>>>(X, H, ln1g + L * DD, ln1b + L * DD);
        {
            GemmArgs a = {H, DD, 0, 0, WQKV, DD, (long long)DD * DD, 0,
                          QKV, DD, (long long)TOK * DD, 0, 3,
                          BQKV, DD, nullptr, TOK, DD, DD, 1.f, 3, 0, 0, 0, 0, 0};
            gemm(0, false, 128, a);
        }
        if (L == 0)
            rope_kernel<<<(TOK * (DD / 2) + 255) / 256, 256>>>(Q, Kb);

        {
            GemmArgs a = {Q, DD, HD, (long long)SS * DD,
                          Kb, DD, HD, (long long)SS * DD,
                          SC, SS, (long long)SS * SS, (long long)HH * SS * SS, HH,
                          nullptr, 0, nullptr, SS, SS, HD, 0.125f, BB * HH, 0, 0, 0, 1, 0};
            gemm(0, true, 128, a);
        }
        softmax_causal<<<dim3(SS, BB * HH), 256>>>(SC);
        {
            GemmArgs a = {SC, SS, (long long)SS * SS, (long long)HH * SS * SS,
                          V, DD, HD, (long long)SS * DD,
                          AO, DD, HD, (long long)SS * DD, HH,
                          nullptr, 0, nullptr, SS, HD, SS, 1.f, BB * HH, 0, 0, 0, 2, 0};
            gemm(0, false, 64, a);
        }
        {
            GemmArgs a = {AO, DD, 0, 0, wo + (long long)L * DD * DD, DD, 0, 0, X, DD, 0, 0, 1,
                          bo + L * DD, 0, X, TOK, DD, DD, 1.f, 1, 0, 0, 0, 0, 0};
            gemm(0, false, 128, a);
        }

        // MoE
        ln_kernel<<<TOK, 256>>>(X, H, ln2g + L * DD, ln2b + L * DD);
        zero_cnt<<<1, 32>>>(CNT);
        route_kernel<<<TOK / 8, 256>>>(H, gatew + (long long)L * DD * EE, CNT, ETK, EAS, WTS);
        {
            GemmArgs a = {H, DD, 0, 0,
                          ew1 + (long long)L * EE * DD * FF, FF, (long long)DD * FF, 0,
                          HID, FF, 0, 0, EE,
                          eb1 + (long long)L * EE * FF, FF, nullptr,
                          TOK, FF, DD, 1.f, EE, ETK, EAS, CNT, 0, TOK / 64};
            gemm(1, false, 128, a);
        }
        {
            GemmArgs a = {HID, FF, 0, 0,
                          ew2 + (long long)L * EE * FF * DD, DD, (long long)FF * DD, 0,
                          YS, DD, 0, 0, EE,
                          eb2 + (long long)L * EE * DD, DD, nullptr,
                          TOK, DD, FF, 1.f, EE, EAS, EAS, CNT, 0, TOK / 64};
            gemm(0, false, 128, a);
        }
        combine_kernel<<<(TOK * DD + 255) / 256, 256>>>(X, YS, WTS);
    }

    // out projection fused with irfft basis: frames = x @ (out_w @ Cb) + out_b @ Cb
    basis_kernel<<<(1026 * 1024 + 255) / 256, 256>>>(CB);
    {
        GemmArgs a = {outw, 2 * FB, 0, 0, CB, 1024, 0, 0, MT, 1024, 0, 0, 1,
                      nullptr, 0, nullptr, DD, 1024, 2 * FB, 1.f, 1, 0, 0, 0, 0, 0};
        gemm(0, false, 128, a);
    }
    bf_kernel<<<8, 128>>>(outb, CB, BF);
    {
        GemmArgs a = {X, DD, 0, 0, MT, 1024, 0, 0, FR, 1024, 0, 0, 1,
                      BF, 0, nullptr, TOK, 1024, DD, 1.f, 1, 0, 0, 0, 0, 0};
        gemm(0, false, 128, a);
    }

    // windowed overlap-add + env normalize + trim
    istft_kernel<<<(BB * OUTL + 255) / 256, 256>>>(FR, out);
}

// round 15
// speedup vs baseline: 1.5521x; 1.0116x over previous
#include <cuda_runtime.h>
#include <math.h>
#include <stdint.h>

// ---------------- constants ----------------
#define BB 2
#define SS 1024
#define DD 768
#define HH 12
#define HD 64
#define EE 8
#define FF 2048
#define CIN 512
#define TOK (BB*SS)          // 2048
#define FB 513
#define PADL 384
#define OUTL 262144
#define TWO_PI_N 0.006135923151542565f   // 2*pi/1024

// ---------------- scratch (device globals; allocation-free) ----------------
__device__ float g_zt[TOK*CIN];
__device__ float g_x [TOK*DD];
__device__ float g_h [TOK*DD];
__device__ float g_qkv[3*TOK*DD];
__device__ float g_bqkv[3*DD];
__device__ float g_ao[TOK*DD];
__device__ float g_scores[24u*1024u*1024u];
__device__ float g_hidden[4096*FF];
__device__ float g_yslot [4096*DD];
__device__ float g_Cb[1026*1024];
__device__ float g_Mt[DD*1024];
__device__ float g_bf[1024];
__device__ float g_frames[TOK*1024];
__device__ int   g_cnt[EE];
__device__ int   g_etok[EE*TOK];
__device__ int   g_easn[EE*TOK];
__device__ float g_wts[2*TOK];

// packed small weights: hi at [0,SZ), lo at [SZ,2SZ)
#define SZ_INW  (256*768)
#define SZ_QKV1 (384*768)
#define SZ_WO   (384*768)
#define SZ_CB   (513*1024)
#define SZ_MT   (384*1024)
__device__ uint32_t g_pk_inw[2*SZ_INW];
__device__ uint32_t g_pk_qkv[2*3*SZ_QKV1];
__device__ uint32_t g_pk_wo [2*SZ_WO];
__device__ uint32_t g_pk_cb [2*SZ_CB];
__device__ uint32_t g_pk_mt [2*SZ_MT];

// ---------------- bf16x3 helpers ----------------
__device__ __forceinline__ void pack_bf16pair(float f0, float f1, uint32_t& hi, uint32_t& lo) {
    uint32_t u0 = __float_as_uint(f0);
    uint32_t u1 = __float_as_uint(f1);
    uint32_t h;
    asm("prmt.b32 %0, %1, %2, 0x7632;" : "=r"(h) : "r"(u0), "r"(u1));
    hi = h;
    float l0 = f0 - __uint_as_float(u0 & 0xFFFF0000u);
    float l1 = f1 - __uint_as_float(u1 & 0xFFFF0000u);
    asm("cvt.rn.bf16x2.f32 %0, %1, %2;" : "=r"(lo) : "f"(l1), "f"(l0));
}
__device__ __forceinline__ void mma_bf16(float* c, const uint32_t* a, const uint32_t* b) {
    asm volatile(
        "mma.sync.aligned.m16n8k16.row.col.f32.bf16.bf16.f32 "
        "{%0,%1,%2,%3}, {%4,%5,%6,%7}, {%8,%9}, {%0,%1,%2,%3};"
        : "+f"(c[0]), "+f"(c[1]), "+f"(c[2]), "+f"(c[3])
        : "r"(a[0]), "r"(a[1]), "r"(a[2]), "r"(a[3]), "r"(b[0]), "r"(b[1]));
}
__device__ __forceinline__ void ldsm4(uint32_t& r0, uint32_t& r1, uint32_t& r2, uint32_t& r3, uint32_t addr) {
    asm volatile("ldmatrix.sync.aligned.m8n8.x4.shared.b16 {%0,%1,%2,%3}, [%4];"
        : "=r"(r0), "=r"(r1), "=r"(r2), "=r"(r3) : "r"(addr));
}
__device__ __forceinline__ void ldsm2(uint32_t& r0, uint32_t& r1, uint32_t addr) {
    asm volatile("ldmatrix.sync.aligned.m8n8.x2.shared.b16 {%0,%1}, [%2];"
        : "=r"(r0), "=r"(r1) : "r"(addr));
}
__device__ __forceinline__ void cpa16(uint32_t dst, const void* src, bool pred) {
    asm volatile("cp.async.ca.shared.global [%0], [%1], 16, %2;"
                 :: "r"(dst), "l"(src), "r"(pred ? 16 : 0));
}
__device__ __forceinline__ void cpa_commit() { asm volatile("cp.async.commit_group;"); }
__device__ __forceinline__ void cpa_wait2() { asm volatile("cp.async.wait_group 2;"); }

// ---------------- weight pre-pack (float4 vectorized) ----------------
__global__ void pack_w(const float* __restrict__ W, long long sWz, int K, int N,
                       uint32_t* __restrict__ Ph, uint32_t* __restrict__ Pl, long long sPz)
{
    int z = blockIdx.z;
    int K2 = (K + 1) >> 1;
    int n4c = N >> 2;
    int idx = blockIdx.x * 256 + threadIdx.x;
    if (idx >= K2 * n4c) return;
    int p = idx / n4c, n4 = (idx - p * n4c) << 2;
    const float* Wz = W + (long long)z * sWz;
    float4 a = *(const float4*)(Wz + (long long)(2 * p) * N + n4);
    float4 b;
    if (2 * p + 1 < K) b = *(const float4*)(Wz + (long long)(2 * p + 1) * N + n4);
    else { b.x = b.y = b.z = b.w = 0.f; }
    uint32_t h0, l0, h1, l1, h2, l2, h3, l3;
    pack_bf16pair(a.x, b.x, h0, l0);
    pack_bf16pair(a.y, b.y, h1, l1);
    pack_bf16pair(a.z, b.z, h2, l2);
    pack_bf16pair(a.w, b.w, h3, l3);
    long long o = (long long)z * sPz + (long long)p * N + n4;
    *(uint4*)(Ph + o) = make_uint4(h0, h1, h2, h3);
    *(uint4*)(Pl + o) = make_uint4(l0, l1, l2, l3);
}

// ---------------- register/async staged tensor-core GEMM (3xBF16) ----------------
// Tile: 64(M) x BN(N), K-step 16. 8 warps as 2(M) x 4(N); warp = 32 x BN/4.
#define APK_LD 12   // packed A row stride (uint32; 8 pairs + pad)
#define APK_SZ (64 * APK_LD)

template<int ACT, bool TRB, int BN, bool PKB>
__global__ __launch_bounds__(256, 2)
void gemm_kernel(const float* __restrict__ A, int lda, long long sAz, long long sAz2,
                 const float* __restrict__ B, int ldb, long long sBz, long long sBz2,
                 float* __restrict__ C, int ldc, long long sCz, long long sCz2,
                 int zdiv,
                 const float* __restrict__ bias, long long sbz,
                 const float* __restrict__ res,
                 int M, int N, int Kd, float alpha,
                 const int* __restrict__ idxA, const int* __restrict__ idxC,
                 const int* __restrict__ cnt, int causal,
                 const uint32_t* __restrict__ PBh, const uint32_t* __restrict__ PBl,
                 long long sPBz, int ldPB)
{
    constexpr int BPK_LD = TRB ? APK_LD : (BN + 8);
    constexpr int BPK_SZ = TRB ? (BN * APK_LD) : (8 * (BN + 8));
    constexpr int STAGE  = 2 * APK_SZ + 2 * BPK_SZ;   // non-PKB stage (u32)
    constexpr int BJ = BN / 32;
    constexpr int PK_AST = 2 * APK_SZ;     // 1536 u32
    constexpr int PK_BST = 2 * 8 * 136;    // 2176 u32 (hi 1088 + lo 1088)

    int z = blockIdx.z;
    int z1 = z / zdiv, z0 = z - z1 * zdiv;
    if (cnt) M = cnt[z];
    int m0 = blockIdx.y * 64, n0 = blockIdx.x * BN;
    if (m0 >= M) return;
    if (causal == 1 && n0 > m0 + 63) return;
    if (causal == 2) Kd = min(Kd, m0 + 64);
    A += (long long)z0 * sAz + (long long)z1 * sAz2;
    if (!PKB) B += (long long)z0 * sBz + (long long)z1 * sBz2;
    else { PBh += (long long)z0 * sPBz; PBl += (long long)z0 * sPBz; }
    C += (long long)z0 * sCz + (long long)z1 * sCz2;
    if (bias) bias += (long long)z * sbz;
    if (res)  res  += (long long)z0 * sCz + (long long)z1 * sCz2;
    const int* iA = idxA ? idxA + z * TOK : nullptr;
    const int* iC = idxC ? idxC + z * TOK : nullptr;

    extern __shared__ uint32_t smem[];
    uint32_t smemAddr = (uint32_t)__cvta_generic_to_shared(smem);

    int tid = threadIdx.x;
    int lane = tid & 31, wid = tid >> 5;
    int wm = wid >> 2, wn = wid & 3;
    int lm = lane >> 2, lk = lane & 3;

    float acc[2][BJ][4];
#pragma unroll
    for (int i = 0; i < 2; i++)
#pragma unroll
        for (int j = 0; j < BJ; j++)
#pragma unroll
            for (int r = 0; r < 4; r++) acc[i][j][r] = 0.f;

    const bool fastA = ((lda & 3) == 0) && ((Kd & 15) == 0);
    const bool fastB = ((ldb & 3) == 0) && (TRB ? ((Kd & 15) == 0) : true);

    float rA[4];
    float rB[8];
    int mmA = tid >> 2, qA = tid & 3;
    int raA = -1;
    {
        int gm = m0 + mmA;
        if (gm < M) raA = iA ? iA[gm] : gm;
    }
    int pB = 0, nqB = 0;
    bool bAct = true;
    if (!TRB && !PKB) {
        if (BN == 128) { pB = tid >> 5; nqB = tid & 31; }
        else { pB = tid >> 4; nqB = tid & 15; bAct = (tid < 128); }
    }

    auto load_regsA = [&](int k0) {
        if (raA >= 0) {
            if (fastA) {
                const float4 v = *(const float4*)(A + (long long)raA * lda + k0 + 4 * qA);
                rA[0] = v.x; rA[1] = v.y; rA[2] = v.z; rA[3] = v.w;
            } else {
#pragma unroll
                for (int j = 0; j < 4; j++) {
                    int gk = k0 + 4 * qA + j;
                    rA[j] = (gk < Kd) ? A[(long long)raA * lda + gk] : 0.f;
                }
            }
        } else {
            rA[0] = rA[1] = rA[2] = rA[3] = 0.f;
        }
    };

    auto load_regsB = [&](int k0) {
        if (!TRB) {
            if (bAct) {
                int gk0 = k0 + 2 * pB;
                int nb = n0 + 4 * nqB;
#pragma unroll
                for (int r = 0; r < 2; r++) {
                    int gk = gk0 + r;
                    if (gk < Kd) {
                        if (fastB) {
                            const float4 v = *(const float4*)(B + (long long)gk * ldb + nb);
                            rB[4 * r + 0] = v.x; rB[4 * r + 1] = v.y;
                            rB[4 * r + 2] = v.z; rB[4 * r + 3] = v.w;
                        } else {
#pragma unroll
                            for (int j = 0; j < 4; j++)
                                rB[4 * r + j] = B[(long long)gk * ldb + nb + j];
                        }
                    } else {
                        rB[4 * r + 0] = rB[4 * r + 1] = rB[4 * r + 2] = rB[4 * r + 3] = 0.f;
                    }
                }
            }
        } else {
#pragma unroll
            for (int it = 0; it < BN / 64; it++) {
                int lin = tid + it * 256;
                int nn = lin >> 2, q = lin & 3;
                int gn = n0 + nn;
                if (gn < N) {
                    if (fastB) {
                        const float4 v = *(const float4*)(B + (long long)gn * ldb + k0 + 4 * q);
                        rB[4 * it + 0] = v.x; rB[4 * it + 1] = v.y;
                        rB[4 * it + 2] = v.z; rB[4 * it + 3] = v.w;
                    } else {
#pragma unroll
                        for (int j = 0; j < 4; j++) {
                            int gk = k0 + 4 * q + j;
                            rB[4 * it + j] = (gk < Kd) ? B[(long long)gn * ldb + gk] : 0.f;
                        }
                    }
                } else {
                    rB[4 * it + 0] = rB[4 * it + 1] = rB[4 * it + 2] = rB[4 * it + 3] = 0.f;
                }
            }
        }
    };

    // ============================ PKB path ============================
    if constexpr (PKB) {
        uint32_t* Asm = smem;                                 // 2 * PK_AST
        uint32_t baseB = smemAddr + ((2 * PK_AST) << 2);      // 4 * PK_BST

        auto convA = [&](int s) {
            uint32_t* Aph = Asm + s * PK_AST;
            uint32_t* Apl = Aph + APK_SZ;
            uint32_t hi, lo;
            pack_bf16pair(rA[0], rA[1], hi, lo);
            Aph[mmA * APK_LD + 2 * qA] = hi;
            Apl[mmA * APK_LD + 2 * qA] = lo;
            pack_bf16pair(rA[2], rA[3], hi, lo);
            Aph[mmA * APK_LD + 2 * qA + 1] = hi;
            Apl[mmA * APK_LD + 2 * qA + 1] = lo;
        };
        auto cpaB = [&](int ks, int st) {
            int p = tid >> 5, n4 = (tid & 31) * 4;
            bool pred = (ks * 16 + 2 * p) < Kd;
            int krow = pred ? (ks * 8 + p) : 0;
            long long row = (long long)krow * ldPB + n0 + n4;
            uint32_t d = baseB + ((st * PK_BST + p * 136 + n4) << 2);
            cpa16(d, PBh + row, pred);
            cpa16(d + (1088 << 2), PBl + row, pred);
        };
        auto computeP = [&](int i) {
            uint32_t aph = smemAddr + (((i & 1) * PK_AST) << 2);
            uint32_t apl = aph + (APK_SZ << 2);
            const uint32_t* Bph = smem + 2 * PK_AST + (i & 3) * PK_BST;
            const uint32_t* Bpl = Bph + 1088;
            uint32_t ah[2][4], al[2][4];
            {
                int arow = wm * 32 + (lane & 15);
                uint32_t colp = (lane >> 4) << 2;
#pragma unroll
                for (int i2 = 0; i2 < 2; i2++) {
                    uint32_t off = (uint32_t)(((arow + i2 * 16) * APK_LD + colp) << 2);
                    ldsm4(ah[i2][0], ah[i2][1], ah[i2][2], ah[i2][3], aph + off);
                    ldsm4(al[i2][0], al[i2][1], al[i2][2], al[i2][3], apl + off);
                }
            }
#pragma unroll
            for (int j = 0; j < BJ; j++) {
                int bn = wn * (BN / 4) + j * 8 + lm;
                uint32_t bh[2], bl[2];
                bh[0] = Bph[lk * 136 + bn];
                bh[1] = Bph[(lk + 4) * 136 + bn];
                bl[0] = Bpl[lk * 136 + bn];
                bl[1] = Bpl[(lk + 4) * 136 + bn];
                mma_bf16(acc[0][j], ah[0], bh);
                mma_bf16(acc[1][j], ah[1], bh);
                mma_bf16(acc[0][j], al[0], bh);
                mma_bf16(acc[1][j], al[1], bh);
                mma_bf16(acc[0][j], ah[0], bl);
                mma_bf16(acc[1][j], ah[1], bl);
            }
        };

        int nk = (Kd + 15) >> 4;
        cpaB(0, 0); cpa_commit();
        if (nk > 1) cpaB(1, 1);
        cpa_commit();
        if (nk > 2) cpaB(2, 2);
        cpa_commit();
        load_regsA(0);
        convA(0);
        if (nk > 1) load_regsA(16);
        cpa_wait2();
        __syncthreads();
        for (int i = 0; i < nk; i++) {
            computeP(i);
            if (i + 1 < nk) convA((i + 1) & 1);
            if (i + 2 < nk) load_regsA((i + 2) * 16);
            if (i + 3 < nk) cpaB(i + 3, (i + 3) & 3);
            cpa_commit();
            cpa_wait2();
            __syncthreads();
        }
    } else {
    // ============================ reg-staged path ============================
        auto convert_stage = [&](int s) {
            uint32_t* Aph = smem + s * STAGE;
            uint32_t* Apl = Aph + APK_SZ;
            uint32_t* Bph = Apl + APK_SZ;
            uint32_t* Bpl = Bph + BPK_SZ;
            {
                uint32_t hi, lo;
                pack_bf16pair(rA[0], rA[1], hi, lo);
                Aph[mmA * APK_LD + 2 * qA] = hi;
                Apl[mmA * APK_LD + 2 * qA] = lo;
                pack_bf16pair(rA[2], rA[3], hi, lo);
                Aph[mmA * APK_LD + 2 * qA + 1] = hi;
                Apl[mmA * APK_LD + 2 * qA + 1] = lo;
            }
            if (!TRB) {
                if (bAct) {
#pragma unroll
                    for (int j = 0; j < 4; j++) {
                        uint32_t hi, lo;
                        pack_bf16pair(rB[j], rB[4 + j], hi, lo);
                        Bph[pB * BPK_LD + 4 * nqB + j] = hi;
                        Bpl[pB * BPK_LD + 4 * nqB + j] = lo;
                    }
                }
            } else {
#pragma unroll
                for (int it = 0; it < BN / 64; it++) {
                    int lin = tid + it * 256;
                    int nn = lin >> 2, q = lin & 3;
                    uint32_t hi, lo;
                    pack_bf16pair(rB[4 * it + 0], rB[4 * it + 1], hi, lo);
                    Bph[nn * BPK_LD + 2 * q] = hi;
                    Bpl[nn * BPK_LD + 2 * q] = lo;
                    pack_bf16pair(rB[4 * it + 2], rB[4 * it + 3], hi, lo);
                    Bph[nn * BPK_LD + 2 * q + 1] = hi;
                    Bpl[nn * BPK_LD + 2 * q + 1] = lo;
                }
            }
        };
        auto compute = [&](int s) {
            uint32_t base = smemAddr + ((s * STAGE) << 2);
            uint32_t aph = base, apl = base + (APK_SZ << 2);
            uint32_t bphA = base + ((2 * APK_SZ) << 2);
            uint32_t bplA = base + ((2 * APK_SZ + BPK_SZ) << 2);
            const uint32_t* Bph = smem + s * STAGE + 2 * APK_SZ;
            const uint32_t* Bpl = Bph + BPK_SZ;
            uint32_t ah[2][4], al[2][4];
            {
                int arow = wm * 32 + (lane & 15);
                uint32_t colp = (lane >> 4) << 2;
#pragma unroll
                for (int i = 0; i < 2; i++) {
                    uint32_t off = (uint32_t)(((arow + i * 16) * APK_LD + colp) << 2);
                    ldsm4(ah[i][0], ah[i][1], ah[i][2], ah[i][3], aph + off);
                    ldsm4(al[i][0], al[i][1], al[i][2], al[i][3], apl + off);
                }
            }
#pragma unroll
            for (int j = 0; j < BJ; j++) {
                uint32_t bh[2], bl[2];
                if (!TRB) {
                    int bn = wn * (BN / 4) + j * 8 + lm;
                    bh[0] = Bph[lk * BPK_LD + bn];
                    bh[1] = Bph[(lk + 4) * BPK_LD + bn];
                    bl[0] = Bpl[lk * BPK_LD + bn];
                    bl[1] = Bpl[(lk + 4) * BPK_LD + bn];
                } else {
                    int brow = wn * (BN / 4) + j * 8 + (lane & 7);
                    uint32_t bcolp = (lane & 8) ? 4u : 0u;
                    uint32_t boff = (uint32_t)((brow * APK_LD + bcolp) << 2);
                    ldsm2(bh[0], bh[1], bphA + boff);
                    ldsm2(bl[0], bl[1], bplA + boff);
                }
                mma_bf16(acc[0][j], ah[0], bh);
                mma_bf16(acc[1][j], ah[1], bh);
                mma_bf16(acc[0][j], al[0], bh);
                mma_bf16(acc[1][j], al[1], bh);
                mma_bf16(acc[0][j], ah[0], bl);
                mma_bf16(acc[1][j], ah[1], bl);
            }
        };

        int nk = (Kd + 15) >> 4;
        load_regsA(0); load_regsB(0);
        convert_stage(0);
        if (nk > 1) { load_regsA(16); load_regsB(16); }
        __syncthreads();
        for (int i = 0; i < nk; i++) {
            compute(i & 1);
            if (i + 1 < nk) {
                convert_stage((i + 1) & 1);
                if (i + 2 < nk) { load_regsA((i + 2) * 16); load_regsB((i + 2) * 16); }
            }
            __syncthreads();
        }
    }

    // ---- epilogue (float2 stores; all N/ldc even) ----
#pragma unroll
    for (int i = 0; i < 2; i++) {
#pragma unroll
        for (int r2 = 0; r2 < 2; r2++) {
            int gm = m0 + wm * 32 + i * 16 + lm + r2 * 8;
            if (gm >= M) continue;
            int rc = iC ? iC[gm] : gm;
            float* crow = C + (long long)rc * ldc;
            const float* rrow = res ? res + (long long)rc * ldc : nullptr;
#pragma unroll
            for (int j = 0; j < BJ; j++) {
                int gn = n0 + wn * (BN / 4) + j * 8 + lk * 2;
                if (gn >= N) continue;
                float v0 = acc[i][j][r2 * 2 + 0] * alpha;
                float v1 = acc[i][j][r2 * 2 + 1] * alpha;
                if (bias) { v0 += bias[gn]; v1 += bias[gn + 1]; }
                if (ACT == 1) {
                    float t0 = tanhf(0.7978845608028654f * (v0 + 0.044715f * v0 * v0 * v0));
                    float t1 = tanhf(0.7978845608028654f * (v1 + 0.044715f * v1 * v1 * v1));
                    v0 = 0.5f * v0 * (1.f + t0);
                    v1 = 0.5f * v1 * (1.f + t1);
                }
                if (rrow) {
                    const float2 rr = *(const float2*)(rrow + gn);
                    v0 += rr.x; v1 += rr.y;
                }
                float2 o; o.x = v0; o.y = v1;
                *(float2*)(crow + gn) = o;
            }
        }
    }
}

// ---------------- small kernels ----------------
__global__ void transpose_z(const float* __restrict__ z, float* __restrict__ zt) {
    __shared__ float tile[32][33];
    int b = blockIdx.z;
    int l0 = blockIdx.x * 32, c0 = blockIdx.y * 32;
    int x = threadIdx.x, y = threadIdx.y;
    for (int i = y; i < 32; i += 8)
        tile[i][x] = z[b * CIN * SS + (c0 + i) * SS + l0 + x];
    __syncthreads();
    for (int i = y; i < 32; i += 8)
        zt[b * SS * CIN + (long long)(l0 + i) * CIN + c0 + x] = tile[x][i];
}

__global__ void ln_kernel(const float* __restrict__ x, float* __restrict__ y,
                          const float* __restrict__ g, const float* __restrict__ b) {
    int row = blockIdx.x;
    const float* xr = x + (long long)row * DD;
    __shared__ float sh[32];
    __shared__ float sh2[32];
    float s = 0.f, s2 = 0.f;
    for (int d = threadIdx.x; d < DD; d += 256) { float v = xr[d]; s += v; s2 += v * v; }
    int lane = threadIdx.x & 31, wid = threadIdx.x >> 5;
    for (int o = 16; o; o >>= 1) { s += __shfl_xor_sync(~0u, s, o); s2 += __shfl_xor_sync(~0u, s2, o); }
    if (lane == 0) { sh[wid] = s; sh2[wid] = s2; }
    __syncthreads();
    if (wid == 0) {
        s  = (lane < 8) ? sh[lane]  : 0.f;
        s2 = (lane < 8) ? sh2[lane] : 0.f;
        for (int o = 16; o; o >>= 1) { s += __shfl_xor_sync(~0u, s, o); s2 += __shfl_xor_sync(~0u, s2, o); }
        if (lane == 0) { sh[0] = s; sh2[0] = s2; }
    }
    __syncthreads();
    float mean = sh[0] / DD;
    float var  = sh2[0] / DD - mean * mean;
    float inv = rsqrtf(var + 1e-5f);
    float* yr = y + (long long)row * DD;
    for (int d = threadIdx.x; d < DD; d += 256)
        yr[d] = (xr[d] - mean) * inv * g[d] + b[d];
}

__global__ void rope_kernel(float* __restrict__ q, float* __restrict__ k) {
    int idx = blockIdx.x * blockDim.x + threadIdx.x;
    if (idx >= TOK * (DD / 2)) return;
    int t = idx / (DD / 2), j = idx - t * (DD / 2);
    int s = t & (SS - 1);
    float freq = __expf(-9.210340371976184f * ((float)j / 384.f));
    float ang = (float)s * freq;
    float c, sn; sincosf(ang, &sn, &c);
    {
        float* p = q + (long long)t * DD + 2 * j;
        float a = p[0], b = p[1];
        p[0] = a * c - b * sn; p[1] = a * sn + b * c;
    }
    {
        float* p = k + (long long)t * DD + 2 * j;
        float a = p[0], b = p[1];
        p[0] = a * c - b * sn; p[1] = a * sn + b * c;
    }
}

__global__ void softmax_causal(float* __restrict__ sc) {
    int z = blockIdx.y, r = blockIdx.x;
    float* row = sc + ((long long)z << 20) + (long long)r * 1024;
    int n = r + 1;
    int nz = (r & ~63) + 64;   // AV (causal=2) reads only up to the row's 64-block end
    __shared__ float sh[32];
    int lane = threadIdx.x & 31, wid = threadIdx.x >> 5;
    float mx = -1e30f;
    for (int j = threadIdx.x; j < n; j += 256) mx = fmaxf(mx, row[j]);
    for (int o = 16; o; o >>= 1) mx = fmaxf(mx, __shfl_xor_sync(~0u, mx, o));
    if (lane == 0) sh[wid] = mx;
    __syncthreads();
    if (wid == 0) {
        mx = (lane < 8) ? sh[lane] : -1e30f;
        for (int o = 16; o; o >>= 1) mx = fmaxf(mx, __shfl_xor_sync(~0u, mx, o));
        if (lane == 0) sh[0] = mx;
    }
    __syncthreads();
    mx = sh[0];
    __syncthreads();
    float s = 0.f;
    for (int j = threadIdx.x; j < n; j += 256) s += __expf(row[j] - mx);
    for (int o = 16; o; o >>= 1) s += __shfl_xor_sync(~0u, s, o);
    if (lane == 0) sh[wid] = s;
    __syncthreads();
    if (wid == 0) {
        s = (lane < 8) ? sh[lane] : 0.f;
        for (int o = 16; o; o >>= 1) s += __shfl_xor_sync(~0u, s, o);
        if (lane == 0) sh[0] = s;
    }
    __syncthreads();
    float inv = 1.f / sh[0];
    for (int j = threadIdx.x; j < nz; j += 256)
        row[j] = (j < n) ? __expf(row[j] - mx) * inv : 0.f;
}

__global__ void zero_cnt(int* c) { if (threadIdx.x < EE) c[threadIdx.x] = 0; }

__global__ void route_kernel(const float* __restrict__ h, const float* __restrict__ gw,
                             int* cnt, int* etok, int* easn, float* wts) {
    int w = (blockIdx.x * blockDim.x + threadIdx.x) >> 5;
    int lane = threadIdx.x & 31;
    if (w >= TOK) return;
    const float* hr = h + (long long)w * DD;
    float lg[EE];
#pragma unroll
    for (int e = 0; e < EE; e++) {
        float s = 0.f;
        for (int d = lane; d < DD; d += 32) s += hr[d] * gw[d * EE + e];
        for (int o = 16; o; o >>= 1) s += __shfl_xor_sync(~0u, s, o);
        lg[e] = s;
    }
    if (lane == 0) {
        int e0 = 0;
        for (int e = 1; e < EE; e++) if (lg[e] > lg[e0]) e0 = e;
        int e1 = -1;
        for (int e = 0; e < EE; e++) { if (e == e0) continue; if (e1 < 0 || lg[e] > lg[e1]) e1 = e; }
        float x1 = __expf(lg[e1] - lg[e0]);
        float den = 1.f + x1;
        float w0 = 1.f / den, w1 = x1 / den;
        int s0 = atomicAdd(&cnt[e0], 1);
        etok[e0 * TOK + s0] = w; easn[e0 * TOK + s0] = 2 * w;
        int s1 = atomicAdd(&cnt[e1], 1);
        etok[e1 * TOK + s1] = w; easn[e1 * TOK + s1] = 2 * w + 1;
        wts[2 * w] = w0; wts[2 * w + 1] = w1;
    }
}

__global__ void combine_kernel(float* __restrict__ x, const float* __restrict__ ys,
                               const float* __restrict__ wts) {
    int idx = blockIdx.x * blockDim.x + threadIdx.x;
    if (idx >= TOK * DD) return;
    int t = idx / DD, d = idx - t * DD;
    x[idx] += wts[2 * t] * ys[(long long)(2 * t) * DD + d]
            + wts[2 * t + 1] * ys[(long long)(2 * t + 1) * DD + d];
}

__global__ void basis_kernel(float* __restrict__ Cb) {
    int idx = blockIdx.x * blockDim.x + threadIdx.x;
    if (idx >= 1026 * 1024) return;
    int j = idx >> 10, n = idx & 1023;
    const float invN = 1.f / 1024.f;
    float v;
    if (j == 0) v = invN;
    else if (j <= 511) { int m = (j * n) & 1023; v = 2.f * invN * cosf(m * TWO_PI_N); }
    else if (j == 512) v = invN * ((n & 1) ? -1.f : 1.f);
    else if (j == 513 || j == 1025) v = 0.f;
    else { int kk = j - 513; int m = (kk * n) & 1023; v = -2.f * invN * sinf(m * TWO_PI_N); }
    Cb[idx] = v;
}

__global__ void bf_kernel(const float* __restrict__ ob, const float* __restrict__ Cb,
                          float* __restrict__ bf) {
    int n = blockIdx.x * 128 + threadIdx.x;
    float s = 0.f;
    for (int j = 0; j < 1026; j++) s += ob[j] * Cb[j * 1024 + n];
    bf[n] = s;
}

__global__ void istft_kernel(const float* __restrict__ frames, float* __restrict__ out) {
    int idx = blockIdx.x * blockDim.x + threadIdx.x;
    if (idx >= BB * OUTL) return;
    int b = idx / OUTL, i = idx - b * OUTL;
    int ip = i + PADL;
    int tmin = (ip >= 1024) ? ((ip - 768) >> 8) : 0;
    int tmax = min(1023, ip >> 8);
    float acc = 0.f, env = 0.f;
    for (int t = tmin; t <= tmax; t++) {
        int n = ip - (t << 8);
        float w = 0.5f * (1.f - cosf(n * TWO_PI_N));
        acc += frames[((long long)(b * 1024 + t) << 10) + n] * w;
        env += w * w;
    }
    out[idx] = acc / env;
}

// ---------------- host side ----------------
static void* symaddr(const void* sym) {
    void* p = nullptr;
    cudaGetSymbolAddress(&p, sym);
    return p;
}

struct GemmArgs {
    const float* A; int lda; long long sAz, sAz2;
    const float* B; int ldb; long long sBz, sBz2;
    float* C; int ldc; long long sCz, sCz2;
    int zdiv;
    const float* bias; long long sbz; const float* res;
    int M, N, Kd; float alpha; int Z;
    const int* idxA; const int* idxC; const int* cnt;
    int causal; int gridM;
    const uint32_t* PBh; const uint32_t* PBl; long long sPBz; int ldPB;
};

#define BPK_SZH(TRB, BN) ((TRB) ? ((BN) * APK_LD) : (8 * ((BN) + 8)))
#define SMEM_RSTG(TRB, BN) (4 * 2 * (2 * APK_SZ + 2 * BPK_SZH(TRB, BN)))
#define SMEM_PKB (4 * (2 * 2 * APK_SZ + 4 * 2 * 8 * 136))

static void gemm(int act, bool trb, int BN, const GemmArgs& a)
{
    dim3 grid((a.N + BN - 1) / BN, a.gridM ? a.gridM : (a.M + 63) / 64, a.Z);
    if (a.PBh) {
        size_t shm = SMEM_PKB;
        cudaFuncSetAttribute(gemm_kernel<0, false, 128, true>, cudaFuncAttributeMaxDynamicSharedMemorySize, (int)shm);
        gemm_kernel<0, false, 128, true><<<grid, 256, shm>>>(a.A, a.lda, a.sAz, a.sAz2, a.B, a.ldb, a.sBz, a.sBz2,
            a.C, a.ldc, a.sCz, a.sCz2, a.zdiv, a.bias, a.sbz, a.res,
            a.M, a.N, a.Kd, a.alpha, a.idxA, a.idxC, a.cnt, a.causal, a.PBh, a.PBl, a.sPBz, a.ldPB);
    } else if (act == 1) {
        size_t shm = SMEM_RSTG(false, 128);
        cudaFuncSetAttribute(gemm_kernel<1, false, 128, false>, cudaFuncAttributeMaxDynamicSharedMemorySize, (int)shm);
        gemm_kernel<1, false, 128, false><<<grid, 256, shm>>>(a.A, a.lda, a.sAz, a.sAz2, a.B, a.ldb, a.sBz, a.sBz2,
            a.C, a.ldc, a.sCz, a.sCz2, a.zdiv, a.bias, a.sbz, a.res,
            a.M, a.N, a.Kd, a.alpha, a.idxA, a.idxC, a.cnt, a.causal, nullptr, nullptr, 0, 0);
    } else if (trb) {
        size_t shm = SMEM_RSTG(true, 128);
        cudaFuncSetAttribute(gemm_kernel<0, true, 128, false>, cudaFuncAttributeMaxDynamicSharedMemorySize, (int)shm);
        gemm_kernel<0, true, 128, false><<<grid, 256, shm>>>(a.A, a.lda, a.sAz, a.sAz2, a.B, a.ldb, a.sBz, a.sBz2,
            a.C, a.ldc, a.sCz, a.sCz2, a.zdiv, a.bias, a.sbz, a.res,
            a.M, a.N, a.Kd, a.alpha, a.idxA, a.idxC, a.cnt, a.causal, nullptr, nullptr, 0, 0);
    } else if (BN == 128) {
        size_t shm = SMEM_RSTG(false, 128);
        cudaFuncSetAttribute(gemm_kernel<0, false, 128, false>, cudaFuncAttributeMaxDynamicSharedMemorySize, (int)shm);
        gemm_kernel<0, false, 128, false><<<grid, 256, shm>>>(a.A, a.lda, a.sAz, a.sAz2, a.B, a.ldb, a.sBz, a.sBz2,
            a.C, a.ldc, a.sCz, a.sCz2, a.zdiv, a.bias, a.sbz, a.res,
            a.M, a.N, a.Kd, a.alpha, a.idxA, a.idxC, a.cnt, a.causal, nullptr, nullptr, 0, 0);
    } else {
        size_t shm = SMEM_RSTG(false, 64);
        cudaFuncSetAttribute(gemm_kernel<0, false, 64, false>, cudaFuncAttributeMaxDynamicSharedMemorySize, (int)shm);
        gemm_kernel<0, false, 64, false><<<grid, 256, shm>>>(a.A, a.lda, a.sAz, a.sAz2, a.B, a.ldb, a.sBz, a.sBz2,
            a.C, a.ldc, a.sCz, a.sCz2, a.zdiv, a.bias, a.sbz, a.res,
            a.M, a.N, a.Kd, a.alpha, a.idxA, a.idxC, a.cnt, a.causal, nullptr, nullptr, 0, 0);
    }
}

static void launch_pack(const float* W, int K, int N, uint32_t* Ph, uint32_t* Pl)
{
    int K2 = (K + 1) >> 1;
    int tot = K2 * (N >> 2);
    pack_w<<<(tot + 255) / 256, 256>>>(W, 0, K, N, Ph, Pl, 0);
}

extern "C" void kernel_launch(void* const* d_in, const int* in_sizes, int n_in,
                              void* d_out, int out_size)
{
    const float* z_in  = (const float*)d_in[0];
    const float* in_w  = (const float*)d_in[1];
    const float* in_b  = (const float*)d_in[2];
    const float* ln1g  = (const float*)d_in[3];
    const float* ln1b  = (const float*)d_in[4];
    const float* wq    = (const float*)d_in[5];
    const float* bq    = (const float*)d_in[6];
    const float* wk    = (const float*)d_in[7];
    const float* bk    = (const float*)d_in[8];
    const float* wv    = (const float*)d_in[9];
    const float* bv    = (const float*)d_in[10];
    const float* wo    = (const float*)d_in[11];
    const float* bo    = (const float*)d_in[12];
    const float* ln2g  = (const float*)d_in[13];
    const float* ln2b  = (const float*)d_in[14];
    const float* gatew = (const float*)d_in[15];
    const float* ew1   = (const float*)d_in[16];
    const float* eb1   = (const float*)d_in[17];
    const float* ew2   = (const float*)d_in[18];
    const float* eb2   = (const float*)d_in[19];
    const float* outw  = (const float*)d_in[20];
    const float* outb  = (const float*)d_in[21];
    float* out = (float*)d_out;

    float* ZT = (float*)symaddr(g_zt);
    float* X  = (float*)symaddr(g_x);
    float* H  = (float*)symaddr(g_h);
    float* QKV = (float*)symaddr(g_qkv);
    float* BQKV = (float*)symaddr(g_bqkv);
    float* Q  = QKV;
    float* Kb = QKV + (long long)TOK * DD;
    float* V  = QKV + 2LL * TOK * DD;
    float* AO = (float*)symaddr(g_ao);
    float* SC = (float*)symaddr(g_scores);
    float* HID = (float*)symaddr(g_hidden);
    float* YS = (float*)symaddr(g_yslot);
    float* CB = (float*)symaddr(g_Cb);
    float* MT = (float*)symaddr(g_Mt);
    float* BF = (float*)symaddr(g_bf);
    float* FR = (float*)symaddr(g_frames);
    int* CNT = (int*)symaddr(g_cnt);
    int* ETK = (int*)symaddr(g_etok);
    int* EAS = (int*)symaddr(g_easn);
    float* WTS = (float*)symaddr(g_wts);
    uint32_t* PK_INW = (uint32_t*)symaddr(g_pk_inw);
    uint32_t* PK_QKV = (uint32_t*)symaddr(g_pk_qkv);
    uint32_t* PK_WO  = (uint32_t*)symaddr(g_pk_wo);
    uint32_t* PK_CB  = (uint32_t*)symaddr(g_pk_cb);
    uint32_t* PK_MT  = (uint32_t*)symaddr(g_pk_mt);

    // pre-pack small static weights (hi then lo halves)
    launch_pack(in_w, CIN, DD, PK_INW, PK_INW + SZ_INW);

    // in_projection: zt = z^T, x = zt @ in_w + in_b
    transpose_z<<<dim3(SS / 32, CIN / 32, BB), dim3(32, 8)>>>(z_in, ZT);
    {
        GemmArgs a = {ZT, CIN, 0, 0, nullptr, DD, 0, 0, X, DD, 0, 0, 1,
                      in_b, 0, nullptr, TOK, DD, CIN, 1.f, 1, nullptr, nullptr, nullptr, 0, 0,
                      PK_INW, PK_INW + SZ_INW, 0, DD};
        gemm(0, false, 128, a);
    }

    for (int L = 0; L < 2; L++) {
        // pack this layer's qkv + wo weights (hi block then lo block, 3 z-slots for qkv)
        launch_pack(wq + (long long)L * DD * DD, DD, DD, PK_QKV,                PK_QKV + 3 * SZ_QKV1);
        launch_pack(wk + (long long)L * DD * DD, DD, DD, PK_QKV + SZ_QKV1,     PK_QKV + 3 * SZ_QKV1 + SZ_QKV1);
        launch_pack(wv + (long long)L * DD * DD, DD, DD, PK_QKV + 2 * SZ_QKV1, PK_QKV + 3 * SZ_QKV1 + 2 * SZ_QKV1);
        launch_pack(wo + (long long)L * DD * DD, DD, DD, PK_WO, PK_WO + SZ_WO);
        cudaMemcpyAsync(BQKV,          bq + L * DD, DD * sizeof(float), cudaMemcpyDeviceToDevice);
        cudaMemcpyAsync(BQKV + DD,     bk + L * DD, DD * sizeof(float), cudaMemcpyDeviceToDevice);
        cudaMemcpyAsync(BQKV + 2 * DD, bv + L * DD, DD * sizeof(float), cudaMemcpyDeviceToDevice);

        ln_kernel<<<TOK, 256>>>(X, H, ln1g + L * DD, ln1b + L * DD);
        {
            GemmArgs a = {H, DD, 0, 0, nullptr, DD, 0, 0,
                          QKV, DD, (long long)TOK * DD, 0, 3,
                          BQKV, DD, nullptr, TOK, DD, DD, 1.f, 3, 0, 0, 0, 0, 0,
                          PK_QKV, PK_QKV + 3 * SZ_QKV1, SZ_QKV1, DD};
            gemm(0, false, 128, a);
        }
        if (L == 0)
            rope_kernel<<<(TOK * (DD / 2) + 255) / 256, 256>>>(Q, Kb);

        {
            GemmArgs a = {Q, DD, HD, (long long)SS * DD,
                          Kb, DD, HD, (long long)SS * DD,
                          SC, SS, (long long)SS * SS, (long long)HH * SS * SS, HH,
                          nullptr, 0, nullptr, SS, SS, HD, 0.125f, BB * HH, 0, 0, 0, 1, 0,
                          nullptr, nullptr, 0, 0};
            gemm(0, true, 128, a);
        }
        softmax_causal<<<dim3(SS, BB * HH), 256>>>(SC);
        {
            GemmArgs a = {SC, SS, (long long)SS * SS, (long long)HH * SS * SS,
                          V, DD, HD, (long long)SS * DD,
                          AO, DD, HD, (long long)SS * DD, HH,
                          nullptr, 0, nullptr, SS, HD, SS, 1.f, BB * HH, 0, 0, 0, 2, 0,
                          nullptr, nullptr, 0, 0};
            gemm(0, false, 64, a);
        }
        {
            GemmArgs a = {AO, DD, 0, 0, nullptr, DD, 0, 0, X, DD, 0, 0, 1,
                          bo + L * DD, 0, X, TOK, DD, DD, 1.f, 1, 0, 0, 0, 0, 0,
                          PK_WO, PK_WO + SZ_WO, 0, DD};
            gemm(0, false, 128, a);
        }

        // MoE (unchanged reg-staged path)
        ln_kernel<<<TOK, 256>>>(X, H, ln2g + L * DD, ln2b + L * DD);
        zero_cnt<<<1, 32>>>(CNT);
        route_kernel<<<TOK / 8, 256>>>(H, gatew + (long long)L * DD * EE, CNT, ETK, EAS, WTS);
        {
            GemmArgs a = {H, DD, 0, 0,
                          ew1 + (long long)L * EE * DD * FF, FF, (long long)DD * FF, 0,
                          HID, FF, 0, 0, EE,
                          eb1 + (long long)L * EE * FF, FF, nullptr,
                          TOK, FF, DD, 1.f, EE, ETK, EAS, CNT, 0, TOK / 64,
                          nullptr, nullptr, 0, 0};
            gemm(1, false, 128, a);
        }
        {
            GemmArgs a = {HID, FF, 0, 0,
                          ew2 + (long long)L * EE * FF * DD, DD, (long long)FF * DD, 0,
                          YS, DD, 0, 0, EE,
                          eb2 + (long long)L * EE * DD, DD, nullptr,
                          TOK, DD, FF, 1.f, EE, EAS, EAS, CNT, 0, TOK / 64,
                          nullptr, nullptr, 0, 0};
            gemm(0, false, 128, a);
        }
        combine_kernel<<<(TOK * DD + 255) / 256, 256>>>(X, YS, WTS);
    }

    // out projection fused with irfft basis: frames = x @ (out_w @ Cb) + out_b @ Cb
    basis_kernel<<<(1026 * 1024 + 255) / 256, 256>>>(CB);
    launch_pack(CB, 1026, 1024, PK_CB, PK_CB + SZ_CB);
    {
        GemmArgs a = {outw, 2 * FB, 0, 0, nullptr, 1024, 0, 0, MT, 1024, 0, 0, 1,
                      nullptr, 0, nullptr, DD, 1024, 2 * FB, 1.f, 1, 0, 0, 0, 0, 0,
                      PK_CB, PK_CB + SZ_CB, 0, 1024};
        gemm(0, false, 128, a);
    }
    launch_pack(MT, DD, 1024, PK_MT, PK_MT + SZ_MT);
    bf_kernel<<<8, 128>>>(outb, CB, BF);
    {
        GemmArgs a = {X, DD, 0, 0, nullptr, 1024, 0, 0, FR, 1024, 0, 0, 1,
                      BF, 0, nullptr, TOK, 1024, DD, 1.f, 1, 0, 0, 0, 0, 0,
                      PK_MT, PK_MT + SZ_MT, 0, 1024};
        gemm(0, false, 128, a);
    }

    // windowed overlap-add + env normalize + trim
    istft_kernel<<<(BB * OUTL + 255) / 256, 256>>>(FR, out);
}

// round 17
// speedup vs baseline: 1.5591x; 1.0045x over previous
#include <cuda_runtime.h>
#include <math.h>
#include <stdint.h>

// ---------------- constants ----------------
#define BB 2
#define SS 1024
#define DD 768
#define HH 12
#define HD 64
#define EE 8
#define FF 2048
#define CIN 512
#define TOK (BB*SS)          // 2048
#define FB 513
#define PADL 384
#define OUTL 262144
#define TWO_PI_N 0.006135923151542565f   // 2*pi/1024

// ---------------- scratch (device globals; allocation-free) ----------------
__device__ float g_zt[TOK*CIN];
__device__ float g_x [TOK*DD];
__device__ float g_h [TOK*DD];
__device__ float g_qkv[3*TOK*DD];
__device__ float g_bqkv[3*DD];
__device__ float g_ao[TOK*DD];
__device__ float g_scores[24u*1024u*1024u];
__device__ float g_hidden[4096*FF];
__device__ float g_yslot [4096*DD];
__device__ float g_Cb[1026*1024];
__device__ float g_Mt[DD*1024];
__device__ float g_bf[1024];
__device__ float g_frames[TOK*1024];
__device__ int   g_cnt[EE];
__device__ int   g_etok[EE*TOK];
__device__ int   g_easn[EE*TOK];
__device__ float g_wts[2*TOK];

// packed small weights: hi at [0,SZ), lo at [SZ,2SZ)
#define SZ_INW  (256*768)
#define SZ_QKV1 (384*768)
#define SZ_WO   (384*768)
#define SZ_CB   (513*1024)
#define SZ_MT   (384*1024)
__device__ uint32_t g_pk_inw[2*SZ_INW];
__device__ uint32_t g_pk_qkv[2*3*SZ_QKV1];
__device__ uint32_t g_pk_wo [2*SZ_WO];
__device__ uint32_t g_pk_cb [2*SZ_CB];
__device__ uint32_t g_pk_mt [2*SZ_MT];
// packed attention activations (per layer, overwritten)
#define SZ_ACT (TOK*384)     // TOK rows x 384 kpairs (Q,K) / (TOK/2) kpair-rows x 768 (V)
__device__ uint32_t g_pk_q[2*SZ_ACT];
__device__ uint32_t g_pk_k[2*SZ_ACT];
__device__ uint32_t g_pk_v[2*SZ_ACT];

// ---------------- bf16x3 helpers ----------------
__device__ __forceinline__ void pack_bf16pair(float f0, float f1, uint32_t& hi, uint32_t& lo) {
    uint32_t u0 = __float_as_uint(f0);
    uint32_t u1 = __float_as_uint(f1);
    uint32_t h;
    asm("prmt.b32 %0, %1, %2, 0x7632;" : "=r"(h) : "r"(u0), "r"(u1));
    hi = h;
    float l0 = f0 - __uint_as_float(u0 & 0xFFFF0000u);
    float l1 = f1 - __uint_as_float(u1 & 0xFFFF0000u);
    asm("cvt.rn.bf16x2.f32 %0, %1, %2;" : "=r"(lo) : "f"(l1), "f"(l0));
}
__device__ __forceinline__ void mma_bf16(float* c, const uint32_t* a, const uint32_t* b) {
    asm volatile(
        "mma.sync.aligned.m16n8k16.row.col.f32.bf16.bf16.f32 "
        "{%0,%1,%2,%3}, {%4,%5,%6,%7}, {%8,%9}, {%0,%1,%2,%3};"
        : "+f"(c[0]), "+f"(c[1]), "+f"(c[2]), "+f"(c[3])
        : "r"(a[0]), "r"(a[1]), "r"(a[2]), "r"(a[3]), "r"(b[0]), "r"(b[1]));
}
__device__ __forceinline__ void ldsm4(uint32_t& r0, uint32_t& r1, uint32_t& r2, uint32_t& r3, uint32_t addr) {
    asm volatile("ldmatrix.sync.aligned.m8n8.x4.shared.b16 {%0,%1,%2,%3}, [%4];"
        : "=r"(r0), "=r"(r1), "=r"(r2), "=r"(r3) : "r"(addr));
}
__device__ __forceinline__ void ldsm2(uint32_t& r0, uint32_t& r1, uint32_t addr) {
    asm volatile("ldmatrix.sync.aligned.m8n8.x2.shared.b16 {%0,%1}, [%2];"
        : "=r"(r0), "=r"(r1) : "r"(addr));
}
__device__ __forceinline__ void cpa16(uint32_t dst, const void* src, bool pred) {
    asm volatile("cp.async.ca.shared.global [%0], [%1], 16, %2;"
                 :: "r"(dst), "l"(src), "r"(pred ? 16 : 0));
}
__device__ __forceinline__ void cpa_commit() { asm volatile("cp.async.commit_group;"); }
__device__ __forceinline__ void cpa_wait0() { asm volatile("cp.async.wait_group 0;"); }
__device__ __forceinline__ void cpa_wait2() { asm volatile("cp.async.wait_group 2;"); }

// ---------------- weight pre-pack (float4 vectorized; pairs along K/rows) ----------------
__global__ void pack_w(const float* __restrict__ W, long long sWz, int K, int N,
                       uint32_t* __restrict__ Ph, uint32_t* __restrict__ Pl, long long sPz)
{
    int z = blockIdx.z;
    int K2 = (K + 1) >> 1;
    int n4c = N >> 2;
    int idx = blockIdx.x * 256 + threadIdx.x;
    if (idx >= K2 * n4c) return;
    int p = idx / n4c, n4 = (idx - p * n4c) << 2;
    const float* Wz = W + (long long)z * sWz;
    float4 a = *(const float4*)(Wz + (long long)(2 * p) * N + n4);
    float4 b;
    if (2 * p + 1 < K) b = *(const float4*)(Wz + (long long)(2 * p + 1) * N + n4);
    else { b.x = b.y = b.z = b.w = 0.f; }
    uint32_t h0, l0, h1, l1, h2, l2, h3, l3;
    pack_bf16pair(a.x, b.x, h0, l0);
    pack_bf16pair(a.y, b.y, h1, l1);
    pack_bf16pair(a.z, b.z, h2, l2);
    pack_bf16pair(a.w, b.w, h3, l3);
    long long o = (long long)z * sPz + (long long)p * N + n4;
    *(uint4*)(Ph + o) = make_uint4(h0, h1, h2, h3);
    *(uint4*)(Pl + o) = make_uint4(l0, l1, l2, l3);
}

// pack pairs along rows (consecutive dims): X[r][2p],X[r][2p+1] -> out[r][p]
__global__ void pack_rows(const float* __restrict__ X, uint32_t* __restrict__ Ph,
                          uint32_t* __restrict__ Pl, int total4)
{
    int idx = blockIdx.x * 256 + threadIdx.x;
    if (idx >= total4) return;
    float4 v = ((const float4*)X)[idx];
    uint32_t h0, l0, h1, l1;
    pack_bf16pair(v.x, v.y, h0, l0);
    pack_bf16pair(v.z, v.w, h1, l1);
    ((uint2*)Ph)[idx] = make_uint2(h0, h1);
    ((uint2*)Pl)[idx] = make_uint2(l0, l1);
}

// ---------------- fully-packed causal scores kernel: S = alpha * Q K^T ----------------
// Tile 64(M) x 128(N), K=64 (32 kpairs) in one shot. 8 warps 2x4.
#define SQ_LD 36
__global__ __launch_bounds__(256, 2)
void scores_pk(const uint32_t* __restrict__ Qph, const uint32_t* __restrict__ Qpl,
               const uint32_t* __restrict__ Kph, const uint32_t* __restrict__ Kpl,
               float* __restrict__ SC, float alpha)
{
    int z = blockIdx.z;
    int b = z / HH, h = z - b * HH;
    int m0 = blockIdx.y * 64, n0 = blockIdx.x * 128;
    if (n0 > m0 + 63) return;
    extern __shared__ uint32_t sm[];
    uint32_t smA = (uint32_t)__cvta_generic_to_shared(sm);

    int tid = threadIdx.x;
    int lane = tid & 31, wid = tid >> 5;
    int wm = wid >> 2, wn = wid & 3;
    int lm = lane >> 2, lk = lane & 3;

    // load Q (64 rows x 32 u32) and K (128 rows x 32 u32), hi & lo
    {
        // Q: 512 chunks of 16B -> 2 per thread
#pragma unroll
        for (int it = 0; it < 2; it++) {
            int cid = tid + it * 256;
            int row = cid >> 3, q = cid & 7;
            long long qb = ((long long)(b * SS + m0 + row)) * 384 + h * 32 + 4 * q;
            cpa16(smA + ((row * SQ_LD + 4 * q) << 2), Qph + qb, true);
            cpa16(smA + ((64 * SQ_LD + row * SQ_LD + 4 * q) << 2), Qpl + qb, true);
        }
        // K: 1024 chunks -> 4 per thread
#pragma unroll
        for (int it = 0; it < 4; it++) {
            int cid = tid + it * 256;
            int row = cid >> 3, q = cid & 7;
            long long kb2 = ((long long)(b * SS + n0 + row)) * 384 + h * 32 + 4 * q;
            cpa16(smA + ((128 * SQ_LD + row * SQ_LD + 4 * q) << 2), Kph + kb2, true);
            cpa16(smA + ((256 * SQ_LD + row * SQ_LD + 4 * q) << 2), Kpl + kb2, true);
        }
    }
    cpa_commit();
    cpa_wait0();
    __syncthreads();

    float acc[2][4][4];
#pragma unroll
    for (int i = 0; i < 2; i++)
#pragma unroll
        for (int j = 0; j < 4; j++)
#pragma unroll
            for (int r = 0; r < 4; r++) acc[i][j][r] = 0.f;

    uint32_t aph = smA, apl = smA + ((64 * SQ_LD) << 2);
    uint32_t bphA = smA + ((128 * SQ_LD) << 2);
    uint32_t bplA = smA + ((256 * SQ_LD) << 2);

#pragma unroll
    for (int c = 0; c < 4; c++) {
        int kb = 8 * c;
        uint32_t ah[2][4], al[2][4];
        {
            int arow = wm * 32 + (lane & 15);
            uint32_t colp = (lane >> 4) << 2;
#pragma unroll
            for (int i = 0; i < 2; i++) {
                uint32_t off = (uint32_t)(((arow + i * 16) * SQ_LD + kb + colp) << 2);
                ldsm4(ah[i][0], ah[i][1], ah[i][2], ah[i][3], aph + off);
                ldsm4(al[i][0], al[i][1], al[i][2], al[i][3], apl + off);
            }
        }
#pragma unroll
        for (int j = 0; j < 4; j++) {
            int brow = wn * 32 + j * 8 + (lane & 7);
            uint32_t bcolp = (lane & 8) ? 4u : 0u;
            uint32_t boff = (uint32_t)((brow * SQ_LD + kb + bcolp) << 2);
            uint32_t bh[2], bl[2];
            ldsm2(bh[0], bh[1], bphA + boff);
            ldsm2(bl[0], bl[1], bplA + boff);
            mma_bf16(acc[0][j], ah[0], bh);
            mma_bf16(acc[1][j], ah[1], bh);
            mma_bf16(acc[0][j], al[0], bh);
            mma_bf16(acc[1][j], al[1], bh);
            mma_bf16(acc[0][j], ah[0], bl);
            mma_bf16(acc[1][j], ah[1], bl);
        }
    }

    float* Sz = SC + ((long long)z << 20);
#pragma unroll
    for (int i = 0; i < 2; i++) {
#pragma unroll
        for (int r2 = 0; r2 < 2; r2++) {
            int gm = m0 + wm * 32 + i * 16 + lm + r2 * 8;
            float* crow = Sz + (long long)gm * 1024;
#pragma unroll
            for (int j = 0; j < 4; j++) {
                int gn = n0 + wn * 32 + j * 8 + lk * 2;
                float2 o;
                o.x = acc[i][j][r2 * 2 + 0] * alpha;
                o.y = acc[i][j][r2 * 2 + 1] * alpha;
                *(float2*)(crow + gn) = o;
            }
        }
    }
}

// ---------------- register/async staged tensor-core GEMM (3xBF16) ----------------
// Tile: 64(M) x BN(N), K-step 16. 8 warps as 2(M) x 4(N); warp = 32 x BN/4.
#define APK_LD 12   // packed A row stride (uint32; 8 pairs + pad)
#define APK_SZ (64 * APK_LD)

template<int ACT, bool TRB, int BN, bool PKB>
__global__ __launch_bounds__(256, 2)
void gemm_kernel(const float* __restrict__ A, int lda, long long sAz, long long sAz2,
                 const float* __restrict__ B, int ldb, long long sBz, long long sBz2,
                 float* __restrict__ C, int ldc, long long sCz, long long sCz2,
                 int zdiv,
                 const float* __restrict__ bias, long long sbz,
                 const float* __restrict__ res,
                 int M, int N, int Kd, float alpha,
                 const int* __restrict__ idxA, const int* __restrict__ idxC,
                 const int* __restrict__ cnt, int causal,
                 const uint32_t* __restrict__ PBh, const uint32_t* __restrict__ PBl,
                 long long sPBz, long long sPBz2, int ldPB)
{
    constexpr int BPK_LD = TRB ? APK_LD : (BN + 8);
    constexpr int BPK_SZ = TRB ? (BN * APK_LD) : (8 * (BN + 8));
    constexpr int STAGE  = 2 * APK_SZ + 2 * BPK_SZ;   // non-PKB stage (u32)
    constexpr int BJ = BN / 32;
    constexpr int PK_AST = 2 * APK_SZ;
    constexpr int PKB_LDp = BN + 8;
    constexpr int PK_BST = 2 * 8 * PKB_LDp;

    int z = blockIdx.z;
    int z1 = z / zdiv, z0 = z - z1 * zdiv;
    if (cnt) M = cnt[z];
    int m0 = blockIdx.y * 64, n0 = blockIdx.x * BN;
    if (m0 >= M) return;
    if (causal == 1 && n0 > m0 + 63) return;
    if (causal == 2) Kd = min(Kd, m0 + 64);
    A += (long long)z0 * sAz + (long long)z1 * sAz2;
    if (!PKB) B += (long long)z0 * sBz + (long long)z1 * sBz2;
    else { PBh += (long long)z0 * sPBz + (long long)z1 * sPBz2;
           PBl += (long long)z0 * sPBz + (long long)z1 * sPBz2; }
    C += (long long)z0 * sCz + (long long)z1 * sCz2;
    if (bias) bias += (long long)z * sbz;
    if (res)  res  += (long long)z0 * sCz + (long long)z1 * sCz2;
    const int* iA = idxA ? idxA + z * TOK : nullptr;
    const int* iC = idxC ? idxC + z * TOK : nullptr;

    extern __shared__ uint32_t smem[];
    uint32_t smemAddr = (uint32_t)__cvta_generic_to_shared(smem);

    int tid = threadIdx.x;
    int lane = tid & 31, wid = tid >> 5;
    int wm = wid >> 2, wn = wid & 3;
    int lm = lane >> 2, lk = lane & 3;

    float acc[2][BJ][4];
#pragma unroll
    for (int i = 0; i < 2; i++)
#pragma unroll
        for (int j = 0; j < BJ; j++)
#pragma unroll
            for (int r = 0; r < 4; r++) acc[i][j][r] = 0.f;

    const bool fastA = ((lda & 3) == 0) && ((Kd & 15) == 0);
    const bool fastB = ((ldb & 3) == 0) && (TRB ? ((Kd & 15) == 0) : true);

    float rA[4];
    float rB[8];
    int mmA = tid >> 2, qA = tid & 3;
    int raA = -1;
    {
        int gm = m0 + mmA;
        if (gm < M) raA = iA ? iA[gm] : gm;
    }
    int pB = 0, nqB = 0;
    bool bAct = true;
    if (!TRB && !PKB) {
        if (BN == 128) { pB = tid >> 5; nqB = tid & 31; }
        else { pB = tid >> 4; nqB = tid & 15; bAct = (tid < 128); }
    }

    auto load_regsA = [&](int k0) {
        if (raA >= 0) {
            if (fastA) {
                const float4 v = *(const float4*)(A + (long long)raA * lda + k0 + 4 * qA);
                rA[0] = v.x; rA[1] = v.y; rA[2] = v.z; rA[3] = v.w;
            } else {
#pragma unroll
                for (int j = 0; j < 4; j++) {
                    int gk = k0 + 4 * qA + j;
                    rA[j] = (gk < Kd) ? A[(long long)raA * lda + gk] : 0.f;
                }
            }
        } else {
            rA[0] = rA[1] = rA[2] = rA[3] = 0.f;
        }
    };

    auto load_regsB = [&](int k0) {
        if (!TRB) {
            if (bAct) {
                int gk0 = k0 + 2 * pB;
                int nb = n0 + 4 * nqB;
#pragma unroll
                for (int r = 0; r < 2; r++) {
                    int gk = gk0 + r;
                    if (gk < Kd) {
                        if (fastB) {
                            const float4 v = *(const float4*)(B + (long long)gk * ldb + nb);
                            rB[4 * r + 0] = v.x; rB[4 * r + 1] = v.y;
                            rB[4 * r + 2] = v.z; rB[4 * r + 3] = v.w;
                        } else {
#pragma unroll
                            for (int j = 0; j < 4; j++)
                                rB[4 * r + j] = B[(long long)gk * ldb + nb + j];
                        }
                    } else {
                        rB[4 * r + 0] = rB[4 * r + 1] = rB[4 * r + 2] = rB[4 * r + 3] = 0.f;
                    }
                }
            }
        } else {
#pragma unroll
            for (int it = 0; it < BN / 64; it++) {
                int lin = tid + it * 256;
                int nn = lin >> 2, q = lin & 3;
                int gn = n0 + nn;
                if (gn < N) {
                    if (fastB) {
                        const float4 v = *(const float4*)(B + (long long)gn * ldb + k0 + 4 * q);
                        rB[4 * it + 0] = v.x; rB[4 * it + 1] = v.y;
                        rB[4 * it + 2] = v.z; rB[4 * it + 3] = v.w;
                    } else {
#pragma unroll
                        for (int j = 0; j < 4; j++) {
                            int gk = k0 + 4 * q + j;
                            rB[4 * it + j] = (gk < Kd) ? B[(long long)gn * ldb + gk] : 0.f;
                        }
                    }
                } else {
                    rB[4 * it + 0] = rB[4 * it + 1] = rB[4 * it + 2] = rB[4 * it + 3] = 0.f;
                }
            }
        }
    };

    // ============================ PKB path ============================
    if constexpr (PKB) {
        uint32_t* Asm = smem;                                 // 2 * PK_AST
        uint32_t baseB = smemAddr + ((2 * PK_AST) << 2);      // 4 * PK_BST

        auto convA = [&](int s) {
            uint32_t* Aph = Asm + s * PK_AST;
            uint32_t* Apl = Aph + APK_SZ;
            uint32_t hi, lo;
            pack_bf16pair(rA[0], rA[1], hi, lo);
            Aph[mmA * APK_LD + 2 * qA] = hi;
            Apl[mmA * APK_LD + 2 * qA] = lo;
            pack_bf16pair(rA[2], rA[3], hi, lo);
            Aph[mmA * APK_LD + 2 * qA + 1] = hi;
            Apl[mmA * APK_LD + 2 * qA + 1] = lo;
        };
        auto cpaB = [&](int ks, int st) {
            bool act = (BN == 128) || (tid < 128);
            if (act) {
                int p, n4;
                if (BN == 128) { p = tid >> 5; n4 = (tid & 31) * 4; }
                else { p = (tid >> 4) & 7; n4 = (tid & 15) * 4; }
                bool pred = (ks * 16 + 2 * p) < Kd;
                int krow = pred ? (ks * 8 + p) : 0;
                long long row = (long long)krow * ldPB + n0 + n4;
                uint32_t d = baseB + ((st * PK_BST + p * PKB_LDp + n4) << 2);
                cpa16(d, PBh + row, pred);
                cpa16(d + ((8 * PKB_LDp) << 2), PBl + row, pred);
            }
        };
        auto computeP = [&](int i) {
            uint32_t aph = smemAddr + (((i & 1) * PK_AST) << 2);
            uint32_t apl = aph + (APK_SZ << 2);
            const uint32_t* Bph = smem + 2 * PK_AST + (i & 3) * PK_BST;
            const uint32_t* Bpl = Bph + 8 * PKB_LDp;
            uint32_t ah[2][4], al[2][4];
            {
                int arow = wm * 32 + (lane & 15);
                uint32_t colp = (lane >> 4) << 2;
#pragma unroll
                for (int i2 = 0; i2 < 2; i2++) {
                    uint32_t off = (uint32_t)(((arow + i2 * 16) * APK_LD + colp) << 2);
                    ldsm4(ah[i2][0], ah[i2][1], ah[i2][2], ah[i2][3], aph + off);
                    ldsm4(al[i2][0], al[i2][1], al[i2][2], al[i2][3], apl + off);
                }
            }
#pragma unroll
            for (int j = 0; j < BJ; j++) {
                int bn = wn * (BN / 4) + j * 8 + lm;
                uint32_t bh[2], bl[2];
                bh[0] = Bph[lk * PKB_LDp + bn];
                bh[1] = Bph[(lk + 4) * PKB_LDp + bn];
                bl[0] = Bpl[lk * PKB_LDp + bn];
                bl[1] = Bpl[(lk + 4) * PKB_LDp + bn];
                mma_bf16(acc[0][j], ah[0], bh);
                mma_bf16(acc[1][j], ah[1], bh);
                mma_bf16(acc[0][j], al[0], bh);
                mma_bf16(acc[1][j], al[1], bh);
                mma_bf16(acc[0][j], ah[0], bl);
                mma_bf16(acc[1][j], ah[1], bl);
            }
        };

        int nk = (Kd + 15) >> 4;
        cpaB(0, 0); cpa_commit();
        if (nk > 1) cpaB(1, 1);
        cpa_commit();
        if (nk > 2) cpaB(2, 2);
        cpa_commit();
        load_regsA(0);
        convA(0);
        if (nk > 1) load_regsA(16);
        cpa_wait2();
        __syncthreads();
        for (int i = 0; i < nk; i++) {
            computeP(i);
            if (i + 1 < nk) convA((i + 1) & 1);
            if (i + 2 < nk) load_regsA((i + 2) * 16);
            if (i + 3 < nk) cpaB(i + 3, (i + 3) & 3);
            cpa_commit();
            cpa_wait2();
            __syncthreads();
        }
    } else {
    // ============================ reg-staged path ============================
        auto convert_stage = [&](int s) {
            uint32_t* Aph = smem + s * STAGE;
            uint32_t* Apl = Aph + APK_SZ;
            uint32_t* Bph = Apl + APK_SZ;
            uint32_t* Bpl = Bph + BPK_SZ;
            {
                uint32_t hi, lo;
                pack_bf16pair(rA[0], rA[1], hi, lo);
                Aph[mmA * APK_LD + 2 * qA] = hi;
                Apl[mmA * APK_LD + 2 * qA] = lo;
                pack_bf16pair(rA[2], rA[3], hi, lo);
                Aph[mmA * APK_LD + 2 * qA + 1] = hi;
                Apl[mmA * APK_LD + 2 * qA + 1] = lo;
            }
            if (!TRB) {
                if (bAct) {
#pragma unroll
                    for (int j = 0; j < 4; j++) {
                        uint32_t hi, lo;
                        pack_bf16pair(rB[j], rB[4 + j], hi, lo);
                        Bph[pB * BPK_LD + 4 * nqB + j] = hi;
                        Bpl[pB * BPK_LD + 4 * nqB + j] = lo;
                    }
                }
            } else {
#pragma unroll
                for (int it = 0; it < BN / 64; it++) {
                    int lin = tid + it * 256;
                    int nn = lin >> 2, q = lin & 3;
                    uint32_t hi, lo;
                    pack_bf16pair(rB[4 * it + 0], rB[4 * it + 1], hi, lo);
                    Bph[nn * BPK_LD + 2 * q] = hi;
                    Bpl[nn * BPK_LD + 2 * q] = lo;
                    pack_bf16pair(rB[4 * it + 2], rB[4 * it + 3], hi, lo);
                    Bph[nn * BPK_LD + 2 * q + 1] = hi;
                    Bpl[nn * BPK_LD + 2 * q + 1] = lo;
                }
            }
        };
        auto compute = [&](int s) {
            uint32_t base = smemAddr + ((s * STAGE) << 2);
            uint32_t aph = base, apl = base + (APK_SZ << 2);
            uint32_t bphA = base + ((2 * APK_SZ) << 2);
            uint32_t bplA = base + ((2 * APK_SZ + BPK_SZ) << 2);
            const uint32_t* Bph = smem + s * STAGE + 2 * APK_SZ;
            const uint32_t* Bpl = Bph + BPK_SZ;
            uint32_t ah[2][4], al[2][4];
            {
                int arow = wm * 32 + (lane & 15);
                uint32_t colp = (lane >> 4) << 2;
#pragma unroll
                for (int i = 0; i < 2; i++) {
                    uint32_t off = (uint32_t)(((arow + i * 16) * APK_LD + colp) << 2);
                    ldsm4(ah[i][0], ah[i][1], ah[i][2], ah[i][3], aph + off);
                    ldsm4(al[i][0], al[i][1], al[i][2], al[i][3], apl + off);
                }
            }
#pragma unroll
            for (int j = 0; j < BJ; j++) {
                uint32_t bh[2], bl[2];
                if (!TRB) {
                    int bn = wn * (BN / 4) + j * 8 + lm;
                    bh[0] = Bph[lk * BPK_LD + bn];
                    bh[1] = Bph[(lk + 4) * BPK_LD + bn];
                    bl[0] = Bpl[lk * BPK_LD + bn];
                    bl[1] = Bpl[(lk + 4) * BPK_LD + bn];
                } else {
                    int brow = wn * (BN / 4) + j * 8 + (lane & 7);
                    uint32_t bcolp = (lane & 8) ? 4u : 0u;
                    uint32_t boff = (uint32_t)((brow * APK_LD + bcolp) << 2);
                    ldsm2(bh[0], bh[1], bphA + boff);
                    ldsm2(bl[0], bl[1], bplA + boff);
                }
                mma_bf16(acc[0][j], ah[0], bh);
                mma_bf16(acc[1][j], ah[1], bh);
                mma_bf16(acc[0][j], al[0], bh);
                mma_bf16(acc[1][j], al[1], bh);
                mma_bf16(acc[0][j], ah[0], bl);
                mma_bf16(acc[1][j], ah[1], bl);
            }
        };

        int nk = (Kd + 15) >> 4;
        load_regsA(0); load_regsB(0);
        convert_stage(0);
        if (nk > 1) { load_regsA(16); load_regsB(16); }
        __syncthreads();
        for (int i = 0; i < nk; i++) {
            compute(i & 1);
            if (i + 1 < nk) {
                convert_stage((i + 1) & 1);
                if (i + 2 < nk) { load_regsA((i + 2) * 16); load_regsB((i + 2) * 16); }
            }
            __syncthreads();
        }
    }

    // ---- epilogue (float2 stores; all N/ldc even) ----
#pragma unroll
    for (int i = 0; i < 2; i++) {
#pragma unroll
        for (int r2 = 0; r2 < 2; r2++) {
            int gm = m0 + wm * 32 + i * 16 + lm + r2 * 8;
            if (gm >= M) continue;
            int rc = iC ? iC[gm] : gm;
            float* crow = C + (long long)rc * ldc;
            const float* rrow = res ? res + (long long)rc * ldc : nullptr;
#pragma unroll
            for (int j = 0; j < BJ; j++) {
                int gn = n0 + wn * (BN / 4) + j * 8 + lk * 2;
                if (gn >= N) continue;
                float v0 = acc[i][j][r2 * 2 + 0] * alpha;
                float v1 = acc[i][j][r2 * 2 + 1] * alpha;
                if (bias) { v0 += bias[gn]; v1 += bias[gn + 1]; }
                if (ACT == 1) {
                    float t0 = tanhf(0.7978845608028654f * (v0 + 0.044715f * v0 * v0 * v0));
                    float t1 = tanhf(0.7978845608028654f * (v1 + 0.044715f * v1 * v1 * v1));
                    v0 = 0.5f * v0 * (1.f + t0);
                    v1 = 0.5f * v1 * (1.f + t1);
                }
                if (rrow) {
                    const float2 rr = *(const float2*)(rrow + gn);
                    v0 += rr.x; v1 += rr.y;
                }
                float2 o; o.x = v0; o.y = v1;
                *(float2*)(crow + gn) = o;
            }
        }
    }
}

// ---------------- small kernels ----------------
__global__ void transpose_z(const float* __restrict__ z, float* __restrict__ zt) {
    __shared__ float tile[32][33];
    int b = blockIdx.z;
    int l0 = blockIdx.x * 32, c0 = blockIdx.y * 32;
    int x = threadIdx.x, y = threadIdx.y;
    for (int i = y; i < 32; i += 8)
        tile[i][x] = z[b * CIN * SS + (c0 + i) * SS + l0 + x];
    __syncthreads();
    for (int i = y; i < 32; i += 8)
        zt[b * SS * CIN + (long long)(l0 + i) * CIN + c0 + x] = tile[x][i];
}

__global__ void ln_kernel(const float* __restrict__ x, float* __restrict__ y,
                          const float* __restrict__ g, const float* __restrict__ b) {
    int row = blockIdx.x;
    const float* xr = x + (long long)row * DD;
    __shared__ float sh[32];
    __shared__ float sh2[32];
    float s = 0.f, s2 = 0.f;
    for (int d = threadIdx.x; d < DD; d += 256) { float v = xr[d]; s += v; s2 += v * v; }
    int lane = threadIdx.x & 31, wid = threadIdx.x >> 5;
    for (int o = 16; o; o >>= 1) { s += __shfl_xor_sync(~0u, s, o); s2 += __shfl_xor_sync(~0u, s2, o); }
    if (lane == 0) { sh[wid] = s; sh2[wid] = s2; }
    __syncthreads();
    if (wid == 0) {
        s  = (lane < 8) ? sh[lane]  : 0.f;
        s2 = (lane < 8) ? sh2[lane] : 0.f;
        for (int o = 16; o; o >>= 1) { s += __shfl_xor_sync(~0u, s, o); s2 += __shfl_xor_sync(~0u, s2, o); }
        if (lane == 0) { sh[0] = s; sh2[0] = s2; }
    }
    __syncthreads();
    float mean = sh[0] / DD;
    float var  = sh2[0] / DD - mean * mean;
    float inv = rsqrtf(var + 1e-5f);
    float* yr = y + (long long)row * DD;
    for (int d = threadIdx.x; d < DD; d += 256)
        yr[d] = (xr[d] - mean) * inv * g[d] + b[d];
}

__global__ void rope_kernel(float* __restrict__ q, float* __restrict__ k) {
    int idx = blockIdx.x * blockDim.x + threadIdx.x;
    if (idx >= TOK * (DD / 2)) return;
    int t = idx / (DD / 2), j = idx - t * (DD / 2);
    int s = t & (SS - 1);
    float freq = __expf(-9.210340371976184f * ((float)j / 384.f));
    float ang = (float)s * freq;
    float c, sn; sincosf(ang, &sn, &c);
    {
        float* p = q + (long long)t * DD + 2 * j;
        float a = p[0], b = p[1];
        p[0] = a * c - b * sn; p[1] = a * sn + b * c;
    }
    {
        float* p = k + (long long)t * DD + 2 * j;
        float a = p[0], b = p[1];
        p[0] = a * c - b * sn; p[1] = a * sn + b * c;
    }
}

__global__ void softmax_causal(float* __restrict__ sc) {
    int z = blockIdx.y, r = blockIdx.x;
    float* row = sc + ((long long)z << 20) + (long long)r * 1024;
    int n = r + 1;
    int nz = (r & ~63) + 64;   // AV (causal=2) reads only up to the row's 64-block end
    __shared__ float sh[32];
    int lane = threadIdx.x & 31, wid = threadIdx.x >> 5;
    float mx = -1e30f;
    for (int j = threadIdx.x; j < n; j += 256) mx = fmaxf(mx, row[j]);
    for (int o = 16; o; o >>= 1) mx = fmaxf(mx, __shfl_xor_sync(~0u, mx, o));
    if (lane == 0) sh[wid] = mx;
    __syncthreads();
    if (wid == 0) {
        mx = (lane < 8) ? sh[lane] : -1e30f;
        for (int o = 16; o; o >>= 1) mx = fmaxf(mx, __shfl_xor_sync(~0u, mx, o));
        if (lane == 0) sh[0] = mx;
    }
    __syncthreads();
    mx = sh[0];
    __syncthreads();
    float s = 0.f;
    for (int j = threadIdx.x; j < n; j += 256) s += __expf(row[j] - mx);
    for (int o = 16; o; o >>= 1) s += __shfl_xor_sync(~0u, s, o);
    if (lane == 0) sh[wid] = s;
    __syncthreads();
    if (wid == 0) {
        s = (lane < 8) ? sh[lane] : 0.f;
        for (int o = 16; o; o >>= 1) s += __shfl_xor_sync(~0u, s, o);
        if (lane == 0) sh[0] = s;
    }
    __syncthreads();
    float inv = 1.f / sh[0];
    for (int j = threadIdx.x; j < nz; j += 256)
        row[j] = (j < n) ? __expf(row[j] - mx) * inv : 0.f;
}

__global__ void zero_cnt(int* c) { if (threadIdx.x < EE) c[threadIdx.x] = 0; }

__global__ void route_kernel(const float* __restrict__ h, const float* __restrict__ gw,
                             int* cnt, int* etok, int* easn, float* wts) {
    int w = (blockIdx.x * blockDim.x + threadIdx.x) >> 5;
    int lane = threadIdx.x & 31;
    if (w >= TOK) return;
    const float* hr = h + (long long)w * DD;
    float lg[EE];
#pragma unroll
    for (int e = 0; e < EE; e++) {
        float s = 0.f;
        for (int d = lane; d < DD; d += 32) s += hr[d] * gw[d * EE + e];
        for (int o = 16; o; o >>= 1) s += __shfl_xor_sync(~0u, s, o);
        lg[e] = s;
    }
    if (lane == 0) {
        int e0 = 0;
        for (int e = 1; e < EE; e++) if (lg[e] > lg[e0]) e0 = e;
        int e1 = -1;
        for (int e = 0; e < EE; e++) { if (e == e0) continue; if (e1 < 0 || lg[e] > lg[e1]) e1 = e; }
        float x1 = __expf(lg[e1] - lg[e0]);
        float den = 1.f + x1;
        float w0 = 1.f / den, w1 = x1 / den;
        int s0 = atomicAdd(&cnt[e0], 1);
        etok[e0 * TOK + s0] = w; easn[e0 * TOK + s0] = 2 * w;
        int s1 = atomicAdd(&cnt[e1], 1);
        etok[e1 * TOK + s1] = w; easn[e1 * TOK + s1] = 2 * w + 1;
        wts[2 * w] = w0; wts[2 * w + 1] = w1;
    }
}

__global__ void combine_kernel(float* __restrict__ x, const float* __restrict__ ys,
                               const float* __restrict__ wts) {
    int idx = blockIdx.x * blockDim.x + threadIdx.x;
    if (idx >= TOK * DD) return;
    int t = idx / DD, d = idx - t * DD;
    x[idx] += wts[2 * t] * ys[(long long)(2 * t) * DD + d]
            + wts[2 * t + 1] * ys[(long long)(2 * t + 1) * DD + d];
}

__global__ void basis_kernel(float* __restrict__ Cb) {
    int idx = blockIdx.x * blockDim.x + threadIdx.x;
    if (idx >= 1026 * 1024) return;
    int j = idx >> 10, n = idx & 1023;
    const float invN = 1.f / 1024.f;
    float v;
    if (j == 0) v = invN;
    else if (j <= 511) { int m = (j * n) & 1023; v = 2.f * invN * cosf(m * TWO_PI_N); }
    else if (j == 512) v = invN * ((n & 1) ? -1.f : 1.f);
    else if (j == 513 || j == 1025) v = 0.f;
    else { int kk = j - 513; int m = (kk * n) & 1023; v = -2.f * invN * sinf(m * TWO_PI_N); }
    Cb[idx] = v;
}

__global__ void bf_kernel(const float* __restrict__ ob, const float* __restrict__ Cb,
                          float* __restrict__ bf) {
    int n = blockIdx.x * 128 + threadIdx.x;
    float s = 0.f;
    for (int j = 0; j < 1026; j++) s += ob[j] * Cb[j * 1024 + n];
    bf[n] = s;
}

__global__ void istft_kernel(const float* __restrict__ frames, float* __restrict__ out) {
    int idx = blockIdx.x * blockDim.x + threadIdx.x;
    if (idx >= BB * OUTL) return;
    int b = idx / OUTL, i = idx - b * OUTL;
    int ip = i + PADL;
    int tmin = (ip >= 1024) ? ((ip - 768) >> 8) : 0;
    int tmax = min(1023, ip >> 8);
    float acc = 0.f, env = 0.f;
    for (int t = tmin; t <= tmax; t++) {
        int n = ip - (t << 8);
        float w = 0.5f * (1.f - cosf(n * TWO_PI_N));
        acc += frames[((long long)(b * 1024 + t) << 10) + n] * w;
        env += w * w;
    }
    out[idx] = acc / env;
}

// ---------------- host side ----------------
static void* symaddr(const void* sym) {
    void* p = nullptr;
    cudaGetSymbolAddress(&p, sym);
    return p;
}

struct GemmArgs {
    const float* A; int lda; long long sAz, sAz2;
    const float* B; int ldb; long long sBz, sBz2;
    float* C; int ldc; long long sCz, sCz2;
    int zdiv;
    const float* bias; long long sbz; const float* res;
    int M, N, Kd; float alpha; int Z;
    const int* idxA; const int* idxC; const int* cnt;
    int causal; int gridM;
    const uint32_t* PBh; const uint32_t* PBl; long long sPBz; long long sPBz2; int ldPB;
};

#define BPK_SZH(TRB, BN) ((TRB) ? ((BN) * APK_LD) : (8 * ((BN) + 8)))
#define SMEM_RSTG(TRB, BN) (4 * 2 * (2 * APK_SZ + 2 * BPK_SZH(TRB, BN)))
#define SMEM_PKB(BN) (4 * (2 * 2 * APK_SZ + 4 * 2 * 8 * ((BN) + 8)))

static void gemm(int act, bool trb, int BN, const GemmArgs& a)
{
    dim3 grid((a.N + BN - 1) / BN, a.gridM ? a.gridM : (a.M + 63) / 64, a.Z);
    if (a.PBh) {
        if (BN == 64) {
            size_t shm = SMEM_PKB(64);
            cudaFuncSetAttribute(gemm_kernel<0, false, 64, true>, cudaFuncAttributeMaxDynamicSharedMemorySize, (int)shm);
            gemm_kernel<0, false, 64, true><<<grid, 256, shm>>>(a.A, a.lda, a.sAz, a.sAz2, a.B, a.ldb, a.sBz, a.sBz2,
                a.C, a.ldc, a.sCz, a.sCz2, a.zdiv, a.bias, a.sbz, a.res,
                a.M, a.N, a.Kd, a.alpha, a.idxA, a.idxC, a.cnt, a.causal, a.PBh, a.PBl, a.sPBz, a.sPBz2, a.ldPB);
        } else {
            size_t shm = SMEM_PKB(128);
            cudaFuncSetAttribute(gemm_kernel<0, false, 128, true>, cudaFuncAttributeMaxDynamicSharedMemorySize, (int)shm);
            gemm_kernel<0, false, 128, true><<<grid, 256, shm>>>(a.A, a.lda, a.sAz, a.sAz2, a.B, a.ldb, a.sBz, a.sBz2,
                a.C, a.ldc, a.sCz, a.sCz2, a.zdiv, a.bias, a.sbz, a.res,
                a.M, a.N, a.Kd, a.alpha, a.idxA, a.idxC, a.cnt, a.causal, a.PBh, a.PBl, a.sPBz, a.sPBz2, a.ldPB);
        }
    } else if (act == 1) {
        size_t shm = SMEM_RSTG(false, 128);
        cudaFuncSetAttribute(gemm_kernel<1, false, 128, false>, cudaFuncAttributeMaxDynamicSharedMemorySize, (int)shm);
        gemm_kernel<1, false, 128, false><<<grid, 256, shm>>>(a.A, a.lda, a.sAz, a.sAz2, a.B, a.ldb, a.sBz, a.sBz2,
            a.C, a.ldc, a.sCz, a.sCz2, a.zdiv, a.bias, a.sbz, a.res,
            a.M, a.N, a.Kd, a.alpha, a.idxA, a.idxC, a.cnt, a.causal, nullptr, nullptr, 0, 0, 0);
    } else {
        size_t shm = SMEM_RSTG(false, 128);
        cudaFuncSetAttribute(gemm_kernel<0, false, 128, false>, cudaFuncAttributeMaxDynamicSharedMemorySize, (int)shm);
        gemm_kernel<0, false, 128, false><<<grid, 256, shm>>>(a.A, a.lda, a.sAz, a.sAz2, a.B, a.ldb, a.sBz, a.sBz2,
            a.C, a.ldc, a.sCz, a.sCz2, a.zdiv, a.bias, a.sbz, a.res,
            a.M, a.N, a.Kd, a.alpha, a.idxA, a.idxC, a.cnt, a.causal, nullptr, nullptr, 0, 0, 0);
    }
}

static void launch_pack(const float* W, int K, int N, uint32_t* Ph, uint32_t* Pl)
{
    int K2 = (K + 1) >> 1;
    int tot = K2 * (N >> 2);
    pack_w<<<(tot + 255) / 256, 256>>>(W, 0, K, N, Ph, Pl, 0);
}

extern "C" void kernel_launch(void* const* d_in, const int* in_sizes, int n_in,
                              void* d_out, int out_size)
{
    const float* z_in  = (const float*)d_in[0];
    const float* in_w  = (const float*)d_in[1];
    const float* in_b  = (const float*)d_in[2];
    const float* ln1g  = (const float*)d_in[3];
    const float* ln1b  = (const float*)d_in[4];
    const float* wq    = (const float*)d_in[5];
    const float* bq    = (const float*)d_in[6];
    const float* wk    = (const float*)d_in[7];
    const float* bk    = (const float*)d_in[8];
    const float* wv    = (const float*)d_in[9];
    const float* bv    = (const float*)d_in[10];
    const float* wo    = (const float*)d_in[11];
    const float* bo    = (const float*)d_in[12];
    const float* ln2g  = (const float*)d_in[13];
    const float* ln2b  = (const float*)d_in[14];
    const float* gatew = (const float*)d_in[15];
    const float* ew1   = (const float*)d_in[16];
    const float* eb1   = (const float*)d_in[17];
    const float* ew2   = (const float*)d_in[18];
    const float* eb2   = (const float*)d_in[19];
    const float* outw  = (const float*)d_in[20];
    const float* outb  = (const float*)d_in[21];
    float* out = (float*)d_out;

    float* ZT = (float*)symaddr(g_zt);
    float* X  = (float*)symaddr(g_x);
    float* H  = (float*)symaddr(g_h);
    float* QKV = (float*)symaddr(g_qkv);
    float* BQKV = (float*)symaddr(g_bqkv);
    float* Q  = QKV;
    float* Kb = QKV + (long long)TOK * DD;
    float* V  = QKV + 2LL * TOK * DD;
    float* AO = (float*)symaddr(g_ao);
    float* SC = (float*)symaddr(g_scores);
    float* HID = (float*)symaddr(g_hidden);
    float* YS = (float*)symaddr(g_yslot);
    float* CB = (float*)symaddr(g_Cb);
    float* MT = (float*)symaddr(g_Mt);
    float* BF = (float*)symaddr(g_bf);
    float* FR = (float*)symaddr(g_frames);
    int* CNT = (int*)symaddr(g_cnt);
    int* ETK = (int*)symaddr(g_etok);
    int* EAS = (int*)symaddr(g_easn);
    float* WTS = (float*)symaddr(g_wts);
    uint32_t* PK_INW = (uint32_t*)symaddr(g_pk_inw);
    uint32_t* PK_QKV = (uint32_t*)symaddr(g_pk_qkv);
    uint32_t* PK_WO  = (uint32_t*)symaddr(g_pk_wo);
    uint32_t* PK_CB  = (uint32_t*)symaddr(g_pk_cb);
    uint32_t* PK_MT  = (uint32_t*)symaddr(g_pk_mt);
    uint32_t* PK_Q   = (uint32_t*)symaddr(g_pk_q);
    uint32_t* PK_K   = (uint32_t*)symaddr(g_pk_k);
    uint32_t* PK_V   = (uint32_t*)symaddr(g_pk_v);

    // pre-pack small static weights (hi then lo halves)
    launch_pack(in_w, CIN, DD, PK_INW, PK_INW + SZ_INW);

    // in_projection: zt = z^T, x = zt @ in_w + in_b
    transpose_z<<<dim3(SS / 32, CIN / 32, BB), dim3(32, 8)>>>(z_in, ZT);
    {
        GemmArgs a = {ZT, CIN, 0, 0, nullptr, DD, 0, 0, X, DD, 0, 0, 1,
                      in_b, 0, nullptr, TOK, DD, CIN, 1.f, 1, nullptr, nullptr, nullptr, 0, 0,
                      PK_INW, PK_INW + SZ_INW, 0, 0, DD};
        gemm(0, false, 128, a);
    }

    for (int L = 0; L < 2; L++) {
        launch_pack(wq + (long long)L * DD * DD, DD, DD, PK_QKV,                PK_QKV + 3 * SZ_QKV1);
        launch_pack(wk + (long long)L * DD * DD, DD, DD, PK_QKV + SZ_QKV1,     PK_QKV + 3 * SZ_QKV1 + SZ_QKV1);
        launch_pack(wv + (long long)L * DD * DD, DD, DD, PK_QKV + 2 * SZ_QKV1, PK_QKV + 3 * SZ_QKV1 + 2 * SZ_QKV1);
        launch_pack(wo + (long long)L * DD * DD, DD, DD, PK_WO, PK_WO + SZ_WO);
        cudaMemcpyAsync(BQKV,          bq + L * DD, DD * sizeof(float), cudaMemcpyDeviceToDevice);
        cudaMemcpyAsync(BQKV + DD,     bk + L * DD, DD * sizeof(float), cudaMemcpyDeviceToDevice);
        cudaMemcpyAsync(BQKV + 2 * DD, bv + L * DD, DD * sizeof(float), cudaMemcpyDeviceToDevice);

        ln_kernel<<<TOK, 256>>>(X, H, ln1g + L * DD, ln1b + L * DD);
        {
            GemmArgs a = {H, DD, 0, 0, nullptr, DD, 0, 0,
                          QKV, DD, (long long)TOK * DD, 0, 3,
                          BQKV, DD, nullptr, TOK, DD, DD, 1.f, 3, 0, 0, 0, 0, 0,
                          PK_QKV, PK_QKV + 3 * SZ_QKV1, SZ_QKV1, 0, DD};
            gemm(0, false, 128, a);
        }
        if (L == 0)
            rope_kernel<<<(TOK * (DD / 2) + 255) / 256, 256>>>(Q, Kb);

        // pack attention activations: Q,K dim-paired; V token-paired per batch
        pack_rows<<<(TOK * DD / 4 + 255) / 256, 256>>>(Q, PK_Q, PK_Q + SZ_ACT, TOK * DD / 4);
        pack_rows<<<(TOK * DD / 4 + 255) / 256, 256>>>(Kb, PK_K, PK_K + SZ_ACT, TOK * DD / 4);
        pack_w<<<dim3(((SS / 2) * (DD / 4) + 255) / 256, 1, BB), 256>>>(
            V, (long long)SS * DD, SS, DD, PK_V, PK_V + SZ_ACT, (long long)(SS / 2) * DD);

        // scores (fully packed, causal)
        cudaFuncSetAttribute(scores_pk, cudaFuncAttributeMaxDynamicSharedMemorySize, 4 * 384 * SQ_LD);
        scores_pk<<<dim3(8, 16, BB * HH), 256, 4 * 384 * SQ_LD>>>(
            PK_Q, PK_Q + SZ_ACT, PK_K, PK_K + SZ_ACT, SC, 0.125f);
        softmax_causal<<<dim3(SS, BB * HH), 256>>>(SC);
        // AV: A = P (reg-staged), B = V pre-packed
        {
            GemmArgs a = {SC, SS, (long long)SS * SS, (long long)HH * SS * SS,
                          nullptr, DD, 0, 0,
                          AO, DD, HD, (long long)SS * DD, HH,
                          nullptr, 0, nullptr, SS, HD, SS, 1.f, BB * HH, 0, 0, 0, 2, 0,
                          PK_V, PK_V + SZ_ACT, HD, (long long)(SS / 2) * DD, DD};
            gemm(0, false, 64, a);
        }
        {
            GemmArgs a = {AO, DD, 0, 0, nullptr, DD, 0, 0, X, DD, 0, 0, 1,
                          bo + L * DD, 0, X, TOK, DD, DD, 1.f, 1, 0, 0, 0, 0, 0,
                          PK_WO, PK_WO + SZ_WO, 0, 0, DD};
            gemm(0, false, 128, a);
        }

        // MoE (unchanged reg-staged path)
        ln_kernel<<<TOK, 256>>>(X, H, ln2g + L * DD, ln2b + L * DD);
        zero_cnt<<<1, 32>>>(CNT);
        route_kernel<<<TOK / 8, 256>>>(H, gatew + (long long)L * DD * EE, CNT, ETK, EAS, WTS);
        {
            GemmArgs a = {H, DD, 0, 0,
                          ew1 + (long long)L * EE * DD * FF, FF, (long long)DD * FF, 0,
                          HID, FF, 0, 0, EE,
                          eb1 + (long long)L * EE * FF, FF, nullptr,
                          TOK, FF, DD, 1.f, EE, ETK, EAS, CNT, 0, TOK / 64,
                          nullptr, nullptr, 0, 0, 0};
            gemm(1, false, 128, a);
        }
        {
            GemmArgs a = {HID, FF, 0, 0,
                          ew2 + (long long)L * EE * FF * DD, DD, (long long)FF * DD, 0,
                          YS, DD, 0, 0, EE,
                          eb2 + (long long)L * EE * DD, DD, nullptr,
                          TOK, DD, FF, 1.f, EE, EAS, EAS, CNT, 0, TOK / 64,
                          nullptr, nullptr, 0, 0, 0};
            gemm(0, false, 128, a);
        }
        combine_kernel<<<(TOK * DD + 255) / 256, 256>>>(X, YS, WTS);
    }

    // out projection fused with irfft basis: frames = x @ (out_w @ Cb) + out_b @ Cb
    basis_kernel<<<(1026 * 1024 + 255) / 256, 256>>>(CB);
    launch_pack(CB, 1026, 1024, PK_CB, PK_CB + SZ_CB);
    {
        GemmArgs a = {outw, 2 * FB, 0, 0, nullptr, 1024, 0, 0, MT, 1024, 0, 0, 1,
                      nullptr, 0, nullptr, DD, 1024, 2 * FB, 1.f, 1, 0, 0, 0, 0, 0,
                      PK_CB, PK_CB + SZ_CB, 0, 0, 1024};
        gemm(0, false, 128, a);
    }
    launch_pack(MT, DD, 1024, PK_MT, PK_MT + SZ_MT);
    bf_kernel<<<8, 128>>>(outb, CB, BF);
    {
        GemmArgs a = {X, DD, 0, 0, nullptr, 1024, 0, 0, FR, 1024, 0, 0, 1,
                      BF, 0, nullptr, TOK, 1024, DD, 1.f, 1, 0, 0, 0, 0, 0,
                      PK_MT, PK_MT + SZ_MT, 0, 0, 1024};
        gemm(0, false, 128, a);
    }

    // windowed overlap-add + env normalize + trim
    istft_kernel<<<(BB * OUTL + 255) / 256, 256>>>(FR, out);
}